// round 1
// baseline (speedup 1.0000x reference)
#include <cuda_runtime.h>
#include <math.h>

#define SEQ     2048
#define HIDDEN  4544
#define NH      71
#define HD      64
#define QKV_OUT ((NH + 2) * HD)   // 4672
#define QDIM    (NH * HD)         // 4544
#define KOFF    (NH * HD)         // 4544
#define VOFF    ((NH + 1) * HD)   // 4608

// ---------------- scratch (device globals; no allocations allowed) ----------
__device__ float g_fused[SEQ * QKV_OUT];   // QKV gemm output (rope applied in place)
__device__ float g_attn [SEQ * QDIM];      // attention output, [s, h*64+d]
__device__ float g_cos  [SEQ * 32];
__device__ float g_sin  [SEQ * 32];

// ---------------- RoPE table (fp64 trig for accuracy) -----------------------
__global__ void rope_table_kernel() {
    int idx = blockIdx.x * blockDim.x + threadIdx.x;
    if (idx >= SEQ * 32) return;
    int s = idx >> 5, j = idx & 31;
    double inv = exp(-(double)j / 32.0 * log(10000.0));
    double ang = (double)s * inv;
    g_cos[idx] = (float)cos(ang);
    g_sin[idx] = (float)sin(ang);
}

// ---------------- SGEMM: C[m,n] = sum_k A[m*K+k] * B[n*K+k] -----------------
// BM=128, BN=64, BK=16, 256 threads, 8x4 microtile per thread.
#define BM 128
#define BN 64
#define BK 16

__global__ __launch_bounds__(256) void sgemm_tn(
    const float* __restrict__ A, const float* __restrict__ B,
    float* __restrict__ C, int M, int N, int K)
{
    __shared__ float As[BK][BM + 1];
    __shared__ float Bs[BK][BN + 1];

    const int tid = threadIdx.x;
    const int tx = tid & 15;          // N direction (4 cols)
    const int ty = tid >> 4;          // M direction (8 rows)
    const int bm = blockIdx.y * BM;
    const int bn = blockIdx.x * BN;

    float acc[8][4];
    #pragma unroll
    for (int i = 0; i < 8; i++)
        #pragma unroll
        for (int j = 0; j < 4; j++) acc[i][j] = 0.0f;

    for (int k0 = 0; k0 < K; k0 += BK) {
        // A tile: 128x16 = 512 float4, 2 per thread
        #pragma unroll
        for (int i = 0; i < 2; i++) {
            int id  = tid + i * 256;
            int row = id >> 2;
            int c4  = (id & 3) * 4;
            float4 v = *reinterpret_cast<const float4*>(
                &A[(size_t)(bm + row) * K + k0 + c4]);
            As[c4 + 0][row] = v.x; As[c4 + 1][row] = v.y;
            As[c4 + 2][row] = v.z; As[c4 + 3][row] = v.w;
        }
        // B tile: 64x16 = 256 float4, 1 per thread
        {
            int row = tid >> 2;
            int c4  = (tid & 3) * 4;
            float4 v = *reinterpret_cast<const float4*>(
                &B[(size_t)(bn + row) * K + k0 + c4]);
            Bs[c4 + 0][row] = v.x; Bs[c4 + 1][row] = v.y;
            Bs[c4 + 2][row] = v.z; Bs[c4 + 3][row] = v.w;
        }
        __syncthreads();

        #pragma unroll
        for (int kk = 0; kk < BK; kk++) {
            float a[8], b[4];
            #pragma unroll
            for (int i = 0; i < 8; i++) a[i] = As[kk][ty * 8 + i];
            #pragma unroll
            for (int j = 0; j < 4; j++) b[j] = Bs[kk][tx * 4 + j];
            #pragma unroll
            for (int i = 0; i < 8; i++)
                #pragma unroll
                for (int j = 0; j < 4; j++)
                    acc[i][j] = fmaf(a[i], b[j], acc[i][j]);
        }
        __syncthreads();
    }

    #pragma unroll
    for (int i = 0; i < 8; i++) {
        int row = bm + ty * 8 + i;
        float4 o = make_float4(acc[i][0], acc[i][1], acc[i][2], acc[i][3]);
        *reinterpret_cast<float4*>(&C[(size_t)row * N + bn + tx * 4]) = o;
    }
}

// ---------------- RoPE apply: in-place on q (cols 0..4543) and k (4544..4607)
__global__ void rope_apply_kernel() {
    int idx = blockIdx.x * blockDim.x + threadIdx.x;
    const int total = SEQ * (NH + 1) * 32;
    if (idx >= total) return;
    int j  = idx & 31;
    int t  = idx >> 5;
    int hh = t % (NH + 1);      // 0..70 = q heads, 71 = k
    int s  = t / (NH + 1);
    size_t base = (size_t)s * QKV_OUT + hh * HD;
    float c  = g_cos[s * 32 + j];
    float sn = g_sin[s * 32 + j];
    float a  = g_fused[base + j];
    float b  = g_fused[base + j + 32];
    g_fused[base + j]      = a * c - b * sn;
    g_fused[base + j + 32] = b * c + a * sn;
}

// ---------------- Flash attention (MQA, causal) ------------------------------
// grid (SEQ/128, NH), block 128. Each thread owns one q row.
// Dyn smem: qb[128*68] (q staging, then scores) | ks4[64*16 float4] | vs4[...]
#define FA_BQ  128
#define FA_BKV 64
#define QB_PITCH 68

__global__ __launch_bounds__(128) void flash_kernel(
    const float* __restrict__ fused, float* __restrict__ attn_out)
{
    extern __shared__ float sm[];
    float*  qb  = sm;                                   // 128*68 floats
    float4* ks4 = (float4*)(sm + FA_BQ * QB_PITCH);     // 64*16
    float4* vs4 = ks4 + FA_BKV * 16;                    // 64*16

    const int tid = threadIdx.x;
    const int qt  = blockIdx.x;
    const int h   = blockIdx.y;
    const int row = qt * FA_BQ + tid;

    // ---- cooperative load of q tile (coalesced), then copy to regs ----
    #pragma unroll
    for (int i = 0; i < 16; i++) {
        int id = i * 128 + tid;
        int r  = id >> 4;
        int c4 = id & 15;
        float4 v = *reinterpret_cast<const float4*>(
            &fused[(size_t)(qt * FA_BQ + r) * QKV_OUT + h * HD + c4 * 4]);
        *(reinterpret_cast<float4*>(qb + r * QB_PITCH) + c4) = v;
    }
    __syncthreads();

    float q[HD];
    #pragma unroll
    for (int d = 0; d < HD; d++) q[d] = qb[tid * QB_PITCH + d];
    __syncthreads();   // qb now free for scores

    float m = -INFINITY, l = 0.0f;
    float acc[HD];
    #pragma unroll
    for (int d = 0; d < HD; d++) acc[d] = 0.0f;

    const int n_kv = 2 * qt + 2;    // causal limit: kv tiles 0 .. 2*qt+1
    for (int kt = 0; kt < n_kv; kt++) {
        // load K/V tiles (64x64 each), coalesced
        #pragma unroll
        for (int i = 0; i < 8; i++) {
            int id = i * 128 + tid;
            int r  = id >> 4;
            int c4 = id & 15;
            size_t src = (size_t)(kt * FA_BKV + r) * QKV_OUT;
            ks4[r * 16 + c4] = *reinterpret_cast<const float4*>(&fused[src + KOFF + c4 * 4]);
            vs4[r * 16 + c4] = *reinterpret_cast<const float4*>(&fused[src + VOFF + c4 * 4]);
        }
        __syncthreads();

        // scores for my row
        float tmax = -INFINITY;
        for (int j = 0; j < FA_BKV; j++) {
            float s0 = 0.f, s1 = 0.f, s2 = 0.f, s3 = 0.f;
            #pragma unroll
            for (int c = 0; c < 16; c++) {
                float4 kk = ks4[j * 16 + c];
                s0 = fmaf(q[4 * c + 0], kk.x, s0);
                s1 = fmaf(q[4 * c + 1], kk.y, s1);
                s2 = fmaf(q[4 * c + 2], kk.z, s2);
                s3 = fmaf(q[4 * c + 3], kk.w, s3);
            }
            float s = ((s0 + s1) + (s2 + s3)) * 0.125f;
            if (kt * FA_BKV + j > row) s = -INFINITY;
            qb[tid * QB_PITCH + j] = s;
            tmax = fmaxf(tmax, s);
        }

        float mnew = fmaxf(m, tmax);
        float corr = __expf(m - mnew);
        l *= corr;
        #pragma unroll
        for (int d = 0; d < HD; d++) acc[d] *= corr;

        float lsum = 0.0f;
        for (int j = 0; j < FA_BKV; j++) {
            float p = __expf(qb[tid * QB_PITCH + j] - mnew);
            lsum += p;
            #pragma unroll
            for (int c = 0; c < 16; c++) {
                float4 vv = vs4[j * 16 + c];
                acc[4 * c + 0] = fmaf(p, vv.x, acc[4 * c + 0]);
                acc[4 * c + 1] = fmaf(p, vv.y, acc[4 * c + 1]);
                acc[4 * c + 2] = fmaf(p, vv.z, acc[4 * c + 2]);
                acc[4 * c + 3] = fmaf(p, vv.w, acc[4 * c + 3]);
            }
        }
        l += lsum;
        m = mnew;
        __syncthreads();   // before next tile overwrites ks4/vs4
    }

    // ---- normalize, stage through smem, coalesced store ----
    float inv = 1.0f / l;
    #pragma unroll
    for (int d = 0; d < HD; d++) qb[tid * QB_PITCH + d] = acc[d] * inv;
    __syncthreads();
    #pragma unroll
    for (int i = 0; i < 16; i++) {
        int id = i * 128 + tid;
        int r  = id >> 4;
        int c4 = id & 15;
        float4 v = *(reinterpret_cast<float4*>(qb + r * QB_PITCH) + c4);
        *reinterpret_cast<float4*>(
            &attn_out[(size_t)(qt * FA_BQ + r) * QDIM + h * HD + c4 * 4]) = v;
    }
}

// ---------------- launch ----------------------------------------------------
extern "C" void kernel_launch(void* const* d_in, const int* in_sizes, int n_in,
                              void* d_out, int out_size)
{
    const float* x       = (const float*)d_in[0];   // [1,1,2048,4544]
    const float* qkv_w   = (const float*)d_in[1];   // [4672,4544]
    const float* dense_w = (const float*)d_in[2];   // [4544,4544]
    // d_in[3] = attention_mask (pure causal -1e5; synthesized in-kernel)
    float* out = (float*)d_out;                     // [1,1,2048,4544]

    float* fused; cudaGetSymbolAddress((void**)&fused, g_fused);
    float* attn;  cudaGetSymbolAddress((void**)&attn,  g_attn);

    // flash kernel needs 66 KB dynamic smem
    const int fa_smem = (FA_BQ * QB_PITCH + 2 * FA_BKV * HD) * (int)sizeof(float);
    cudaFuncSetAttribute(flash_kernel,
                         cudaFuncAttributeMaxDynamicSharedMemorySize, fa_smem);

    // 1. RoPE table
    rope_table_kernel<<<(SEQ * 32 + 255) / 256, 256>>>();

    // 2. QKV GEMM: [2048,4544] x [4672,4544]^T -> [2048,4672]
    {
        dim3 grid(QKV_OUT / BN, SEQ / BM);
        sgemm_tn<<<grid, 256>>>(x, qkv_w, fused, SEQ, QKV_OUT, HIDDEN);
    }

    // 3. RoPE on q + k, in place
    {
        int total = SEQ * (NH + 1) * 32;
        rope_apply_kernel<<<(total + 255) / 256, 256>>>();
    }

    // 4. Flash attention
    {
        dim3 grid(SEQ / FA_BQ, NH);
        flash_kernel<<<grid, 128, fa_smem>>>(fused, attn);
    }

    // 5. Dense GEMM: [2048,4544] x [4544,4544]^T -> out
    {
        dim3 grid(HIDDEN / BN, SEQ / BM);
        sgemm_tn<<<grid, 256>>>(attn, dense_w, out, SEQ, HIDDEN, HIDDEN);
    }
}

// round 3
// speedup vs baseline: 1.7982x; 1.7982x over previous
#include <cuda_runtime.h>
#include <cuda_bf16.h>
#include <math.h>
#include <stdint.h>

#define SEQ     2048
#define HIDDEN  4544
#define NH      71
#define HD      64
#define QKV_OUT 4672
#define QKV_PAD 4736            // 37*128
#define DEN_PAD 4608            // 36*128
#define QDIM    4544
#define KOFF    4544
#define VOFF    4608

// ---------------- scratch (device globals; no allocations allowed) ----------
__device__ float g_fused[SEQ * QKV_OUT];
__device__ float g_attn [SEQ * QDIM];
__device__ float g_cos  [SEQ * 32];
__device__ float g_sin  [SEQ * 32];
__device__ __nv_bfloat16 g_xh [SEQ * HIDDEN],     g_xl [SEQ * HIDDEN];
__device__ __nv_bfloat16 g_wqh[QKV_PAD * HIDDEN], g_wql[QKV_PAD * HIDDEN];
__device__ __nv_bfloat16 g_wdh[DEN_PAD * HIDDEN], g_wdl[DEN_PAD * HIDDEN];
__device__ __nv_bfloat16 g_ah [SEQ * HIDDEN],     g_al [SEQ * HIDDEN];

// ================= portable PTX helpers (sm_80+; no tcgen05) ================
__device__ __forceinline__ uint32_t smem_to_u32(const void* p) {
    uint32_t a;
    asm("{ .reg .u64 t; cvta.to.shared.u64 t, %1; cvt.u32.u64 %0, t; }"
        : "=r"(a) : "l"(p));
    return a;
}
__device__ __forceinline__ void ldsm_x4(uint32_t& r0, uint32_t& r1,
                                        uint32_t& r2, uint32_t& r3, uint32_t addr) {
    asm volatile("ldmatrix.sync.aligned.m8n8.x4.shared.b16 {%0,%1,%2,%3}, [%4];"
                 : "=r"(r0), "=r"(r1), "=r"(r2), "=r"(r3) : "r"(addr));
}
__device__ __forceinline__ void mma16816(float* c, const uint32_t* a,
                                         uint32_t b0, uint32_t b1) {
    asm volatile("mma.sync.aligned.m16n8k16.row.col.f32.bf16.bf16.f32 "
                 "{%0,%1,%2,%3}, {%4,%5,%6,%7}, {%8,%9}, {%0,%1,%2,%3};"
                 : "+f"(c[0]), "+f"(c[1]), "+f"(c[2]), "+f"(c[3])
                 : "r"(a[0]), "r"(a[1]), "r"(a[2]), "r"(a[3]), "r"(b0), "r"(b1));
}
__device__ __forceinline__ void cp_async16(uint32_t sdst, const void* gsrc) {
    asm volatile("cp.async.cg.shared.global [%0], [%1], 16;" :: "r"(sdst), "l"(gsrc));
}
#define CP_COMMIT() asm volatile("cp.async.commit_group;" ::: "memory")
#define CP_WAIT(n)  asm volatile("cp.async.wait_group %0;" :: "n"(n) : "memory")

// ---------------- RoPE table (fp64 trig for accuracy) -----------------------
__global__ void rope_table_kernel() {
    int idx = blockIdx.x * blockDim.x + threadIdx.x;
    if (idx >= SEQ * 32) return;
    int s = idx >> 5, j = idx & 31;
    double inv = exp(-(double)j / 32.0 * log(10000.0));
    double ang = (double)s * inv;
    g_cos[idx] = (float)cos(ang);
    g_sin[idx] = (float)sin(ang);
}

// ---------------- fp32 -> bf16 hi/lo split (with row zero-padding) ----------
__global__ void split_kernel(const float* __restrict__ src,
                             __nv_bfloat16* __restrict__ hi,
                             __nv_bfloat16* __restrict__ lo,
                             int total, int src_total)
{
    int i = blockIdx.x * blockDim.x + threadIdx.x;
    if (i >= total) return;
    float a = (i < src_total) ? src[i] : 0.0f;
    __nv_bfloat16 h = __float2bfloat16(a);
    float hf = __bfloat162float(h);
    hi[i] = h;
    lo[i] = __float2bfloat16(a - hf);
}

// ---------------- mma.sync bf16-split GEMM ----------------------------------
// C[m,n] = sum_k A[m,k]*B[n,k]  via  Ah*Bh + Ah*Bl + Al*Bh (drop Al*Bl).
// Tile 128x128, K-chunk 32, cp.async double buffer, 8 warps (64x32 warptiles).
#define BMT 128
#define BNT 128
#define BKC 32
#define PITCH 40                         // bf16 elems per smem row (80 B)
#define ARR_B (BMT * PITCH * 2)          // 10240 B per operand array
#define STG_B (4 * ARR_B)                // Ah, Al, Bh, Bl per stage
#define GEMM_SMEM (2 * STG_B)            // 81920 B

__global__ __launch_bounds__(256, 1) void gemm_mma(
    const __nv_bfloat16* __restrict__ Ah, const __nv_bfloat16* __restrict__ Al,
    const __nv_bfloat16* __restrict__ Bh, const __nv_bfloat16* __restrict__ Bl,
    float* __restrict__ C, int N_real, int K)
{
    extern __shared__ __align__(128) char smem[];
    const int tid = threadIdx.x;
    const int wid = tid >> 5;
    const int lid = tid & 31;
    const int m0 = blockIdx.y * BMT;
    const int n0 = blockIdx.x * BNT;
    const int wm = (wid & 1) * 64;
    const int wn = (wid >> 1) * 32;
    const uint32_t sbase = smem_to_u32(smem);

    // cp.async work split: 4 groups of 64 threads, one operand array each
    const int arr = tid >> 6;
    const int t64 = tid & 63;
    const __nv_bfloat16* gp = (arr == 0) ? Ah : (arr == 1) ? Al : (arr == 2) ? Bh : Bl;
    const int rbase = (arr < 2) ? m0 : n0;

#define LOAD_STAGE(s, k0) do {                                                 \
        uint32_t sb_ = sbase + (s) * STG_B + arr * ARR_B;                      \
        _Pragma("unroll")                                                      \
        for (int i_ = 0; i_ < 8; i_++) {                                       \
            int id_ = i_ * 64 + t64;                                           \
            int r_ = id_ >> 2, ch_ = id_ & 3;                                  \
            cp_async16(sb_ + r_ * 80 + ch_ * 16,                               \
                       gp + (size_t)(rbase + r_) * K + (k0) + ch_ * 8);        \
        }                                                                      \
    } while (0)

    float acc[4][4][4];
    #pragma unroll
    for (int i = 0; i < 4; i++)
        #pragma unroll
        for (int j = 0; j < 4; j++)
            #pragma unroll
            for (int e = 0; e < 4; e++) acc[i][j][e] = 0.0f;

    LOAD_STAGE(0, 0);
    CP_COMMIT();

    // ldmatrix lane addressing (constant per thread)
    const int arow = (lid & 7) | (((lid >> 3) & 1) << 3);
    const int acolh = (lid >> 4) * 8;                 // 0 or 8
    const int brow = (lid & 7) + ((lid >> 4) & 1) * 8;
    const int bcolh = ((lid >> 3) & 1) * 8;

    const int nchunk = K / BKC;
    for (int c = 0; c < nchunk; c++) {
        const int cur = c & 1;
        if (c + 1 < nchunk) {
            LOAD_STAGE(cur ^ 1, (c + 1) * BKC);
            CP_COMMIT();
            CP_WAIT(1);
        } else {
            CP_WAIT(0);
        }
        __syncthreads();

        const uint32_t sAh = sbase + cur * STG_B;
        const uint32_t sAl = sAh + ARR_B;
        const uint32_t sBh = sAh + 2 * ARR_B;
        const uint32_t sBl = sAh + 3 * ARR_B;

        #pragma unroll
        for (int kk = 0; kk < 2; kk++) {
            const int kc = kk * 16;
            uint32_t ah[4][4], al[4][4], bh[2][4], bl[2][4];
            #pragma unroll
            for (int i = 0; i < 4; i++) {
                uint32_t off = (uint32_t)((wm + i * 16 + arow) * 80 + (kc + acolh) * 2);
                ldsm_x4(ah[i][0], ah[i][1], ah[i][2], ah[i][3], sAh + off);
                ldsm_x4(al[i][0], al[i][1], al[i][2], al[i][3], sAl + off);
            }
            #pragma unroll
            for (int j = 0; j < 2; j++) {
                uint32_t off = (uint32_t)((wn + j * 16 + brow) * 80 + (kc + bcolh) * 2);
                ldsm_x4(bh[j][0], bh[j][1], bh[j][2], bh[j][3], sBh + off);
                ldsm_x4(bl[j][0], bl[j][1], bl[j][2], bl[j][3], sBl + off);
            }
            #pragma unroll
            for (int i = 0; i < 4; i++) {
                #pragma unroll
                for (int j = 0; j < 2; j++) {
                    mma16816(acc[i][j * 2 + 0], ah[i], bh[j][0], bh[j][1]);
                    mma16816(acc[i][j * 2 + 1], ah[i], bh[j][2], bh[j][3]);
                    mma16816(acc[i][j * 2 + 0], ah[i], bl[j][0], bl[j][1]);
                    mma16816(acc[i][j * 2 + 1], ah[i], bl[j][2], bl[j][3]);
                    mma16816(acc[i][j * 2 + 0], al[i], bh[j][0], bh[j][1]);
                    mma16816(acc[i][j * 2 + 1], al[i], bh[j][2], bh[j][3]);
                }
            }
        }
        __syncthreads();
    }

    // epilogue: direct float2 stores
    const int gr = lid >> 2, tg = lid & 3;
    #pragma unroll
    for (int i = 0; i < 4; i++) {
        #pragma unroll
        for (int j = 0; j < 4; j++) {
            int col = n0 + wn + j * 8 + tg * 2;
            if (col < N_real) {
                int row = m0 + wm + i * 16 + gr;
                float2 v0 = make_float2(acc[i][j][0], acc[i][j][1]);
                float2 v1 = make_float2(acc[i][j][2], acc[i][j][3]);
                *reinterpret_cast<float2*>(&C[(size_t)row * N_real + col]) = v0;
                *reinterpret_cast<float2*>(&C[(size_t)(row + 8) * N_real + col]) = v1;
            }
        }
    }
#undef LOAD_STAGE
}

// ---------------- RoPE apply: in-place on q (cols 0..4543) and k (4544..4607)
__global__ void rope_apply_kernel() {
    int idx = blockIdx.x * blockDim.x + threadIdx.x;
    const int total = SEQ * (NH + 1) * 32;
    if (idx >= total) return;
    int j  = idx & 31;
    int t  = idx >> 5;
    int hh = t % (NH + 1);
    int s  = t / (NH + 1);
    size_t base = (size_t)s * QKV_OUT + hh * HD;
    float c  = g_cos[s * 32 + j];
    float sn = g_sin[s * 32 + j];
    float a  = g_fused[base + j];
    float b  = g_fused[base + j + 32];
    g_fused[base + j]      = a * c - b * sn;
    g_fused[base + j + 32] = b * c + a * sn;
}

// ---------------- Flash attention (MQA, causal) ------------------------------
#define FA_BQ  128
#define FA_BKV 64
#define QB_PITCH 68

__global__ __launch_bounds__(128) void flash_kernel(
    const float* __restrict__ fused, float* __restrict__ attn_out)
{
    extern __shared__ float sm[];
    float*  qb  = sm;
    float4* ks4 = (float4*)(sm + FA_BQ * QB_PITCH);
    float4* vs4 = ks4 + FA_BKV * 16;

    const int tid = threadIdx.x;
    const int qt  = blockIdx.x;
    const int h   = blockIdx.y;
    const int row = qt * FA_BQ + tid;

    #pragma unroll
    for (int i = 0; i < 16; i++) {
        int id = i * 128 + tid;
        int r  = id >> 4;
        int c4 = id & 15;
        float4 v = *reinterpret_cast<const float4*>(
            &fused[(size_t)(qt * FA_BQ + r) * QKV_OUT + h * HD + c4 * 4]);
        *(reinterpret_cast<float4*>(qb + r * QB_PITCH) + c4) = v;
    }
    __syncthreads();

    float q[HD];
    #pragma unroll
    for (int d = 0; d < HD; d++) q[d] = qb[tid * QB_PITCH + d];
    __syncthreads();

    float m = -INFINITY, l = 0.0f;
    float acc[HD];
    #pragma unroll
    for (int d = 0; d < HD; d++) acc[d] = 0.0f;

    const int n_kv = 2 * qt + 2;
    for (int kt = 0; kt < n_kv; kt++) {
        #pragma unroll
        for (int i = 0; i < 8; i++) {
            int id = i * 128 + tid;
            int r  = id >> 4;
            int c4 = id & 15;
            size_t src = (size_t)(kt * FA_BKV + r) * QKV_OUT;
            ks4[r * 16 + c4] = *reinterpret_cast<const float4*>(&fused[src + KOFF + c4 * 4]);
            vs4[r * 16 + c4] = *reinterpret_cast<const float4*>(&fused[src + VOFF + c4 * 4]);
        }
        __syncthreads();

        float tmax = -INFINITY;
        for (int j = 0; j < FA_BKV; j++) {
            float s0 = 0.f, s1 = 0.f, s2 = 0.f, s3 = 0.f;
            #pragma unroll
            for (int c = 0; c < 16; c++) {
                float4 kk = ks4[j * 16 + c];
                s0 = fmaf(q[4 * c + 0], kk.x, s0);
                s1 = fmaf(q[4 * c + 1], kk.y, s1);
                s2 = fmaf(q[4 * c + 2], kk.z, s2);
                s3 = fmaf(q[4 * c + 3], kk.w, s3);
            }
            float s = ((s0 + s1) + (s2 + s3)) * 0.125f;
            if (kt * FA_BKV + j > row) s = -INFINITY;
            qb[tid * QB_PITCH + j] = s;
            tmax = fmaxf(tmax, s);
        }

        float mnew = fmaxf(m, tmax);
        float corr = __expf(m - mnew);
        l *= corr;
        #pragma unroll
        for (int d = 0; d < HD; d++) acc[d] *= corr;

        float lsum = 0.0f;
        for (int j = 0; j < FA_BKV; j++) {
            float p = __expf(qb[tid * QB_PITCH + j] - mnew);
            lsum += p;
            #pragma unroll
            for (int c = 0; c < 16; c++) {
                float4 vv = vs4[j * 16 + c];
                acc[4 * c + 0] = fmaf(p, vv.x, acc[4 * c + 0]);
                acc[4 * c + 1] = fmaf(p, vv.y, acc[4 * c + 1]);
                acc[4 * c + 2] = fmaf(p, vv.z, acc[4 * c + 2]);
                acc[4 * c + 3] = fmaf(p, vv.w, acc[4 * c + 3]);
            }
        }
        l += lsum;
        m = mnew;
        __syncthreads();
    }

    float inv = 1.0f / l;
    #pragma unroll
    for (int d = 0; d < HD; d++) qb[tid * QB_PITCH + d] = acc[d] * inv;
    __syncthreads();
    #pragma unroll
    for (int i = 0; i < 16; i++) {
        int id = i * 128 + tid;
        int r  = id >> 4;
        int c4 = id & 15;
        float4 v = *(reinterpret_cast<float4*>(qb + r * QB_PITCH) + c4);
        *reinterpret_cast<float4*>(
            &attn_out[(size_t)(qt * FA_BQ + r) * QDIM + h * HD + c4 * 4]) = v;
    }
}

// ---------------- launch ----------------------------------------------------
extern "C" void kernel_launch(void* const* d_in, const int* in_sizes, int n_in,
                              void* d_out, int out_size)
{
    const float* x       = (const float*)d_in[0];
    const float* qkv_w   = (const float*)d_in[1];
    const float* dense_w = (const float*)d_in[2];
    float* out = (float*)d_out;

    float* fused; cudaGetSymbolAddress((void**)&fused, g_fused);
    float* attn;  cudaGetSymbolAddress((void**)&attn,  g_attn);
    __nv_bfloat16 *xh, *xl, *wqh, *wql, *wdh, *wdl, *ah, *al;
    cudaGetSymbolAddress((void**)&xh,  g_xh);  cudaGetSymbolAddress((void**)&xl,  g_xl);
    cudaGetSymbolAddress((void**)&wqh, g_wqh); cudaGetSymbolAddress((void**)&wql, g_wql);
    cudaGetSymbolAddress((void**)&wdh, g_wdh); cudaGetSymbolAddress((void**)&wdl, g_wdl);
    cudaGetSymbolAddress((void**)&ah,  g_ah);  cudaGetSymbolAddress((void**)&al,  g_al);

    const int fa_smem = (FA_BQ * QB_PITCH + 2 * FA_BKV * HD) * (int)sizeof(float);
    cudaFuncSetAttribute(flash_kernel,
                         cudaFuncAttributeMaxDynamicSharedMemorySize, fa_smem);
    cudaFuncSetAttribute(gemm_mma,
                         cudaFuncAttributeMaxDynamicSharedMemorySize, GEMM_SMEM);

    // 1. RoPE table
    rope_table_kernel<<<(SEQ * 32 + 255) / 256, 256>>>();

    // 2. bf16 hi/lo splits of x and qkv weight (padded rows zeroed)
    {
        int t = SEQ * HIDDEN;
        split_kernel<<<(t + 255) / 256, 256>>>(x, xh, xl, t, t);
        int tw = QKV_PAD * HIDDEN, sw = QKV_OUT * HIDDEN;
        split_kernel<<<(tw + 255) / 256, 256>>>(qkv_w, wqh, wql, tw, sw);
    }

    // 3. QKV GEMM (mma.sync bf16-split)
    {
        dim3 grid(QKV_PAD / BNT, SEQ / BMT);
        gemm_mma<<<grid, 256, GEMM_SMEM>>>(xh, xl, wqh, wql, fused,
                                           QKV_OUT, HIDDEN);
    }

    // 4. RoPE on q + k, in place
    {
        int total = SEQ * (NH + 1) * 32;
        rope_apply_kernel<<<(total + 255) / 256, 256>>>();
    }

    // 5. Flash attention
    {
        dim3 grid(SEQ / FA_BQ, NH);
        flash_kernel<<<grid, 128, fa_smem>>>(fused, attn);
    }

    // 6. splits for dense GEMM
    {
        int t = SEQ * HIDDEN;
        split_kernel<<<(t + 255) / 256, 256>>>(attn, ah, al, t, t);
        int tw = DEN_PAD * HIDDEN, sw = HIDDEN * HIDDEN;
        split_kernel<<<(tw + 255) / 256, 256>>>(dense_w, wdh, wdl, tw, sw);
    }

    // 7. Dense GEMM (mma.sync bf16-split) -> out
    {
        dim3 grid(DEN_PAD / BNT, SEQ / BMT);
        gemm_mma<<<grid, 256, GEMM_SMEM>>>(ah, al, wdh, wdl, out,
                                           HIDDEN, HIDDEN);
    }
}

// round 4
// speedup vs baseline: 2.8920x; 1.6083x over previous
#include <cuda_runtime.h>
#include <cuda_bf16.h>
#include <math.h>
#include <stdint.h>

#define SEQ     2048
#define HIDDEN  4544
#define NH      71
#define HD      64
#define QKV_OUT 4672
#define QKV_PAD 4736            // 37*128
#define DEN_PAD 4608            // 36*128
#define QDIM    4544
#define KOFF    4544
#define VOFF    4608

// ---------------- scratch (device globals; no allocations allowed) ----------
__device__ float g_fused[SEQ * QKV_OUT];
__device__ float g_attn [SEQ * QDIM];
__device__ float g_cos  [SEQ * 32];
__device__ float g_sin  [SEQ * 32];
__device__ __nv_bfloat16 g_xh [SEQ * HIDDEN],     g_xl [SEQ * HIDDEN];
__device__ __nv_bfloat16 g_wqh[QKV_PAD * HIDDEN], g_wql[QKV_PAD * HIDDEN];
__device__ __nv_bfloat16 g_wdh[DEN_PAD * HIDDEN], g_wdl[DEN_PAD * HIDDEN];
__device__ __nv_bfloat16 g_ah [SEQ * HIDDEN],     g_al [SEQ * HIDDEN];
// flash inputs (bf16 hi/lo, roped; q pre-scaled by 1/8)
__device__ __nv_bfloat16 g_qsh[NH * SEQ * HD], g_qsl[NH * SEQ * HD];
__device__ __nv_bfloat16 g_ksh[SEQ * HD], g_ksl[SEQ * HD];
__device__ __nv_bfloat16 g_vsh[SEQ * HD], g_vsl[SEQ * HD];

// ================= portable PTX helpers (sm_80+; no tcgen05) ================
__device__ __forceinline__ uint32_t smem_to_u32(const void* p) {
    uint32_t a;
    asm("{ .reg .u64 t; cvta.to.shared.u64 t, %1; cvt.u32.u64 %0, t; }"
        : "=r"(a) : "l"(p));
    return a;
}
__device__ __forceinline__ void ldsm_x4(uint32_t& r0, uint32_t& r1,
                                        uint32_t& r2, uint32_t& r3, uint32_t addr) {
    asm volatile("ldmatrix.sync.aligned.m8n8.x4.shared.b16 {%0,%1,%2,%3}, [%4];"
                 : "=r"(r0), "=r"(r1), "=r"(r2), "=r"(r3) : "r"(addr));
}
__device__ __forceinline__ void ldsm_x4_t(uint32_t& r0, uint32_t& r1,
                                          uint32_t& r2, uint32_t& r3, uint32_t addr) {
    asm volatile("ldmatrix.sync.aligned.m8n8.x4.trans.shared.b16 {%0,%1,%2,%3}, [%4];"
                 : "=r"(r0), "=r"(r1), "=r"(r2), "=r"(r3) : "r"(addr));
}
__device__ __forceinline__ void mma16816(float* c, const uint32_t* a,
                                         uint32_t b0, uint32_t b1) {
    asm volatile("mma.sync.aligned.m16n8k16.row.col.f32.bf16.bf16.f32 "
                 "{%0,%1,%2,%3}, {%4,%5,%6,%7}, {%8,%9}, {%0,%1,%2,%3};"
                 : "+f"(c[0]), "+f"(c[1]), "+f"(c[2]), "+f"(c[3])
                 : "r"(a[0]), "r"(a[1]), "r"(a[2]), "r"(a[3]), "r"(b0), "r"(b1));
}
__device__ __forceinline__ void cp_async16(uint32_t sdst, const void* gsrc) {
    asm volatile("cp.async.cg.shared.global [%0], [%1], 16;" :: "r"(sdst), "l"(gsrc));
}
#define CP_COMMIT() asm volatile("cp.async.commit_group;" ::: "memory")
#define CP_WAIT(n)  asm volatile("cp.async.wait_group %0;" :: "n"(n) : "memory")

__device__ __forceinline__ void split2(float a, float b, uint32_t& hi, uint32_t& lo) {
    __nv_bfloat162 h2 = __floats2bfloat162_rn(a, b);
    hi = *reinterpret_cast<uint32_t*>(&h2);
    float ra = a - __bfloat162float(h2.x);
    float rb = b - __bfloat162float(h2.y);
    __nv_bfloat162 l2 = __floats2bfloat162_rn(ra, rb);
    lo = *reinterpret_cast<uint32_t*>(&l2);
}

// ---------------- RoPE table (fp64 trig for accuracy) -----------------------
__global__ void rope_table_kernel() {
    int idx = blockIdx.x * blockDim.x + threadIdx.x;
    if (idx >= SEQ * 32) return;
    int s = idx >> 5, j = idx & 31;
    double inv = exp(-(double)j / 32.0 * log(10000.0));
    double ang = (double)s * inv;
    g_cos[idx] = (float)cos(ang);
    g_sin[idx] = (float)sin(ang);
}

// ---------------- fp32 -> bf16 hi/lo split ----------------------------------
__global__ void split_kernel(const float* __restrict__ src,
                             __nv_bfloat16* __restrict__ hi,
                             __nv_bfloat16* __restrict__ lo,
                             int total, int src_total)
{
    int i = blockIdx.x * blockDim.x + threadIdx.x;
    if (i >= total) return;
    float a = (i < src_total) ? src[i] : 0.0f;
    __nv_bfloat16 h = __float2bfloat16(a);
    float hf = __bfloat162float(h);
    hi[i] = h;
    lo[i] = __float2bfloat16(a - hf);
}

// ---------------- prep: rope + scale + bf16 hi/lo for q,k,v -----------------
__global__ void prep_kernel() {
    int idx = blockIdx.x * blockDim.x + threadIdx.x;
    const int total = SEQ * (NH + 2) * 32;
    if (idx >= total) return;
    int j  = idx & 31;
    int t  = idx >> 5;
    int hh = t % (NH + 2);
    int s  = t / (NH + 2);
    size_t base = (size_t)s * QKV_OUT + hh * HD;
    float a = g_fused[base + j];
    float b = g_fused[base + j + 32];
    float o1, o2;
    if (hh <= NH) {   // rope for q heads and k
        float c  = g_cos[s * 32 + j];
        float sn = g_sin[s * 32 + j];
        o1 = a * c - b * sn;
        o2 = b * c + a * sn;
    } else {          // v: passthrough
        o1 = a; o2 = b;
    }
    __nv_bfloat16 *dh, *dl;
    size_t doff;
    if (hh < NH) {
        o1 *= 0.125f; o2 *= 0.125f;    // fold softmax scale into q
        dh = g_qsh; dl = g_qsl;
        doff = ((size_t)hh * SEQ + s) * HD;
    } else if (hh == NH) {
        dh = g_ksh; dl = g_ksl;
        doff = (size_t)s * HD;
    } else {
        dh = g_vsh; dl = g_vsl;
        doff = (size_t)s * HD;
    }
    __nv_bfloat16 h1 = __float2bfloat16(o1);
    __nv_bfloat16 h2 = __float2bfloat16(o2);
    dh[doff + j]      = h1;
    dh[doff + j + 32] = h2;
    dl[doff + j]      = __float2bfloat16(o1 - __bfloat162float(h1));
    dl[doff + j + 32] = __float2bfloat16(o2 - __bfloat162float(h2));
}

// ---------------- mma.sync bf16-split GEMM (unchanged, validated) -----------
#define BMT 128
#define BNT 128
#define BKC 32
#define ARR_B (BMT * 40 * 2)
#define STG_B (4 * ARR_B)
#define GEMM_SMEM (2 * STG_B)

__global__ __launch_bounds__(256, 1) void gemm_mma(
    const __nv_bfloat16* __restrict__ Ah, const __nv_bfloat16* __restrict__ Al,
    const __nv_bfloat16* __restrict__ Bh, const __nv_bfloat16* __restrict__ Bl,
    float* __restrict__ C, int N_real, int K)
{
    extern __shared__ __align__(128) char smem[];
    const int tid = threadIdx.x;
    const int wid = tid >> 5;
    const int lid = tid & 31;
    const int m0 = blockIdx.y * BMT;
    const int n0 = blockIdx.x * BNT;
    const int wm = (wid & 1) * 64;
    const int wn = (wid >> 1) * 32;
    const uint32_t sbase = smem_to_u32(smem);

    const int arr = tid >> 6;
    const int t64 = tid & 63;
    const __nv_bfloat16* gp = (arr == 0) ? Ah : (arr == 1) ? Al : (arr == 2) ? Bh : Bl;
    const int rbase = (arr < 2) ? m0 : n0;

#define LOAD_STAGE(s, k0) do {                                                 \
        uint32_t sb_ = sbase + (s) * STG_B + arr * ARR_B;                      \
        _Pragma("unroll")                                                      \
        for (int i_ = 0; i_ < 8; i_++) {                                       \
            int id_ = i_ * 64 + t64;                                           \
            int r_ = id_ >> 2, ch_ = id_ & 3;                                  \
            cp_async16(sb_ + r_ * 80 + ch_ * 16,                               \
                       gp + (size_t)(rbase + r_) * K + (k0) + ch_ * 8);        \
        }                                                                      \
    } while (0)

    float acc[4][4][4];
    #pragma unroll
    for (int i = 0; i < 4; i++)
        #pragma unroll
        for (int j = 0; j < 4; j++)
            #pragma unroll
            for (int e = 0; e < 4; e++) acc[i][j][e] = 0.0f;

    LOAD_STAGE(0, 0);
    CP_COMMIT();

    const int arow = (lid & 7) | (((lid >> 3) & 1) << 3);
    const int acolh = (lid >> 4) * 8;
    const int brow = (lid & 7) + ((lid >> 4) & 1) * 8;
    const int bcolh = ((lid >> 3) & 1) * 8;

    const int nchunk = K / BKC;
    for (int c = 0; c < nchunk; c++) {
        const int cur = c & 1;
        if (c + 1 < nchunk) {
            LOAD_STAGE(cur ^ 1, (c + 1) * BKC);
            CP_COMMIT();
            CP_WAIT(1);
        } else {
            CP_WAIT(0);
        }
        __syncthreads();

        const uint32_t sAh = sbase + cur * STG_B;
        const uint32_t sAl = sAh + ARR_B;
        const uint32_t sBh = sAh + 2 * ARR_B;
        const uint32_t sBl = sAh + 3 * ARR_B;

        #pragma unroll
        for (int kk = 0; kk < 2; kk++) {
            const int kc = kk * 16;
            uint32_t ah[4][4], al[4][4], bh[2][4], bl[2][4];
            #pragma unroll
            for (int i = 0; i < 4; i++) {
                uint32_t off = (uint32_t)((wm + i * 16 + arow) * 80 + (kc + acolh) * 2);
                ldsm_x4(ah[i][0], ah[i][1], ah[i][2], ah[i][3], sAh + off);
                ldsm_x4(al[i][0], al[i][1], al[i][2], al[i][3], sAl + off);
            }
            #pragma unroll
            for (int j = 0; j < 2; j++) {
                uint32_t off = (uint32_t)((wn + j * 16 + brow) * 80 + (kc + bcolh) * 2);
                ldsm_x4(bh[j][0], bh[j][1], bh[j][2], bh[j][3], sBh + off);
                ldsm_x4(bl[j][0], bl[j][1], bl[j][2], bl[j][3], sBl + off);
            }
            #pragma unroll
            for (int i = 0; i < 4; i++) {
                #pragma unroll
                for (int j = 0; j < 2; j++) {
                    mma16816(acc[i][j * 2 + 0], ah[i], bh[j][0], bh[j][1]);
                    mma16816(acc[i][j * 2 + 1], ah[i], bh[j][2], bh[j][3]);
                    mma16816(acc[i][j * 2 + 0], ah[i], bl[j][0], bl[j][1]);
                    mma16816(acc[i][j * 2 + 1], ah[i], bl[j][2], bl[j][3]);
                    mma16816(acc[i][j * 2 + 0], al[i], bh[j][0], bh[j][1]);
                    mma16816(acc[i][j * 2 + 1], al[i], bh[j][2], bh[j][3]);
                }
            }
        }
        __syncthreads();
    }

    const int gr = lid >> 2, tg = lid & 3;
    #pragma unroll
    for (int i = 0; i < 4; i++) {
        #pragma unroll
        for (int j = 0; j < 4; j++) {
            int col = n0 + wn + j * 8 + tg * 2;
            if (col < N_real) {
                int row = m0 + wm + i * 16 + gr;
                float2 v0 = make_float2(acc[i][j][0], acc[i][j][1]);
                float2 v1 = make_float2(acc[i][j][2], acc[i][j][3]);
                *reinterpret_cast<float2*>(&C[(size_t)row * N_real + col]) = v0;
                *reinterpret_cast<float2*>(&C[(size_t)(row + 8) * N_real + col]) = v1;
            }
        }
    }
#undef LOAD_STAGE
}

// ---------------- flash attention via mma.sync (MQA, causal) -----------------
// Q tile 128 x 64, KV tile 128 x 64. 8 warps, each owns 16 q rows.
#define FROW_B 144                       // smem pitch bytes (72 bf16)
#define QARR_B (128 * FROW_B)            // 18432 per array
#define KV_STG (4 * QARR_B)              // Kh,Kl,Vh,Vl
#define FA_SMEM (2 * QARR_B + 2 * KV_STG) // 184320

__global__ __launch_bounds__(256, 1) void flash_mma(
    const __nv_bfloat16* __restrict__ qh, const __nv_bfloat16* __restrict__ ql,
    const __nv_bfloat16* __restrict__ kh, const __nv_bfloat16* __restrict__ kl,
    const __nv_bfloat16* __restrict__ vh, const __nv_bfloat16* __restrict__ vl,
    float* __restrict__ attn_out)
{
    extern __shared__ __align__(128) char smem[];
    const int tid = threadIdx.x, wid = tid >> 5, lid = tid & 31;
    const int qt = blockIdx.x, h = blockIdx.y;
    const int q0 = qt * 128;
    const uint32_t sb = smem_to_u32(smem);
    const uint32_t sQh = sb, sQl = sb + QARR_B;
    const uint32_t sKV = sb + 2 * QARR_B;

    // Q tile hi/lo
    {
        const __nv_bfloat16* srcs[2] = {qh, ql};
        #pragma unroll
        for (int i = 0; i < 8; i++) {
            int id = i * 256 + tid;
            int a = id >> 10, w = id & 1023, r = w >> 3, c = w & 7;
            cp_async16(sb + a * QARR_B + r * FROW_B + c * 16,
                       srcs[a] + ((size_t)h * SEQ + q0 + r) * HD + c * 8);
        }
    }
    const __nv_bfloat16* kvsrc[4] = {kh, kl, vh, vl};
#define LOAD_KV(s, kt_) do {                                                   \
        _Pragma("unroll")                                                      \
        for (int i_ = 0; i_ < 16; i_++) {                                      \
            int id_ = i_ * 256 + tid;                                          \
            int a_ = id_ >> 10, w_ = id_ & 1023, r_ = w_ >> 3, c_ = w_ & 7;    \
            cp_async16(sKV + (s) * KV_STG + a_ * QARR_B + r_ * FROW_B + c_ * 16, \
                       kvsrc[a_] + ((size_t)((kt_) * 128 + r_)) * HD + c_ * 8); \
        }                                                                      \
    } while (0)
    LOAD_KV(0, 0);
    CP_COMMIT();
    CP_WAIT(0);
    __syncthreads();

    const int arow  = (lid & 7) | (((lid >> 3) & 1) << 3);
    const int acolh = (lid >> 4) * 8;
    const int brow  = (lid & 7) + ((lid >> 4) & 1) * 8;
    const int bcolh = ((lid >> 3) & 1) * 8;

    uint32_t aqh[4][4], aql[4][4];
    #pragma unroll
    for (int k = 0; k < 4; k++) {
        uint32_t off = (uint32_t)((wid * 16 + arow) * FROW_B + (k * 16 + acolh) * 2);
        ldsm_x4(aqh[k][0], aqh[k][1], aqh[k][2], aqh[k][3], sQh + off);
        ldsm_x4(aql[k][0], aql[k][1], aql[k][2], aql[k][3], sQl + off);
    }

    float acc[8][4];
    #pragma unroll
    for (int g = 0; g < 8; g++)
        #pragma unroll
        for (int e = 0; e < 4; e++) acc[g][e] = 0.0f;
    float m0 = -1e30f, m1 = -1e30f, l0 = 0.0f, l1 = 0.0f;
    const int row0 = q0 + wid * 16 + (lid >> 2);

    const int nkv = qt + 1;
    for (int kt = 0; kt < nkv; kt++) {
        const int cur = kt & 1;
        if (kt + 1 < nkv) { LOAD_KV(cur ^ 1, kt + 1); CP_COMMIT(); }
        const uint32_t sK  = sKV + cur * KV_STG;
        const uint32_t sKl = sK + QARR_B;
        const uint32_t sV  = sK + 2 * QARR_B;
        const uint32_t sVl = sK + 3 * QARR_B;

        // ---- scores S = Q K^T (3-term split) ----
        float sc[16][4];
        #pragma unroll
        for (int t = 0; t < 16; t++)
            #pragma unroll
            for (int e = 0; e < 4; e++) sc[t][e] = 0.0f;

        #pragma unroll
        for (int j2 = 0; j2 < 8; j2++) {
            #pragma unroll
            for (int k = 0; k < 4; k++) {
                uint32_t off = (uint32_t)((j2 * 16 + brow) * FROW_B + (k * 16 + bcolh) * 2);
                uint32_t b0, b1, b2, b3, c0, c1, c2, c3;
                ldsm_x4(b0, b1, b2, b3, sK + off);
                ldsm_x4(c0, c1, c2, c3, sKl + off);
                mma16816(sc[j2 * 2],     aqh[k], b0, b1);
                mma16816(sc[j2 * 2 + 1], aqh[k], b2, b3);
                mma16816(sc[j2 * 2],     aqh[k], c0, c1);
                mma16816(sc[j2 * 2 + 1], aqh[k], c2, c3);
                mma16816(sc[j2 * 2],     aql[k], b0, b1);
                mma16816(sc[j2 * 2 + 1], aql[k], b2, b3);
            }
        }

        // ---- causal mask (diag tile only) ----
        if (kt == qt) {
            #pragma unroll
            for (int t = 0; t < 16; t++) {
                int colb = kt * 128 + t * 8 + (lid & 3) * 2;
                if (colb     > row0)     sc[t][0] = -1e30f;
                if (colb + 1 > row0)     sc[t][1] = -1e30f;
                if (colb     > row0 + 8) sc[t][2] = -1e30f;
                if (colb + 1 > row0 + 8) sc[t][3] = -1e30f;
            }
        }

        // ---- online softmax ----
        float mn0 = m0, mn1 = m1;
        #pragma unroll
        for (int t = 0; t < 16; t++) {
            mn0 = fmaxf(mn0, fmaxf(sc[t][0], sc[t][1]));
            mn1 = fmaxf(mn1, fmaxf(sc[t][2], sc[t][3]));
        }
        mn0 = fmaxf(mn0, __shfl_xor_sync(0xffffffffu, mn0, 1));
        mn0 = fmaxf(mn0, __shfl_xor_sync(0xffffffffu, mn0, 2));
        mn1 = fmaxf(mn1, __shfl_xor_sync(0xffffffffu, mn1, 1));
        mn1 = fmaxf(mn1, __shfl_xor_sync(0xffffffffu, mn1, 2));
        float corr0 = __expf(m0 - mn0);
        float corr1 = __expf(m1 - mn1);

        uint32_t phi[16][2], plo[16][2];
        float ls0 = 0.0f, ls1 = 0.0f;
        #pragma unroll
        for (int t = 0; t < 16; t++) {
            float p0 = __expf(sc[t][0] - mn0);
            float p1 = __expf(sc[t][1] - mn0);
            float p2 = __expf(sc[t][2] - mn1);
            float p3 = __expf(sc[t][3] - mn1);
            ls0 += p0 + p1;  ls1 += p2 + p3;
            split2(p0, p1, phi[t][0], plo[t][0]);
            split2(p2, p3, phi[t][1], plo[t][1]);
        }
        ls0 += __shfl_xor_sync(0xffffffffu, ls0, 1);
        ls0 += __shfl_xor_sync(0xffffffffu, ls0, 2);
        ls1 += __shfl_xor_sync(0xffffffffu, ls1, 1);
        ls1 += __shfl_xor_sync(0xffffffffu, ls1, 2);
        l0 = l0 * corr0 + ls0;  l1 = l1 * corr1 + ls1;
        m0 = mn0;  m1 = mn1;
        #pragma unroll
        for (int g = 0; g < 8; g++) {
            acc[g][0] *= corr0; acc[g][1] *= corr0;
            acc[g][2] *= corr1; acc[g][3] *= corr1;
        }

        // ---- O += P V (3-term split), V B-frags via ldmatrix.trans ----
        #pragma unroll
        for (int k = 0; k < 8; k++) {
            uint32_t ph_[4] = {phi[k * 2][0], phi[k * 2][1], phi[k * 2 + 1][0], phi[k * 2 + 1][1]};
            uint32_t pl_[4] = {plo[k * 2][0], plo[k * 2][1], plo[k * 2 + 1][0], plo[k * 2 + 1][1]};
            #pragma unroll
            for (int g = 0; g < 4; g++) {
                uint32_t off = (uint32_t)((k * 16 + (lid & 15)) * FROW_B +
                                          (g * 16 + ((lid >> 4) & 1) * 8) * 2);
                uint32_t v0, v1, v2, v3, w0, w1, w2, w3;
                ldsm_x4_t(v0, v1, v2, v3, sV + off);
                ldsm_x4_t(w0, w1, w2, w3, sVl + off);
                mma16816(acc[g * 2],     ph_, v0, v1);
                mma16816(acc[g * 2 + 1], ph_, v2, v3);
                mma16816(acc[g * 2],     ph_, w0, w1);
                mma16816(acc[g * 2 + 1], ph_, w2, w3);
                mma16816(acc[g * 2],     pl_, v0, v1);
                mma16816(acc[g * 2 + 1], pl_, v2, v3);
            }
        }

        if (kt + 1 < nkv) CP_WAIT(0);
        __syncthreads();
    }
#undef LOAD_KV

    float inv0 = 1.0f / l0, inv1 = 1.0f / l1;
    #pragma unroll
    for (int g = 0; g < 8; g++) {
        int col = h * HD + g * 8 + (lid & 3) * 2;
        int r = q0 + wid * 16 + (lid >> 2);
        float2 o0 = make_float2(acc[g][0] * inv0, acc[g][1] * inv0);
        float2 o1 = make_float2(acc[g][2] * inv1, acc[g][3] * inv1);
        *reinterpret_cast<float2*>(&attn_out[(size_t)r * QDIM + col]) = o0;
        *reinterpret_cast<float2*>(&attn_out[(size_t)(r + 8) * QDIM + col]) = o1;
    }
}

// ---------------- launch ----------------------------------------------------
extern "C" void kernel_launch(void* const* d_in, const int* in_sizes, int n_in,
                              void* d_out, int out_size)
{
    const float* x       = (const float*)d_in[0];
    const float* qkv_w   = (const float*)d_in[1];
    const float* dense_w = (const float*)d_in[2];
    float* out = (float*)d_out;

    float* fused; cudaGetSymbolAddress((void**)&fused, g_fused);
    float* attn;  cudaGetSymbolAddress((void**)&attn,  g_attn);
    __nv_bfloat16 *xh, *xl, *wqh, *wql, *wdh, *wdl, *ah, *al;
    __nv_bfloat16 *qsh, *qsl, *ksh, *ksl, *vsh, *vsl;
    cudaGetSymbolAddress((void**)&xh,  g_xh);  cudaGetSymbolAddress((void**)&xl,  g_xl);
    cudaGetSymbolAddress((void**)&wqh, g_wqh); cudaGetSymbolAddress((void**)&wql, g_wql);
    cudaGetSymbolAddress((void**)&wdh, g_wdh); cudaGetSymbolAddress((void**)&wdl, g_wdl);
    cudaGetSymbolAddress((void**)&ah,  g_ah);  cudaGetSymbolAddress((void**)&al,  g_al);
    cudaGetSymbolAddress((void**)&qsh, g_qsh); cudaGetSymbolAddress((void**)&qsl, g_qsl);
    cudaGetSymbolAddress((void**)&ksh, g_ksh); cudaGetSymbolAddress((void**)&ksl, g_ksl);
    cudaGetSymbolAddress((void**)&vsh, g_vsh); cudaGetSymbolAddress((void**)&vsl, g_vsl);

    cudaFuncSetAttribute(gemm_mma,
                         cudaFuncAttributeMaxDynamicSharedMemorySize, GEMM_SMEM);
    cudaFuncSetAttribute(flash_mma,
                         cudaFuncAttributeMaxDynamicSharedMemorySize, FA_SMEM);

    // 1. RoPE table
    rope_table_kernel<<<(SEQ * 32 + 255) / 256, 256>>>();

    // 2. bf16 hi/lo splits of x and qkv weight
    {
        int t = SEQ * HIDDEN;
        split_kernel<<<(t + 255) / 256, 256>>>(x, xh, xl, t, t);
        int tw = QKV_PAD * HIDDEN, sw = QKV_OUT * HIDDEN;
        split_kernel<<<(tw + 255) / 256, 256>>>(qkv_w, wqh, wql, tw, sw);
    }

    // 3. QKV GEMM
    {
        dim3 grid(QKV_PAD / BNT, SEQ / BMT);
        gemm_mma<<<grid, 256, GEMM_SMEM>>>(xh, xl, wqh, wql, fused,
                                           QKV_OUT, HIDDEN);
    }

    // 4. prep: rope + scale + hi/lo split of q, k, v
    {
        int total = SEQ * (NH + 2) * 32;
        prep_kernel<<<(total + 255) / 256, 256>>>();
    }

    // 5. flash attention (tensor cores)
    {
        dim3 grid(SEQ / 128, NH);
        flash_mma<<<grid, 256, FA_SMEM>>>(qsh, qsl, ksh, ksl, vsh, vsl, attn);
    }

    // 6. splits for dense GEMM
    {
        int t = SEQ * HIDDEN;
        split_kernel<<<(t + 255) / 256, 256>>>(attn, ah, al, t, t);
        int tw = DEN_PAD * HIDDEN, sw = HIDDEN * HIDDEN;
        split_kernel<<<(tw + 255) / 256, 256>>>(dense_w, wdh, wdl, tw, sw);
    }

    // 7. dense GEMM -> out
    {
        dim3 grid(DEN_PAD / BNT, SEQ / BMT);
        gemm_mma<<<grid, 256, GEMM_SMEM>>>(ah, al, wdh, wdl, out,
                                           HIDDEN, HIDDEN);
    }
}

// round 5
// speedup vs baseline: 3.1930x; 1.1041x over previous
#include <cuda_runtime.h>
#include <cuda_bf16.h>
#include <math.h>
#include <stdint.h>

#define SEQ     2048
#define HIDDEN  4544
#define NH      71
#define HD      64
#define QKV_OUT 4672
#define QKV_PAD 4736            // 37*128
#define DEN_PAD 4608            // 36*128
#define QDIM    4544

// ---------------- scratch (device globals; no allocations allowed) ----------
__device__ float g_fused[SEQ * QKV_OUT];
__device__ float g_cos  [SEQ * 32];
__device__ float g_sin  [SEQ * 32];
__device__ __nv_bfloat16 g_xh [SEQ * HIDDEN],     g_xl [SEQ * HIDDEN];
__device__ __nv_bfloat16 g_wqh[QKV_PAD * HIDDEN], g_wql[QKV_PAD * HIDDEN];
__device__ __nv_bfloat16 g_wdh[DEN_PAD * HIDDEN], g_wdl[DEN_PAD * HIDDEN];
__device__ __nv_bfloat16 g_ah [SEQ * HIDDEN],     g_al [SEQ * HIDDEN];
// flash inputs (bf16 hi/lo, roped; q pre-scaled by 1/8)
__device__ __nv_bfloat16 g_qsh[NH * SEQ * HD], g_qsl[NH * SEQ * HD];
__device__ __nv_bfloat16 g_ksh[SEQ * HD], g_ksl[SEQ * HD];
__device__ __nv_bfloat16 g_vsh[SEQ * HD], g_vsl[SEQ * HD];

// ================= portable PTX helpers (sm_80+; no tcgen05) ================
__device__ __forceinline__ uint32_t smem_to_u32(const void* p) {
    uint32_t a;
    asm("{ .reg .u64 t; cvta.to.shared.u64 t, %1; cvt.u32.u64 %0, t; }"
        : "=r"(a) : "l"(p));
    return a;
}
__device__ __forceinline__ void ldsm_x4(uint32_t& r0, uint32_t& r1,
                                        uint32_t& r2, uint32_t& r3, uint32_t addr) {
    asm volatile("ldmatrix.sync.aligned.m8n8.x4.shared.b16 {%0,%1,%2,%3}, [%4];"
                 : "=r"(r0), "=r"(r1), "=r"(r2), "=r"(r3) : "r"(addr));
}
__device__ __forceinline__ void ldsm_x4_t(uint32_t& r0, uint32_t& r1,
                                          uint32_t& r2, uint32_t& r3, uint32_t addr) {
    asm volatile("ldmatrix.sync.aligned.m8n8.x4.trans.shared.b16 {%0,%1,%2,%3}, [%4];"
                 : "=r"(r0), "=r"(r1), "=r"(r2), "=r"(r3) : "r"(addr));
}
__device__ __forceinline__ void mma16816(float* c, const uint32_t* a,
                                         uint32_t b0, uint32_t b1) {
    asm volatile("mma.sync.aligned.m16n8k16.row.col.f32.bf16.bf16.f32 "
                 "{%0,%1,%2,%3}, {%4,%5,%6,%7}, {%8,%9}, {%0,%1,%2,%3};"
                 : "+f"(c[0]), "+f"(c[1]), "+f"(c[2]), "+f"(c[3])
                 : "r"(a[0]), "r"(a[1]), "r"(a[2]), "r"(a[3]), "r"(b0), "r"(b1));
}
__device__ __forceinline__ void cp_async16(uint32_t sdst, const void* gsrc) {
    asm volatile("cp.async.cg.shared.global [%0], [%1], 16;" :: "r"(sdst), "l"(gsrc));
}
#define CP_COMMIT() asm volatile("cp.async.commit_group;" ::: "memory")
#define CP_WAIT(n)  asm volatile("cp.async.wait_group %0;" :: "n"(n) : "memory")

__device__ __forceinline__ void split2(float a, float b, uint32_t& hi, uint32_t& lo) {
    __nv_bfloat162 h2 = __floats2bfloat162_rn(a, b);
    hi = *reinterpret_cast<uint32_t*>(&h2);
    float ra = a - __bfloat162float(h2.x);
    float rb = b - __bfloat162float(h2.y);
    __nv_bfloat162 l2 = __floats2bfloat162_rn(ra, rb);
    lo = *reinterpret_cast<uint32_t*>(&l2);
}

// ---------------- RoPE table (fp64 trig for accuracy) -----------------------
__global__ void rope_table_kernel() {
    int idx = blockIdx.x * blockDim.x + threadIdx.x;
    if (idx >= SEQ * 32) return;
    int s = idx >> 5, j = idx & 31;
    double inv = exp(-(double)j / 32.0 * log(10000.0));
    double ang = (double)s * inv;
    g_cos[idx] = (float)cos(ang);
    g_sin[idx] = (float)sin(ang);
}

// ---------------- fp32 -> bf16 hi/lo split ----------------------------------
__global__ void split_kernel(const float* __restrict__ src,
                             __nv_bfloat16* __restrict__ hi,
                             __nv_bfloat16* __restrict__ lo,
                             int total, int src_total)
{
    int i = blockIdx.x * blockDim.x + threadIdx.x;
    if (i >= total) return;
    float a = (i < src_total) ? src[i] : 0.0f;
    __nv_bfloat16 h = __float2bfloat16(a);
    float hf = __bfloat162float(h);
    hi[i] = h;
    lo[i] = __float2bfloat16(a - hf);
}

// ---------------- prep: rope + scale + bf16 hi/lo for q,k,v -----------------
__global__ void prep_kernel() {
    int idx = blockIdx.x * blockDim.x + threadIdx.x;
    const int total = SEQ * (NH + 2) * 32;
    if (idx >= total) return;
    int j  = idx & 31;
    int t  = idx >> 5;
    int hh = t % (NH + 2);
    int s  = t / (NH + 2);
    size_t base = (size_t)s * QKV_OUT + hh * HD;
    float a = g_fused[base + j];
    float b = g_fused[base + j + 32];
    float o1, o2;
    if (hh <= NH) {   // rope for q heads and k
        float c  = g_cos[s * 32 + j];
        float sn = g_sin[s * 32 + j];
        o1 = a * c - b * sn;
        o2 = b * c + a * sn;
    } else {          // v: passthrough
        o1 = a; o2 = b;
    }
    __nv_bfloat16 *dh, *dl;
    size_t doff;
    if (hh < NH) {
        o1 *= 0.125f; o2 *= 0.125f;    // fold softmax scale into q
        dh = g_qsh; dl = g_qsl;
        doff = ((size_t)hh * SEQ + s) * HD;
    } else if (hh == NH) {
        dh = g_ksh; dl = g_ksl;
        doff = (size_t)s * HD;
    } else {
        dh = g_vsh; dl = g_vsl;
        doff = (size_t)s * HD;
    }
    __nv_bfloat16 h1 = __float2bfloat16(o1);
    __nv_bfloat16 h2 = __float2bfloat16(o2);
    dh[doff + j]      = h1;
    dh[doff + j + 32] = h2;
    dl[doff + j]      = __float2bfloat16(o1 - __bfloat162float(h1));
    dl[doff + j + 32] = __float2bfloat16(o2 - __bfloat162float(h2));
}

// ---------------- mma.sync bf16-split GEMM ----------------------------------
// C[m,n] = sum_k A[m,k]*B[n,k]  via  Ah*Bh + Ah*Bl + Al*Bh (drop Al*Bl).
// Tile 128x128, K-chunk 32, cp.async double buffer, 8 warps (64x32 warptiles).
// __launch_bounds__(256, 2): 2 CTAs/SM so tensor-pipe bubbles overlap.
#define BMT 128
#define BNT 128
#define BKC 32
#define ARR_B (BMT * 40 * 2)
#define STG_B (4 * ARR_B)
#define GEMM_SMEM (2 * STG_B)

__global__ __launch_bounds__(256, 2) void gemm_mma(
    const __nv_bfloat16* __restrict__ Ah, const __nv_bfloat16* __restrict__ Al,
    const __nv_bfloat16* __restrict__ Bh, const __nv_bfloat16* __restrict__ Bl,
    float* __restrict__ C, int N_real, int K)
{
    extern __shared__ __align__(128) char smem[];
    const int tid = threadIdx.x;
    const int wid = tid >> 5;
    const int lid = tid & 31;
    const int m0 = blockIdx.y * BMT;
    const int n0 = blockIdx.x * BNT;
    const int wm = (wid & 1) * 64;
    const int wn = (wid >> 1) * 32;
    const uint32_t sbase = smem_to_u32(smem);

    const int arr = tid >> 6;
    const int t64 = tid & 63;
    const __nv_bfloat16* gp = (arr == 0) ? Ah : (arr == 1) ? Al : (arr == 2) ? Bh : Bl;
    const int rbase = (arr < 2) ? m0 : n0;

#define LOAD_STAGE(s, k0) do {                                                 \
        uint32_t sb_ = sbase + (s) * STG_B + arr * ARR_B;                      \
        _Pragma("unroll")                                                      \
        for (int i_ = 0; i_ < 8; i_++) {                                       \
            int id_ = i_ * 64 + t64;                                           \
            int r_ = id_ >> 2, ch_ = id_ & 3;                                  \
            cp_async16(sb_ + r_ * 80 + ch_ * 16,                               \
                       gp + (size_t)(rbase + r_) * K + (k0) + ch_ * 8);        \
        }                                                                      \
    } while (0)

    float acc[4][4][4];
    #pragma unroll
    for (int i = 0; i < 4; i++)
        #pragma unroll
        for (int j = 0; j < 4; j++)
            #pragma unroll
            for (int e = 0; e < 4; e++) acc[i][j][e] = 0.0f;

    LOAD_STAGE(0, 0);
    CP_COMMIT();

    const int arow = (lid & 7) | (((lid >> 3) & 1) << 3);
    const int acolh = (lid >> 4) * 8;
    const int brow = (lid & 7) + ((lid >> 4) & 1) * 8;
    const int bcolh = ((lid >> 3) & 1) * 8;

    const int nchunk = K / BKC;
    for (int c = 0; c < nchunk; c++) {
        const int cur = c & 1;
        if (c + 1 < nchunk) {
            LOAD_STAGE(cur ^ 1, (c + 1) * BKC);
            CP_COMMIT();
            CP_WAIT(1);
        } else {
            CP_WAIT(0);
        }
        __syncthreads();

        const uint32_t sAh = sbase + cur * STG_B;
        const uint32_t sAl = sAh + ARR_B;
        const uint32_t sBh = sAh + 2 * ARR_B;
        const uint32_t sBl = sAh + 3 * ARR_B;

        #pragma unroll
        for (int kk = 0; kk < 2; kk++) {
            const int kc = kk * 16;
            uint32_t ah[4][4], al[4][4], bh[2][4], bl[2][4];
            #pragma unroll
            for (int i = 0; i < 4; i++) {
                uint32_t off = (uint32_t)((wm + i * 16 + arow) * 80 + (kc + acolh) * 2);
                ldsm_x4(ah[i][0], ah[i][1], ah[i][2], ah[i][3], sAh + off);
                ldsm_x4(al[i][0], al[i][1], al[i][2], al[i][3], sAl + off);
            }
            #pragma unroll
            for (int j = 0; j < 2; j++) {
                uint32_t off = (uint32_t)((wn + j * 16 + brow) * 80 + (kc + bcolh) * 2);
                ldsm_x4(bh[j][0], bh[j][1], bh[j][2], bh[j][3], sBh + off);
                ldsm_x4(bl[j][0], bl[j][1], bl[j][2], bl[j][3], sBl + off);
            }
            #pragma unroll
            for (int i = 0; i < 4; i++) {
                #pragma unroll
                for (int j = 0; j < 2; j++) {
                    mma16816(acc[i][j * 2 + 0], ah[i], bh[j][0], bh[j][1]);
                    mma16816(acc[i][j * 2 + 1], ah[i], bh[j][2], bh[j][3]);
                    mma16816(acc[i][j * 2 + 0], ah[i], bl[j][0], bl[j][1]);
                    mma16816(acc[i][j * 2 + 1], ah[i], bl[j][2], bl[j][3]);
                    mma16816(acc[i][j * 2 + 0], al[i], bh[j][0], bh[j][1]);
                    mma16816(acc[i][j * 2 + 1], al[i], bh[j][2], bh[j][3]);
                }
            }
        }
        __syncthreads();
    }

    const int gr = lid >> 2, tg = lid & 3;
    #pragma unroll
    for (int i = 0; i < 4; i++) {
        #pragma unroll
        for (int j = 0; j < 4; j++) {
            int col = n0 + wn + j * 8 + tg * 2;
            if (col < N_real) {
                int row = m0 + wm + i * 16 + gr;
                float2 v0 = make_float2(acc[i][j][0], acc[i][j][1]);
                float2 v1 = make_float2(acc[i][j][2], acc[i][j][3]);
                *reinterpret_cast<float2*>(&C[(size_t)row * N_real + col]) = v0;
                *reinterpret_cast<float2*>(&C[(size_t)(row + 8) * N_real + col]) = v1;
            }
        }
    }
#undef LOAD_STAGE
}

// ---------------- flash attention via mma.sync (MQA, causal) -----------------
// Q tile 128 x 64, KV tile 128 x 64. 8 warps, each owns 16 q rows.
// Emits bf16 hi/lo directly (fused activation split for the dense GEMM).
#define FROW_B 144
#define QARR_B (128 * FROW_B)
#define KV_STG (4 * QARR_B)
#define FA_SMEM (2 * QARR_B + 2 * KV_STG)

__global__ __launch_bounds__(256, 1) void flash_mma(
    const __nv_bfloat16* __restrict__ qh, const __nv_bfloat16* __restrict__ ql,
    const __nv_bfloat16* __restrict__ kh, const __nv_bfloat16* __restrict__ kl,
    const __nv_bfloat16* __restrict__ vh, const __nv_bfloat16* __restrict__ vl,
    __nv_bfloat16* __restrict__ oh, __nv_bfloat16* __restrict__ ol)
{
    extern __shared__ __align__(128) char smem[];
    const int tid = threadIdx.x, wid = tid >> 5, lid = tid & 31;
    const int qt = blockIdx.x, h = blockIdx.y;
    const int q0 = qt * 128;
    const uint32_t sb = smem_to_u32(smem);
    const uint32_t sQh = sb, sQl = sb + QARR_B;
    const uint32_t sKV = sb + 2 * QARR_B;

    {
        const __nv_bfloat16* srcs[2] = {qh, ql};
        #pragma unroll
        for (int i = 0; i < 8; i++) {
            int id = i * 256 + tid;
            int a = id >> 10, w = id & 1023, r = w >> 3, c = w & 7;
            cp_async16(sb + a * QARR_B + r * FROW_B + c * 16,
                       srcs[a] + ((size_t)h * SEQ + q0 + r) * HD + c * 8);
        }
    }
    const __nv_bfloat16* kvsrc[4] = {kh, kl, vh, vl};
#define LOAD_KV(s, kt_) do {                                                   \
        _Pragma("unroll")                                                      \
        for (int i_ = 0; i_ < 16; i_++) {                                      \
            int id_ = i_ * 256 + tid;                                          \
            int a_ = id_ >> 10, w_ = id_ & 1023, r_ = w_ >> 3, c_ = w_ & 7;    \
            cp_async16(sKV + (s) * KV_STG + a_ * QARR_B + r_ * FROW_B + c_ * 16, \
                       kvsrc[a_] + ((size_t)((kt_) * 128 + r_)) * HD + c_ * 8); \
        }                                                                      \
    } while (0)
    LOAD_KV(0, 0);
    CP_COMMIT();
    CP_WAIT(0);
    __syncthreads();

    const int arow  = (lid & 7) | (((lid >> 3) & 1) << 3);
    const int acolh = (lid >> 4) * 8;
    const int brow  = (lid & 7) + ((lid >> 4) & 1) * 8;
    const int bcolh = ((lid >> 3) & 1) * 8;

    uint32_t aqh[4][4], aql[4][4];
    #pragma unroll
    for (int k = 0; k < 4; k++) {
        uint32_t off = (uint32_t)((wid * 16 + arow) * FROW_B + (k * 16 + acolh) * 2);
        ldsm_x4(aqh[k][0], aqh[k][1], aqh[k][2], aqh[k][3], sQh + off);
        ldsm_x4(aql[k][0], aql[k][1], aql[k][2], aql[k][3], sQl + off);
    }

    float acc[8][4];
    #pragma unroll
    for (int g = 0; g < 8; g++)
        #pragma unroll
        for (int e = 0; e < 4; e++) acc[g][e] = 0.0f;
    float m0 = -1e30f, m1 = -1e30f, l0 = 0.0f, l1 = 0.0f;
    const int row0 = q0 + wid * 16 + (lid >> 2);

    const int nkv = qt + 1;
    for (int kt = 0; kt < nkv; kt++) {
        const int cur = kt & 1;
        if (kt + 1 < nkv) { LOAD_KV(cur ^ 1, kt + 1); CP_COMMIT(); }
        const uint32_t sK  = sKV + cur * KV_STG;
        const uint32_t sKl = sK + QARR_B;
        const uint32_t sV  = sK + 2 * QARR_B;
        const uint32_t sVl = sK + 3 * QARR_B;

        float sc[16][4];
        #pragma unroll
        for (int t = 0; t < 16; t++)
            #pragma unroll
            for (int e = 0; e < 4; e++) sc[t][e] = 0.0f;

        #pragma unroll
        for (int j2 = 0; j2 < 8; j2++) {
            #pragma unroll
            for (int k = 0; k < 4; k++) {
                uint32_t off = (uint32_t)((j2 * 16 + brow) * FROW_B + (k * 16 + bcolh) * 2);
                uint32_t b0, b1, b2, b3, c0, c1, c2, c3;
                ldsm_x4(b0, b1, b2, b3, sK + off);
                ldsm_x4(c0, c1, c2, c3, sKl + off);
                mma16816(sc[j2 * 2],     aqh[k], b0, b1);
                mma16816(sc[j2 * 2 + 1], aqh[k], b2, b3);
                mma16816(sc[j2 * 2],     aqh[k], c0, c1);
                mma16816(sc[j2 * 2 + 1], aqh[k], c2, c3);
                mma16816(sc[j2 * 2],     aql[k], b0, b1);
                mma16816(sc[j2 * 2 + 1], aql[k], b2, b3);
            }
        }

        if (kt == qt) {
            #pragma unroll
            for (int t = 0; t < 16; t++) {
                int colb = kt * 128 + t * 8 + (lid & 3) * 2;
                if (colb     > row0)     sc[t][0] = -1e30f;
                if (colb + 1 > row0)     sc[t][1] = -1e30f;
                if (colb     > row0 + 8) sc[t][2] = -1e30f;
                if (colb + 1 > row0 + 8) sc[t][3] = -1e30f;
            }
        }

        float mn0 = m0, mn1 = m1;
        #pragma unroll
        for (int t = 0; t < 16; t++) {
            mn0 = fmaxf(mn0, fmaxf(sc[t][0], sc[t][1]));
            mn1 = fmaxf(mn1, fmaxf(sc[t][2], sc[t][3]));
        }
        mn0 = fmaxf(mn0, __shfl_xor_sync(0xffffffffu, mn0, 1));
        mn0 = fmaxf(mn0, __shfl_xor_sync(0xffffffffu, mn0, 2));
        mn1 = fmaxf(mn1, __shfl_xor_sync(0xffffffffu, mn1, 1));
        mn1 = fmaxf(mn1, __shfl_xor_sync(0xffffffffu, mn1, 2));
        float corr0 = __expf(m0 - mn0);
        float corr1 = __expf(m1 - mn1);

        uint32_t phi[16][2], plo[16][2];
        float ls0 = 0.0f, ls1 = 0.0f;
        #pragma unroll
        for (int t = 0; t < 16; t++) {
            float p0 = __expf(sc[t][0] - mn0);
            float p1 = __expf(sc[t][1] - mn0);
            float p2 = __expf(sc[t][2] - mn1);
            float p3 = __expf(sc[t][3] - mn1);
            ls0 += p0 + p1;  ls1 += p2 + p3;
            split2(p0, p1, phi[t][0], plo[t][0]);
            split2(p2, p3, phi[t][1], plo[t][1]);
        }
        ls0 += __shfl_xor_sync(0xffffffffu, ls0, 1);
        ls0 += __shfl_xor_sync(0xffffffffu, ls0, 2);
        ls1 += __shfl_xor_sync(0xffffffffu, ls1, 1);
        ls1 += __shfl_xor_sync(0xffffffffu, ls1, 2);
        l0 = l0 * corr0 + ls0;  l1 = l1 * corr1 + ls1;
        m0 = mn0;  m1 = mn1;
        #pragma unroll
        for (int g = 0; g < 8; g++) {
            acc[g][0] *= corr0; acc[g][1] *= corr0;
            acc[g][2] *= corr1; acc[g][3] *= corr1;
        }

        #pragma unroll
        for (int k = 0; k < 8; k++) {
            uint32_t ph_[4] = {phi[k * 2][0], phi[k * 2][1], phi[k * 2 + 1][0], phi[k * 2 + 1][1]};
            uint32_t pl_[4] = {plo[k * 2][0], plo[k * 2][1], plo[k * 2 + 1][0], plo[k * 2 + 1][1]};
            #pragma unroll
            for (int g = 0; g < 4; g++) {
                uint32_t off = (uint32_t)((k * 16 + (lid & 15)) * FROW_B +
                                          (g * 16 + ((lid >> 4) & 1) * 8) * 2);
                uint32_t v0, v1, v2, v3, w0, w1, w2, w3;
                ldsm_x4_t(v0, v1, v2, v3, sV + off);
                ldsm_x4_t(w0, w1, w2, w3, sVl + off);
                mma16816(acc[g * 2],     ph_, v0, v1);
                mma16816(acc[g * 2 + 1], ph_, v2, v3);
                mma16816(acc[g * 2],     ph_, w0, w1);
                mma16816(acc[g * 2 + 1], ph_, w2, w3);
                mma16816(acc[g * 2],     pl_, v0, v1);
                mma16816(acc[g * 2 + 1], pl_, v2, v3);
            }
        }

        if (kt + 1 < nkv) CP_WAIT(0);
        __syncthreads();
    }
#undef LOAD_KV

    // fused epilogue: normalize + bf16 hi/lo split (feeds dense GEMM directly)
    float inv0 = 1.0f / l0, inv1 = 1.0f / l1;
    #pragma unroll
    for (int g = 0; g < 8; g++) {
        int col = h * HD + g * 8 + (lid & 3) * 2;
        int r = q0 + wid * 16 + (lid >> 2);
        uint32_t h0, lo0, h1, lo1;
        split2(acc[g][0] * inv0, acc[g][1] * inv0, h0, lo0);
        split2(acc[g][2] * inv1, acc[g][3] * inv1, h1, lo1);
        *reinterpret_cast<uint32_t*>(&oh[(size_t)r * QDIM + col]) = h0;
        *reinterpret_cast<uint32_t*>(&ol[(size_t)r * QDIM + col]) = lo0;
        *reinterpret_cast<uint32_t*>(&oh[(size_t)(r + 8) * QDIM + col]) = h1;
        *reinterpret_cast<uint32_t*>(&ol[(size_t)(r + 8) * QDIM + col]) = lo1;
    }
}

// ---------------- launch ----------------------------------------------------
extern "C" void kernel_launch(void* const* d_in, const int* in_sizes, int n_in,
                              void* d_out, int out_size)
{
    const float* x       = (const float*)d_in[0];
    const float* qkv_w   = (const float*)d_in[1];
    const float* dense_w = (const float*)d_in[2];
    float* out = (float*)d_out;

    float* fused; cudaGetSymbolAddress((void**)&fused, g_fused);
    __nv_bfloat16 *xh, *xl, *wqh, *wql, *wdh, *wdl, *ah, *al;
    __nv_bfloat16 *qsh, *qsl, *ksh, *ksl, *vsh, *vsl;
    cudaGetSymbolAddress((void**)&xh,  g_xh);  cudaGetSymbolAddress((void**)&xl,  g_xl);
    cudaGetSymbolAddress((void**)&wqh, g_wqh); cudaGetSymbolAddress((void**)&wql, g_wql);
    cudaGetSymbolAddress((void**)&wdh, g_wdh); cudaGetSymbolAddress((void**)&wdl, g_wdl);
    cudaGetSymbolAddress((void**)&ah,  g_ah);  cudaGetSymbolAddress((void**)&al,  g_al);
    cudaGetSymbolAddress((void**)&qsh, g_qsh); cudaGetSymbolAddress((void**)&qsl, g_qsl);
    cudaGetSymbolAddress((void**)&ksh, g_ksh); cudaGetSymbolAddress((void**)&ksl, g_ksl);
    cudaGetSymbolAddress((void**)&vsh, g_vsh); cudaGetSymbolAddress((void**)&vsl, g_vsl);

    cudaFuncSetAttribute(gemm_mma,
                         cudaFuncAttributeMaxDynamicSharedMemorySize, GEMM_SMEM);
    cudaFuncSetAttribute(flash_mma,
                         cudaFuncAttributeMaxDynamicSharedMemorySize, FA_SMEM);

    // 1. RoPE table
    rope_table_kernel<<<(SEQ * 32 + 255) / 256, 256>>>();

    // 2. bf16 hi/lo splits of x, qkv weight, dense weight
    {
        int t = SEQ * HIDDEN;
        split_kernel<<<(t + 255) / 256, 256>>>(x, xh, xl, t, t);
        int tw = QKV_PAD * HIDDEN, sw = QKV_OUT * HIDDEN;
        split_kernel<<<(tw + 255) / 256, 256>>>(qkv_w, wqh, wql, tw, sw);
        int td = DEN_PAD * HIDDEN, sd = HIDDEN * HIDDEN;
        split_kernel<<<(td + 255) / 256, 256>>>(dense_w, wdh, wdl, td, sd);
    }

    // 3. QKV GEMM
    {
        dim3 grid(QKV_PAD / BNT, SEQ / BMT);
        gemm_mma<<<grid, 256, GEMM_SMEM>>>(xh, xl, wqh, wql, fused,
                                           QKV_OUT, HIDDEN);
    }

    // 4. prep: rope + scale + hi/lo split of q, k, v
    {
        int total = SEQ * (NH + 2) * 32;
        prep_kernel<<<(total + 255) / 256, 256>>>();
    }

    // 5. flash attention (tensor cores) -> bf16 hi/lo activations
    {
        dim3 grid(SEQ / 128, NH);
        flash_mma<<<grid, 256, FA_SMEM>>>(qsh, qsl, ksh, ksl, vsh, vsl, ah, al);
    }

    // 6. dense GEMM -> out
    {
        dim3 grid(DEN_PAD / BNT, SEQ / BMT);
        gemm_mma<<<grid, 256, GEMM_SMEM>>>(ah, al, wdh, wdl, out,
                                           HIDDEN, HIDDEN);
    }
}

// round 6
// speedup vs baseline: 3.3200x; 1.0398x over previous
#include <cuda_runtime.h>
#include <cuda_bf16.h>
#include <math.h>
#include <stdint.h>

#define SEQ     2048
#define HIDDEN  4544
#define NH      71
#define HD      64
#define QKV_OUT 4672
#define QKV_PAD 4736            // 37*128
#define DEN_PAD 4608            // 36*128
#define QDIM    4544

// ---------------- scratch (device globals; no allocations allowed) ----------
__device__ float g_fused[SEQ * QKV_OUT];
__device__ float g_cos  [SEQ * 32];
__device__ float g_sin  [SEQ * 32];
__device__ __nv_bfloat16 g_xh [SEQ * HIDDEN],     g_xl [SEQ * HIDDEN];
__device__ __nv_bfloat16 g_wqh[QKV_PAD * HIDDEN], g_wql[QKV_PAD * HIDDEN];
__device__ __nv_bfloat16 g_wdh[DEN_PAD * HIDDEN], g_wdl[DEN_PAD * HIDDEN];
__device__ __nv_bfloat16 g_ah [SEQ * HIDDEN],     g_al [SEQ * HIDDEN];
// flash inputs (bf16 hi/lo, roped; q pre-scaled by 1/8)
__device__ __nv_bfloat16 g_qsh[NH * SEQ * HD], g_qsl[NH * SEQ * HD];
__device__ __nv_bfloat16 g_ksh[SEQ * HD], g_ksl[SEQ * HD];
__device__ __nv_bfloat16 g_vsh[SEQ * HD], g_vsl[SEQ * HD];

// ================= portable PTX helpers (sm_80+; no tcgen05) ================
__device__ __forceinline__ uint32_t smem_to_u32(const void* p) {
    uint32_t a;
    asm("{ .reg .u64 t; cvta.to.shared.u64 t, %1; cvt.u32.u64 %0, t; }"
        : "=r"(a) : "l"(p));
    return a;
}
__device__ __forceinline__ void ldsm_x4(uint32_t& r0, uint32_t& r1,
                                        uint32_t& r2, uint32_t& r3, uint32_t addr) {
    asm volatile("ldmatrix.sync.aligned.m8n8.x4.shared.b16 {%0,%1,%2,%3}, [%4];"
                 : "=r"(r0), "=r"(r1), "=r"(r2), "=r"(r3) : "r"(addr));
}
__device__ __forceinline__ void ldsm_x4_t(uint32_t& r0, uint32_t& r1,
                                          uint32_t& r2, uint32_t& r3, uint32_t addr) {
    asm volatile("ldmatrix.sync.aligned.m8n8.x4.trans.shared.b16 {%0,%1,%2,%3}, [%4];"
                 : "=r"(r0), "=r"(r1), "=r"(r2), "=r"(r3) : "r"(addr));
}
__device__ __forceinline__ void mma16816(float* c, const uint32_t* a,
                                         uint32_t b0, uint32_t b1) {
    asm volatile("mma.sync.aligned.m16n8k16.row.col.f32.bf16.bf16.f32 "
                 "{%0,%1,%2,%3}, {%4,%5,%6,%7}, {%8,%9}, {%0,%1,%2,%3};"
                 : "+f"(c[0]), "+f"(c[1]), "+f"(c[2]), "+f"(c[3])
                 : "r"(a[0]), "r"(a[1]), "r"(a[2]), "r"(a[3]), "r"(b0), "r"(b1));
}
__device__ __forceinline__ void cp_async16(uint32_t sdst, const void* gsrc) {
    asm volatile("cp.async.cg.shared.global [%0], [%1], 16;" :: "r"(sdst), "l"(gsrc));
}
#define CP_COMMIT() asm volatile("cp.async.commit_group;" ::: "memory")
#define CP_WAIT(n)  asm volatile("cp.async.wait_group %0;" :: "n"(n) : "memory")

__device__ __forceinline__ void split2(float a, float b, uint32_t& hi, uint32_t& lo) {
    __nv_bfloat162 h2 = __floats2bfloat162_rn(a, b);
    hi = *reinterpret_cast<uint32_t*>(&h2);
    float ra = a - __bfloat162float(h2.x);
    float rb = b - __bfloat162float(h2.y);
    __nv_bfloat162 l2 = __floats2bfloat162_rn(ra, rb);
    lo = *reinterpret_cast<uint32_t*>(&l2);
}

// ---------------- RoPE table (fp64 trig for accuracy) -----------------------
__global__ void rope_table_kernel() {
    int idx = blockIdx.x * blockDim.x + threadIdx.x;
    if (idx >= SEQ * 32) return;
    int s = idx >> 5, j = idx & 31;
    double inv = exp(-(double)j / 32.0 * log(10000.0));
    double ang = (double)s * inv;
    g_cos[idx] = (float)cos(ang);
    g_sin[idx] = (float)sin(ang);
}

// ---------------- fp32 -> bf16 hi/lo split, vectorized (4 elems/thread) -----
__global__ void split4_kernel(const float4* __restrict__ src,
                              uint2* __restrict__ hi,
                              uint2* __restrict__ lo,
                              int total4, int src_total4)
{
    int i = blockIdx.x * blockDim.x + threadIdx.x;
    if (i >= total4) return;
    float4 v = (i < src_total4) ? src[i] : make_float4(0.f, 0.f, 0.f, 0.f);
    uint2 h, l;
    split2(v.x, v.y, h.x, l.x);
    split2(v.z, v.w, h.y, l.y);
    hi[i] = h;
    lo[i] = l;
}

// ---------------- prep: rope + scale + bf16 hi/lo for q,k,v -----------------
__global__ void prep_kernel() {
    int idx = blockIdx.x * blockDim.x + threadIdx.x;
    const int total = SEQ * (NH + 2) * 32;
    if (idx >= total) return;
    int j  = idx & 31;
    int t  = idx >> 5;
    int hh = t % (NH + 2);
    int s  = t / (NH + 2);
    size_t base = (size_t)s * QKV_OUT + hh * HD;
    float a = g_fused[base + j];
    float b = g_fused[base + j + 32];
    float o1, o2;
    if (hh <= NH) {
        float c  = g_cos[s * 32 + j];
        float sn = g_sin[s * 32 + j];
        o1 = a * c - b * sn;
        o2 = b * c + a * sn;
    } else {
        o1 = a; o2 = b;
    }
    __nv_bfloat16 *dh, *dl;
    size_t doff;
    if (hh < NH) {
        o1 *= 0.125f; o2 *= 0.125f;
        dh = g_qsh; dl = g_qsl;
        doff = ((size_t)hh * SEQ + s) * HD;
    } else if (hh == NH) {
        dh = g_ksh; dl = g_ksl;
        doff = (size_t)s * HD;
    } else {
        dh = g_vsh; dl = g_vsl;
        doff = (size_t)s * HD;
    }
    __nv_bfloat16 h1 = __float2bfloat16(o1);
    __nv_bfloat16 h2 = __float2bfloat16(o2);
    dh[doff + j]      = h1;
    dh[doff + j + 32] = h2;
    dl[doff + j]      = __float2bfloat16(o1 - __bfloat162float(h1));
    dl[doff + j + 32] = __float2bfloat16(o2 - __bfloat162float(h2));
}

// ---------------- mma.sync bf16-split GEMM ----------------------------------
// C[m,n] = sum_k A[m,k]*B[n,k]  via  Ah*Bh + Ah*Bl + Al*Bh (drop Al*Bl).
// Tile 128x128, K-chunk 32, cp.async double buffer, 8 warps (64x32 warptiles).
// 2 CTAs/SM; A-fragment register array reused Ah->Al so peak regs < 128.
#define BMT 128
#define BNT 128
#define BKC 32
#define ARR_B (BMT * 40 * 2)
#define STG_B (4 * ARR_B)
#define GEMM_SMEM (2 * STG_B)

__global__ __launch_bounds__(256, 2) void gemm_mma(
    const __nv_bfloat16* __restrict__ Ah, const __nv_bfloat16* __restrict__ Al,
    const __nv_bfloat16* __restrict__ Bh, const __nv_bfloat16* __restrict__ Bl,
    float* __restrict__ C, int N_real, int K)
{
    extern __shared__ __align__(128) char smem[];
    const int tid = threadIdx.x;
    const int wid = tid >> 5;
    const int lid = tid & 31;
    const int m0 = blockIdx.y * BMT;
    const int n0 = blockIdx.x * BNT;
    const int wm = (wid & 1) * 64;
    const int wn = (wid >> 1) * 32;
    const uint32_t sbase = smem_to_u32(smem);

    const int arr = tid >> 6;
    const int t64 = tid & 63;
    const __nv_bfloat16* gp = (arr == 0) ? Ah : (arr == 1) ? Al : (arr == 2) ? Bh : Bl;
    const int rbase = (arr < 2) ? m0 : n0;

#define LOAD_STAGE(s, k0) do {                                                 \
        uint32_t sb_ = sbase + (s) * STG_B + arr * ARR_B;                      \
        _Pragma("unroll")                                                      \
        for (int i_ = 0; i_ < 8; i_++) {                                       \
            int id_ = i_ * 64 + t64;                                           \
            int r_ = id_ >> 2, ch_ = id_ & 3;                                  \
            cp_async16(sb_ + r_ * 80 + ch_ * 16,                               \
                       gp + (size_t)(rbase + r_) * K + (k0) + ch_ * 8);        \
        }                                                                      \
    } while (0)

    float acc[4][4][4];
    #pragma unroll
    for (int i = 0; i < 4; i++)
        #pragma unroll
        for (int j = 0; j < 4; j++)
            #pragma unroll
            for (int e = 0; e < 4; e++) acc[i][j][e] = 0.0f;

    LOAD_STAGE(0, 0);
    CP_COMMIT();

    const int arow = (lid & 7) | (((lid >> 3) & 1) << 3);
    const int acolh = (lid >> 4) * 8;
    const int brow = (lid & 7) + ((lid >> 4) & 1) * 8;
    const int bcolh = ((lid >> 3) & 1) * 8;

    const int nchunk = K / BKC;
    for (int c = 0; c < nchunk; c++) {
        const int cur = c & 1;
        if (c + 1 < nchunk) {
            LOAD_STAGE(cur ^ 1, (c + 1) * BKC);
            CP_COMMIT();
            CP_WAIT(1);
        } else {
            CP_WAIT(0);
        }
        __syncthreads();

        const uint32_t sAh = sbase + cur * STG_B;
        const uint32_t sAl = sAh + ARR_B;
        const uint32_t sBh = sAh + 2 * ARR_B;
        const uint32_t sBl = sAh + 3 * ARR_B;

        #pragma unroll
        for (int kk = 0; kk < 2; kk++) {
            const int kc = kk * 16;
            uint32_t bh[2][4], bl[2][4], af[4][4];
            #pragma unroll
            for (int j = 0; j < 2; j++) {
                uint32_t off = (uint32_t)((wn + j * 16 + brow) * 80 + (kc + bcolh) * 2);
                ldsm_x4(bh[j][0], bh[j][1], bh[j][2], bh[j][3], sBh + off);
                ldsm_x4(bl[j][0], bl[j][1], bl[j][2], bl[j][3], sBl + off);
            }
            // phase A: af = Ah frags; acc += Ah*Bh + Ah*Bl
            #pragma unroll
            for (int i = 0; i < 4; i++) {
                uint32_t off = (uint32_t)((wm + i * 16 + arow) * 80 + (kc + acolh) * 2);
                ldsm_x4(af[i][0], af[i][1], af[i][2], af[i][3], sAh + off);
            }
            #pragma unroll
            for (int i = 0; i < 4; i++) {
                #pragma unroll
                for (int j = 0; j < 2; j++) {
                    mma16816(acc[i][j * 2 + 0], af[i], bh[j][0], bh[j][1]);
                    mma16816(acc[i][j * 2 + 1], af[i], bh[j][2], bh[j][3]);
                    mma16816(acc[i][j * 2 + 0], af[i], bl[j][0], bl[j][1]);
                    mma16816(acc[i][j * 2 + 1], af[i], bl[j][2], bl[j][3]);
                }
            }
            // phase B: af = Al frags (reuse registers); acc += Al*Bh
            #pragma unroll
            for (int i = 0; i < 4; i++) {
                uint32_t off = (uint32_t)((wm + i * 16 + arow) * 80 + (kc + acolh) * 2);
                ldsm_x4(af[i][0], af[i][1], af[i][2], af[i][3], sAl + off);
            }
            #pragma unroll
            for (int i = 0; i < 4; i++) {
                #pragma unroll
                for (int j = 0; j < 2; j++) {
                    mma16816(acc[i][j * 2 + 0], af[i], bh[j][0], bh[j][1]);
                    mma16816(acc[i][j * 2 + 1], af[i], bh[j][2], bh[j][3]);
                }
            }
        }
        __syncthreads();
    }

    const int gr = lid >> 2, tg = lid & 3;
    #pragma unroll
    for (int i = 0; i < 4; i++) {
        #pragma unroll
        for (int j = 0; j < 4; j++) {
            int col = n0 + wn + j * 8 + tg * 2;
            if (col < N_real) {
                int row = m0 + wm + i * 16 + gr;
                float2 v0 = make_float2(acc[i][j][0], acc[i][j][1]);
                float2 v1 = make_float2(acc[i][j][2], acc[i][j][3]);
                *reinterpret_cast<float2*>(&C[(size_t)row * N_real + col]) = v0;
                *reinterpret_cast<float2*>(&C[(size_t)(row + 8) * N_real + col]) = v1;
            }
        }
    }
#undef LOAD_STAGE
}

// ---------------- flash attention via mma.sync (MQA, causal) -----------------
#define FROW_B 144
#define QARR_B (128 * FROW_B)
#define KV_STG (4 * QARR_B)
#define FA_SMEM (2 * QARR_B + 2 * KV_STG)

__global__ __launch_bounds__(256, 1) void flash_mma(
    const __nv_bfloat16* __restrict__ qh, const __nv_bfloat16* __restrict__ ql,
    const __nv_bfloat16* __restrict__ kh, const __nv_bfloat16* __restrict__ kl,
    const __nv_bfloat16* __restrict__ vh, const __nv_bfloat16* __restrict__ vl,
    __nv_bfloat16* __restrict__ oh, __nv_bfloat16* __restrict__ ol)
{
    extern __shared__ __align__(128) char smem[];
    const int tid = threadIdx.x, wid = tid >> 5, lid = tid & 31;
    const int qt = blockIdx.x, h = blockIdx.y;
    const int q0 = qt * 128;
    const uint32_t sb = smem_to_u32(smem);
    const uint32_t sQh = sb, sQl = sb + QARR_B;
    const uint32_t sKV = sb + 2 * QARR_B;

    {
        const __nv_bfloat16* srcs[2] = {qh, ql};
        #pragma unroll
        for (int i = 0; i < 8; i++) {
            int id = i * 256 + tid;
            int a = id >> 10, w = id & 1023, r = w >> 3, c = w & 7;
            cp_async16(sb + a * QARR_B + r * FROW_B + c * 16,
                       srcs[a] + ((size_t)h * SEQ + q0 + r) * HD + c * 8);
        }
    }
    const __nv_bfloat16* kvsrc[4] = {kh, kl, vh, vl};
#define LOAD_KV(s, kt_) do {                                                   \
        _Pragma("unroll")                                                      \
        for (int i_ = 0; i_ < 16; i_++) {                                      \
            int id_ = i_ * 256 + tid;                                          \
            int a_ = id_ >> 10, w_ = id_ & 1023, r_ = w_ >> 3, c_ = w_ & 7;    \
            cp_async16(sKV + (s) * KV_STG + a_ * QARR_B + r_ * FROW_B + c_ * 16, \
                       kvsrc[a_] + ((size_t)((kt_) * 128 + r_)) * HD + c_ * 8); \
        }                                                                      \
    } while (0)
    LOAD_KV(0, 0);
    CP_COMMIT();
    CP_WAIT(0);
    __syncthreads();

    const int arow  = (lid & 7) | (((lid >> 3) & 1) << 3);
    const int acolh = (lid >> 4) * 8;
    const int brow  = (lid & 7) + ((lid >> 4) & 1) * 8;
    const int bcolh = ((lid >> 3) & 1) * 8;

    uint32_t aqh[4][4], aql[4][4];
    #pragma unroll
    for (int k = 0; k < 4; k++) {
        uint32_t off = (uint32_t)((wid * 16 + arow) * FROW_B + (k * 16 + acolh) * 2);
        ldsm_x4(aqh[k][0], aqh[k][1], aqh[k][2], aqh[k][3], sQh + off);
        ldsm_x4(aql[k][0], aql[k][1], aql[k][2], aql[k][3], sQl + off);
    }

    float acc[8][4];
    #pragma unroll
    for (int g = 0; g < 8; g++)
        #pragma unroll
        for (int e = 0; e < 4; e++) acc[g][e] = 0.0f;
    float m0 = -1e30f, m1 = -1e30f, l0 = 0.0f, l1 = 0.0f;
    const int row0 = q0 + wid * 16 + (lid >> 2);

    const int nkv = qt + 1;
    for (int kt = 0; kt < nkv; kt++) {
        const int cur = kt & 1;
        if (kt + 1 < nkv) { LOAD_KV(cur ^ 1, kt + 1); CP_COMMIT(); }
        const uint32_t sK  = sKV + cur * KV_STG;
        const uint32_t sKl = sK + QARR_B;
        const uint32_t sV  = sK + 2 * QARR_B;
        const uint32_t sVl = sK + 3 * QARR_B;

        float sc[16][4];
        #pragma unroll
        for (int t = 0; t < 16; t++)
            #pragma unroll
            for (int e = 0; e < 4; e++) sc[t][e] = 0.0f;

        #pragma unroll
        for (int j2 = 0; j2 < 8; j2++) {
            #pragma unroll
            for (int k = 0; k < 4; k++) {
                uint32_t off = (uint32_t)((j2 * 16 + brow) * FROW_B + (k * 16 + bcolh) * 2);
                uint32_t b0, b1, b2, b3, c0, c1, c2, c3;
                ldsm_x4(b0, b1, b2, b3, sK + off);
                ldsm_x4(c0, c1, c2, c3, sKl + off);
                mma16816(sc[j2 * 2],     aqh[k], b0, b1);
                mma16816(sc[j2 * 2 + 1], aqh[k], b2, b3);
                mma16816(sc[j2 * 2],     aqh[k], c0, c1);
                mma16816(sc[j2 * 2 + 1], aqh[k], c2, c3);
                mma16816(sc[j2 * 2],     aql[k], b0, b1);
                mma16816(sc[j2 * 2 + 1], aql[k], b2, b3);
            }
        }

        if (kt == qt) {
            #pragma unroll
            for (int t = 0; t < 16; t++) {
                int colb = kt * 128 + t * 8 + (lid & 3) * 2;
                if (colb     > row0)     sc[t][0] = -1e30f;
                if (colb + 1 > row0)     sc[t][1] = -1e30f;
                if (colb     > row0 + 8) sc[t][2] = -1e30f;
                if (colb + 1 > row0 + 8) sc[t][3] = -1e30f;
            }
        }

        float mn0 = m0, mn1 = m1;
        #pragma unroll
        for (int t = 0; t < 16; t++) {
            mn0 = fmaxf(mn0, fmaxf(sc[t][0], sc[t][1]));
            mn1 = fmaxf(mn1, fmaxf(sc[t][2], sc[t][3]));
        }
        mn0 = fmaxf(mn0, __shfl_xor_sync(0xffffffffu, mn0, 1));
        mn0 = fmaxf(mn0, __shfl_xor_sync(0xffffffffu, mn0, 2));
        mn1 = fmaxf(mn1, __shfl_xor_sync(0xffffffffu, mn1, 1));
        mn1 = fmaxf(mn1, __shfl_xor_sync(0xffffffffu, mn1, 2));
        float corr0 = __expf(m0 - mn0);
        float corr1 = __expf(m1 - mn1);

        uint32_t phi[16][2], plo[16][2];
        float ls0 = 0.0f, ls1 = 0.0f;
        #pragma unroll
        for (int t = 0; t < 16; t++) {
            float p0 = __expf(sc[t][0] - mn0);
            float p1 = __expf(sc[t][1] - mn0);
            float p2 = __expf(sc[t][2] - mn1);
            float p3 = __expf(sc[t][3] - mn1);
            ls0 += p0 + p1;  ls1 += p2 + p3;
            split2(p0, p1, phi[t][0], plo[t][0]);
            split2(p2, p3, phi[t][1], plo[t][1]);
        }
        ls0 += __shfl_xor_sync(0xffffffffu, ls0, 1);
        ls0 += __shfl_xor_sync(0xffffffffu, ls0, 2);
        ls1 += __shfl_xor_sync(0xffffffffu, ls1, 1);
        ls1 += __shfl_xor_sync(0xffffffffu, ls1, 2);
        l0 = l0 * corr0 + ls0;  l1 = l1 * corr1 + ls1;
        m0 = mn0;  m1 = mn1;
        #pragma unroll
        for (int g = 0; g < 8; g++) {
            acc[g][0] *= corr0; acc[g][1] *= corr0;
            acc[g][2] *= corr1; acc[g][3] *= corr1;
        }

        #pragma unroll
        for (int k = 0; k < 8; k++) {
            uint32_t ph_[4] = {phi[k * 2][0], phi[k * 2][1], phi[k * 2 + 1][0], phi[k * 2 + 1][1]};
            uint32_t pl_[4] = {plo[k * 2][0], plo[k * 2][1], plo[k * 2 + 1][0], plo[k * 2 + 1][1]};
            #pragma unroll
            for (int g = 0; g < 4; g++) {
                uint32_t off = (uint32_t)((k * 16 + (lid & 15)) * FROW_B +
                                          (g * 16 + ((lid >> 4) & 1) * 8) * 2);
                uint32_t v0, v1, v2, v3, w0, w1, w2, w3;
                ldsm_x4_t(v0, v1, v2, v3, sV + off);
                ldsm_x4_t(w0, w1, w2, w3, sVl + off);
                mma16816(acc[g * 2],     ph_, v0, v1);
                mma16816(acc[g * 2 + 1], ph_, v2, v3);
                mma16816(acc[g * 2],     ph_, w0, w1);
                mma16816(acc[g * 2 + 1], ph_, w2, w3);
                mma16816(acc[g * 2],     pl_, v0, v1);
                mma16816(acc[g * 2 + 1], pl_, v2, v3);
            }
        }

        if (kt + 1 < nkv) CP_WAIT(0);
        __syncthreads();
    }
#undef LOAD_KV

    float inv0 = 1.0f / l0, inv1 = 1.0f / l1;
    #pragma unroll
    for (int g = 0; g < 8; g++) {
        int col = h * HD + g * 8 + (lid & 3) * 2;
        int r = q0 + wid * 16 + (lid >> 2);
        uint32_t h0, lo0, h1, lo1;
        split2(acc[g][0] * inv0, acc[g][1] * inv0, h0, lo0);
        split2(acc[g][2] * inv1, acc[g][3] * inv1, h1, lo1);
        *reinterpret_cast<uint32_t*>(&oh[(size_t)r * QDIM + col]) = h0;
        *reinterpret_cast<uint32_t*>(&ol[(size_t)r * QDIM + col]) = lo0;
        *reinterpret_cast<uint32_t*>(&oh[(size_t)(r + 8) * QDIM + col]) = h1;
        *reinterpret_cast<uint32_t*>(&ol[(size_t)(r + 8) * QDIM + col]) = lo1;
    }
}

// ---------------- launch ----------------------------------------------------
extern "C" void kernel_launch(void* const* d_in, const int* in_sizes, int n_in,
                              void* d_out, int out_size)
{
    const float* x       = (const float*)d_in[0];
    const float* qkv_w   = (const float*)d_in[1];
    const float* dense_w = (const float*)d_in[2];
    float* out = (float*)d_out;

    float* fused; cudaGetSymbolAddress((void**)&fused, g_fused);
    __nv_bfloat16 *xh, *xl, *wqh, *wql, *wdh, *wdl, *ah, *al;
    __nv_bfloat16 *qsh, *qsl, *ksh, *ksl, *vsh, *vsl;
    cudaGetSymbolAddress((void**)&xh,  g_xh);  cudaGetSymbolAddress((void**)&xl,  g_xl);
    cudaGetSymbolAddress((void**)&wqh, g_wqh); cudaGetSymbolAddress((void**)&wql, g_wql);
    cudaGetSymbolAddress((void**)&wdh, g_wdh); cudaGetSymbolAddress((void**)&wdl, g_wdl);
    cudaGetSymbolAddress((void**)&ah,  g_ah);  cudaGetSymbolAddress((void**)&al,  g_al);
    cudaGetSymbolAddress((void**)&qsh, g_qsh); cudaGetSymbolAddress((void**)&qsl, g_qsl);
    cudaGetSymbolAddress((void**)&ksh, g_ksh); cudaGetSymbolAddress((void**)&ksl, g_ksl);
    cudaGetSymbolAddress((void**)&vsh, g_vsh); cudaGetSymbolAddress((void**)&vsl, g_vsl);

    cudaFuncSetAttribute(gemm_mma,
                         cudaFuncAttributeMaxDynamicSharedMemorySize, GEMM_SMEM);
    cudaFuncSetAttribute(flash_mma,
                         cudaFuncAttributeMaxDynamicSharedMemorySize, FA_SMEM);

    // 1. RoPE table
    rope_table_kernel<<<(SEQ * 32 + 255) / 256, 256>>>();

    // 2. bf16 hi/lo splits (vectorized) of x, qkv weight, dense weight
    {
        int t4 = SEQ * HIDDEN / 4;
        split4_kernel<<<(t4 + 255) / 256, 256>>>(
            (const float4*)x, (uint2*)xh, (uint2*)xl, t4, t4);
        int tw4 = QKV_PAD * HIDDEN / 4, sw4 = QKV_OUT * HIDDEN / 4;
        split4_kernel<<<(tw4 + 255) / 256, 256>>>(
            (const float4*)qkv_w, (uint2*)wqh, (uint2*)wql, tw4, sw4);
        int td4 = DEN_PAD * HIDDEN / 4, sd4 = HIDDEN * HIDDEN / 4;
        split4_kernel<<<(td4 + 255) / 256, 256>>>(
            (const float4*)dense_w, (uint2*)wdh, (uint2*)wdl, td4, sd4);
    }

    // 3. QKV GEMM
    {
        dim3 grid(QKV_PAD / BNT, SEQ / BMT);
        gemm_mma<<<grid, 256, GEMM_SMEM>>>(xh, xl, wqh, wql, fused,
                                           QKV_OUT, HIDDEN);
    }

    // 4. prep: rope + scale + hi/lo split of q, k, v
    {
        int total = SEQ * (NH + 2) * 32;
        prep_kernel<<<(total + 255) / 256, 256>>>();
    }

    // 5. flash attention (tensor cores) -> bf16 hi/lo activations
    {
        dim3 grid(SEQ / 128, NH);
        flash_mma<<<grid, 256, FA_SMEM>>>(qsh, qsl, ksh, ksl, vsh, vsl, ah, al);
    }

    // 6. dense GEMM -> out
    {
        dim3 grid(DEN_PAD / BNT, SEQ / BMT);
        gemm_mma<<<grid, 256, GEMM_SMEM>>>(ah, al, wdh, wdl, out,
                                           HIDDEN, HIDDEN);
    }
}

// round 7
// speedup vs baseline: 3.3274x; 1.0022x over previous
#include <cuda_runtime.h>
#include <cuda_bf16.h>
#include <math.h>
#include <stdint.h>

#define SEQ     2048
#define HIDDEN  4544
#define NH      71
#define HD      64
#define QKV_OUT 4672
#define QKV_PAD 4736            // 37*128
#define DEN_PAD 4608            // 36*128
#define QDIM    4544

// ---------------- scratch (device globals; no allocations allowed) ----------
__device__ float g_fused[SEQ * QKV_OUT];
__device__ float g_cos  [SEQ * 32];
__device__ float g_sin  [SEQ * 32];
__device__ __nv_bfloat16 g_xh [SEQ * HIDDEN],     g_xl [SEQ * HIDDEN];
__device__ __nv_bfloat16 g_wqh[QKV_PAD * HIDDEN], g_wql[QKV_PAD * HIDDEN];
__device__ __nv_bfloat16 g_wdh[DEN_PAD * HIDDEN], g_wdl[DEN_PAD * HIDDEN];
__device__ __nv_bfloat16 g_ah [SEQ * HIDDEN],     g_al [SEQ * HIDDEN];
// flash inputs (bf16 hi/lo, roped; q pre-scaled by 1/8)
__device__ __nv_bfloat16 g_qsh[NH * SEQ * HD], g_qsl[NH * SEQ * HD];
__device__ __nv_bfloat16 g_ksh[SEQ * HD], g_ksl[SEQ * HD];
__device__ __nv_bfloat16 g_vsh[SEQ * HD], g_vsl[SEQ * HD];

// ================= portable PTX helpers (sm_80+; no tcgen05) ================
__device__ __forceinline__ uint32_t smem_to_u32(const void* p) {
    uint32_t a;
    asm("{ .reg .u64 t; cvta.to.shared.u64 t, %1; cvt.u32.u64 %0, t; }"
        : "=r"(a) : "l"(p));
    return a;
}
__device__ __forceinline__ void ldsm_x4(uint32_t& r0, uint32_t& r1,
                                        uint32_t& r2, uint32_t& r3, uint32_t addr) {
    asm volatile("ldmatrix.sync.aligned.m8n8.x4.shared.b16 {%0,%1,%2,%3}, [%4];"
                 : "=r"(r0), "=r"(r1), "=r"(r2), "=r"(r3) : "r"(addr));
}
__device__ __forceinline__ void ldsm_x4_t(uint32_t& r0, uint32_t& r1,
                                          uint32_t& r2, uint32_t& r3, uint32_t addr) {
    asm volatile("ldmatrix.sync.aligned.m8n8.x4.trans.shared.b16 {%0,%1,%2,%3}, [%4];"
                 : "=r"(r0), "=r"(r1), "=r"(r2), "=r"(r3) : "r"(addr));
}
__device__ __forceinline__ void mma16816(float* c, const uint32_t* a,
                                         uint32_t b0, uint32_t b1) {
    asm volatile("mma.sync.aligned.m16n8k16.row.col.f32.bf16.bf16.f32 "
                 "{%0,%1,%2,%3}, {%4,%5,%6,%7}, {%8,%9}, {%0,%1,%2,%3};"
                 : "+f"(c[0]), "+f"(c[1]), "+f"(c[2]), "+f"(c[3])
                 : "r"(a[0]), "r"(a[1]), "r"(a[2]), "r"(a[3]), "r"(b0), "r"(b1));
}
__device__ __forceinline__ void cp_async16(uint32_t sdst, const void* gsrc) {
    asm volatile("cp.async.cg.shared.global [%0], [%1], 16;" :: "r"(sdst), "l"(gsrc));
}
#define CP_COMMIT() asm volatile("cp.async.commit_group;" ::: "memory")
#define CP_WAIT(n)  asm volatile("cp.async.wait_group %0;" :: "n"(n) : "memory")

__device__ __forceinline__ void split2(float a, float b, uint32_t& hi, uint32_t& lo) {
    __nv_bfloat162 h2 = __floats2bfloat162_rn(a, b);
    hi = *reinterpret_cast<uint32_t*>(&h2);
    float ra = a - __bfloat162float(h2.x);
    float rb = b - __bfloat162float(h2.y);
    __nv_bfloat162 l2 = __floats2bfloat162_rn(ra, rb);
    lo = *reinterpret_cast<uint32_t*>(&l2);
}

// ---------------- RoPE table (fp64 trig for accuracy) -----------------------
__global__ void rope_table_kernel() {
    int idx = blockIdx.x * blockDim.x + threadIdx.x;
    if (idx >= SEQ * 32) return;
    int s = idx >> 5, j = idx & 31;
    double inv = exp(-(double)j / 32.0 * log(10000.0));
    double ang = (double)s * inv;
    g_cos[idx] = (float)cos(ang);
    g_sin[idx] = (float)sin(ang);
}

// ---------------- fp32 -> bf16 hi/lo split, vectorized ----------------------
__global__ void split4_kernel(const float4* __restrict__ src,
                              uint2* __restrict__ hi,
                              uint2* __restrict__ lo,
                              int total4, int src_total4)
{
    int i = blockIdx.x * blockDim.x + threadIdx.x;
    if (i >= total4) return;
    float4 v = (i < src_total4) ? src[i] : make_float4(0.f, 0.f, 0.f, 0.f);
    uint2 h, l;
    split2(v.x, v.y, h.x, l.x);
    split2(v.z, v.w, h.y, l.y);
    hi[i] = h;
    lo[i] = l;
}

// ---------------- prep: rope + scale + bf16 hi/lo for q,k,v -----------------
__global__ void prep_kernel() {
    int idx = blockIdx.x * blockDim.x + threadIdx.x;
    const int total = SEQ * (NH + 2) * 32;
    if (idx >= total) return;
    int j  = idx & 31;
    int t  = idx >> 5;
    int hh = t % (NH + 2);
    int s  = t / (NH + 2);
    size_t base = (size_t)s * QKV_OUT + hh * HD;
    float a = g_fused[base + j];
    float b = g_fused[base + j + 32];
    float o1, o2;
    if (hh <= NH) {
        float c  = g_cos[s * 32 + j];
        float sn = g_sin[s * 32 + j];
        o1 = a * c - b * sn;
        o2 = b * c + a * sn;
    } else {
        o1 = a; o2 = b;
    }
    __nv_bfloat16 *dh, *dl;
    size_t doff;
    if (hh < NH) {
        o1 *= 0.125f; o2 *= 0.125f;
        dh = g_qsh; dl = g_qsl;
        doff = ((size_t)hh * SEQ + s) * HD;
    } else if (hh == NH) {
        dh = g_ksh; dl = g_ksl;
        doff = (size_t)s * HD;
    } else {
        dh = g_vsh; dl = g_vsl;
        doff = (size_t)s * HD;
    }
    __nv_bfloat16 h1 = __float2bfloat16(o1);
    __nv_bfloat16 h2 = __float2bfloat16(o2);
    dh[doff + j]      = h1;
    dh[doff + j + 32] = h2;
    dl[doff + j]      = __float2bfloat16(o1 - __bfloat162float(h1));
    dl[doff + j + 32] = __float2bfloat16(o2 - __bfloat162float(h2));
}

// ---------------- mma.sync bf16-split GEMM, 256x128 CTA / 64x64 warptile ----
// C[m,n] = sum_k A[m,k]*B[n,k]  via  Ah*Bh + Ah*Bl + Al*Bh (drop Al*Bl).
// 8 warps in 4(M)x2(N); B hi/lo frags resident, A phased through one buffer.
// MMA-bound by design: per chunk smem ~1400cy < MMA 3072cy.
#define BM2 256
#define BN2 128
#define BKC 32
#define PIT 80                        // smem row pitch bytes
#define A_ARR (BM2 * PIT)             // 20480
#define B_ARR (BN2 * PIT)             // 10240
#define STG2 (2 * A_ARR + 2 * B_ARR)  // 61440
#define GEMM_SMEM (2 * STG2)          // 122880

__global__ __launch_bounds__(256, 1) void gemm_mma(
    const __nv_bfloat16* __restrict__ Ah, const __nv_bfloat16* __restrict__ Al,
    const __nv_bfloat16* __restrict__ Bh, const __nv_bfloat16* __restrict__ Bl,
    float* __restrict__ C, int N_real, int K)
{
    extern __shared__ __align__(128) char smem[];
    const int tid = threadIdx.x;
    const int wid = tid >> 5;
    const int lid = tid & 31;
    const int m0 = blockIdx.y * BM2;
    const int n0 = blockIdx.x * BN2;
    const int wm = (wid >> 1) * 64;       // 0,64,128,192
    const int wn = (wid & 1) * 64;        // 0,64
    const uint32_t sbase = smem_to_u32(smem);

#define LOAD_STAGE(s, k0) do {                                                  \
        uint32_t st_ = sbase + (s) * STG2;                                      \
        _Pragma("unroll")                                                       \
        for (int it_ = 0; it_ < 8; it_++) {          /* A: Ah then Al */        \
            int id_ = it_ * 256 + tid;                                          \
            int sel_ = id_ >> 10, w_ = id_ & 1023;                              \
            int r_ = w_ >> 2, ch_ = w_ & 3;                                     \
            const __nv_bfloat16* g_ = sel_ ? Al : Ah;                           \
            cp_async16(st_ + sel_ * A_ARR + r_ * PIT + ch_ * 16,                \
                       g_ + (size_t)(m0 + r_) * K + (k0) + ch_ * 8);            \
        }                                                                       \
        _Pragma("unroll")                                                       \
        for (int jt_ = 0; jt_ < 4; jt_++) {          /* B: Bh then Bl */        \
            int id_ = jt_ * 256 + tid;                                          \
            int sel_ = id_ >> 9, w_ = id_ & 511;                                \
            int r_ = w_ >> 2, ch_ = w_ & 3;                                     \
            const __nv_bfloat16* g_ = sel_ ? Bl : Bh;                           \
            cp_async16(st_ + 2 * A_ARR + sel_ * B_ARR + r_ * PIT + ch_ * 16,    \
                       g_ + (size_t)(n0 + r_) * K + (k0) + ch_ * 8);            \
        }                                                                       \
    } while (0)

    float acc[4][8][4];
    #pragma unroll
    for (int i = 0; i < 4; i++)
        #pragma unroll
        for (int j = 0; j < 8; j++)
            #pragma unroll
            for (int e = 0; e < 4; e++) acc[i][j][e] = 0.0f;

    LOAD_STAGE(0, 0);
    CP_COMMIT();

    const int arow  = (lid & 7) | (((lid >> 3) & 1) << 3);
    const int acolh = (lid >> 4) * 8;
    const int brow  = (lid & 7) + ((lid >> 4) & 1) * 8;
    const int bcolh = ((lid >> 3) & 1) * 8;

    const int nchunk = K / BKC;
    for (int c = 0; c < nchunk; c++) {
        const int cur = c & 1;
        if (c + 1 < nchunk) {
            LOAD_STAGE(cur ^ 1, (c + 1) * BKC);
            CP_COMMIT();
            CP_WAIT(1);
        } else {
            CP_WAIT(0);
        }
        __syncthreads();

        const uint32_t sAh = sbase + cur * STG2;
        const uint32_t sAl = sAh + A_ARR;
        const uint32_t sBh = sAh + 2 * A_ARR;
        const uint32_t sBl = sBh + B_ARR;

        #pragma unroll
        for (int kk = 0; kk < 2; kk++) {
            const int kc = kk * 16;
            uint32_t bh[4][4], bl[4][4], af[4][4];
            #pragma unroll
            for (int j = 0; j < 4; j++) {
                uint32_t off = (uint32_t)((wn + j * 16 + brow) * PIT + (kc + bcolh) * 2);
                ldsm_x4(bh[j][0], bh[j][1], bh[j][2], bh[j][3], sBh + off);
                ldsm_x4(bl[j][0], bl[j][1], bl[j][2], bl[j][3], sBl + off);
            }
            // phase A: af = Ah; acc += Ah*Bh + Ah*Bl
            #pragma unroll
            for (int i = 0; i < 4; i++) {
                uint32_t off = (uint32_t)((wm + i * 16 + arow) * PIT + (kc + acolh) * 2);
                ldsm_x4(af[i][0], af[i][1], af[i][2], af[i][3], sAh + off);
            }
            #pragma unroll
            for (int i = 0; i < 4; i++) {
                #pragma unroll
                for (int j = 0; j < 4; j++) {
                    mma16816(acc[i][j * 2 + 0], af[i], bh[j][0], bh[j][1]);
                    mma16816(acc[i][j * 2 + 1], af[i], bh[j][2], bh[j][3]);
                    mma16816(acc[i][j * 2 + 0], af[i], bl[j][0], bl[j][1]);
                    mma16816(acc[i][j * 2 + 1], af[i], bl[j][2], bl[j][3]);
                }
            }
            // phase B: af = Al; acc += Al*Bh
            #pragma unroll
            for (int i = 0; i < 4; i++) {
                uint32_t off = (uint32_t)((wm + i * 16 + arow) * PIT + (kc + acolh) * 2);
                ldsm_x4(af[i][0], af[i][1], af[i][2], af[i][3], sAl + off);
            }
            #pragma unroll
            for (int i = 0; i < 4; i++) {
                #pragma unroll
                for (int j = 0; j < 4; j++) {
                    mma16816(acc[i][j * 2 + 0], af[i], bh[j][0], bh[j][1]);
                    mma16816(acc[i][j * 2 + 1], af[i], bh[j][2], bh[j][3]);
                }
            }
        }
        __syncthreads();
    }

    const int gr = lid >> 2, tg = lid & 3;
    #pragma unroll
    for (int i = 0; i < 4; i++) {
        #pragma unroll
        for (int j = 0; j < 8; j++) {
            int col = n0 + wn + j * 8 + tg * 2;
            if (col < N_real) {
                int row = m0 + wm + i * 16 + gr;
                float2 v0 = make_float2(acc[i][j][0], acc[i][j][1]);
                float2 v1 = make_float2(acc[i][j][2], acc[i][j][3]);
                *reinterpret_cast<float2*>(&C[(size_t)row * N_real + col]) = v0;
                *reinterpret_cast<float2*>(&C[(size_t)(row + 8) * N_real + col]) = v1;
            }
        }
    }
#undef LOAD_STAGE
}

// ---------------- flash attention via mma.sync (MQA, causal) -----------------
#define FROW_B 144
#define QARR_B (128 * FROW_B)
#define KV_STG (4 * QARR_B)
#define FA_SMEM (2 * QARR_B + 2 * KV_STG)

__global__ __launch_bounds__(256, 1) void flash_mma(
    const __nv_bfloat16* __restrict__ qh, const __nv_bfloat16* __restrict__ ql,
    const __nv_bfloat16* __restrict__ kh, const __nv_bfloat16* __restrict__ kl,
    const __nv_bfloat16* __restrict__ vh, const __nv_bfloat16* __restrict__ vl,
    __nv_bfloat16* __restrict__ oh, __nv_bfloat16* __restrict__ ol)
{
    extern __shared__ __align__(128) char smem[];
    const int tid = threadIdx.x, wid = tid >> 5, lid = tid & 31;
    const int qt = blockIdx.x, h = blockIdx.y;
    const int q0 = qt * 128;
    const uint32_t sb = smem_to_u32(smem);
    const uint32_t sQh = sb, sQl = sb + QARR_B;
    const uint32_t sKV = sb + 2 * QARR_B;

    {
        const __nv_bfloat16* srcs[2] = {qh, ql};
        #pragma unroll
        for (int i = 0; i < 8; i++) {
            int id = i * 256 + tid;
            int a = id >> 10, w = id & 1023, r = w >> 3, c = w & 7;
            cp_async16(sb + a * QARR_B + r * FROW_B + c * 16,
                       srcs[a] + ((size_t)h * SEQ + q0 + r) * HD + c * 8);
        }
    }
    const __nv_bfloat16* kvsrc[4] = {kh, kl, vh, vl};
#define LOAD_KV(s, kt_) do {                                                   \
        _Pragma("unroll")                                                      \
        for (int i_ = 0; i_ < 16; i_++) {                                      \
            int id_ = i_ * 256 + tid;                                          \
            int a_ = id_ >> 10, w_ = id_ & 1023, r_ = w_ >> 3, c_ = w_ & 7;    \
            cp_async16(sKV + (s) * KV_STG + a_ * QARR_B + r_ * FROW_B + c_ * 16, \
                       kvsrc[a_] + ((size_t)((kt_) * 128 + r_)) * HD + c_ * 8); \
        }                                                                      \
    } while (0)
    LOAD_KV(0, 0);
    CP_COMMIT();
    CP_WAIT(0);
    __syncthreads();

    const int arow  = (lid & 7) | (((lid >> 3) & 1) << 3);
    const int acolh = (lid >> 4) * 8;
    const int brow  = (lid & 7) + ((lid >> 4) & 1) * 8;
    const int bcolh = ((lid >> 3) & 1) * 8;

    uint32_t aqh[4][4], aql[4][4];
    #pragma unroll
    for (int k = 0; k < 4; k++) {
        uint32_t off = (uint32_t)((wid * 16 + arow) * FROW_B + (k * 16 + acolh) * 2);
        ldsm_x4(aqh[k][0], aqh[k][1], aqh[k][2], aqh[k][3], sQh + off);
        ldsm_x4(aql[k][0], aql[k][1], aql[k][2], aql[k][3], sQl + off);
    }

    float acc[8][4];
    #pragma unroll
    for (int g = 0; g < 8; g++)
        #pragma unroll
        for (int e = 0; e < 4; e++) acc[g][e] = 0.0f;
    float m0 = -1e30f, m1 = -1e30f, l0 = 0.0f, l1 = 0.0f;
    const int row0 = q0 + wid * 16 + (lid >> 2);

    const int nkv = qt + 1;
    for (int kt = 0; kt < nkv; kt++) {
        const int cur = kt & 1;
        if (kt + 1 < nkv) { LOAD_KV(cur ^ 1, kt + 1); CP_COMMIT(); }
        const uint32_t sK  = sKV + cur * KV_STG;
        const uint32_t sKl = sK + QARR_B;
        const uint32_t sV  = sK + 2 * QARR_B;
        const uint32_t sVl = sK + 3 * QARR_B;

        float sc[16][4];
        #pragma unroll
        for (int t = 0; t < 16; t++)
            #pragma unroll
            for (int e = 0; e < 4; e++) sc[t][e] = 0.0f;

        #pragma unroll
        for (int j2 = 0; j2 < 8; j2++) {
            #pragma unroll
            for (int k = 0; k < 4; k++) {
                uint32_t off = (uint32_t)((j2 * 16 + brow) * FROW_B + (k * 16 + bcolh) * 2);
                uint32_t b0, b1, b2, b3, c0, c1, c2, c3;
                ldsm_x4(b0, b1, b2, b3, sK + off);
                ldsm_x4(c0, c1, c2, c3, sKl + off);
                mma16816(sc[j2 * 2],     aqh[k], b0, b1);
                mma16816(sc[j2 * 2 + 1], aqh[k], b2, b3);
                mma16816(sc[j2 * 2],     aqh[k], c0, c1);
                mma16816(sc[j2 * 2 + 1], aqh[k], c2, c3);
                mma16816(sc[j2 * 2],     aql[k], b0, b1);
                mma16816(sc[j2 * 2 + 1], aql[k], b2, b3);
            }
        }

        if (kt == qt) {
            #pragma unroll
            for (int t = 0; t < 16; t++) {
                int colb = kt * 128 + t * 8 + (lid & 3) * 2;
                if (colb     > row0)     sc[t][0] = -1e30f;
                if (colb + 1 > row0)     sc[t][1] = -1e30f;
                if (colb     > row0 + 8) sc[t][2] = -1e30f;
                if (colb + 1 > row0 + 8) sc[t][3] = -1e30f;
            }
        }

        float mn0 = m0, mn1 = m1;
        #pragma unroll
        for (int t = 0; t < 16; t++) {
            mn0 = fmaxf(mn0, fmaxf(sc[t][0], sc[t][1]));
            mn1 = fmaxf(mn1, fmaxf(sc[t][2], sc[t][3]));
        }
        mn0 = fmaxf(mn0, __shfl_xor_sync(0xffffffffu, mn0, 1));
        mn0 = fmaxf(mn0, __shfl_xor_sync(0xffffffffu, mn0, 2));
        mn1 = fmaxf(mn1, __shfl_xor_sync(0xffffffffu, mn1, 1));
        mn1 = fmaxf(mn1, __shfl_xor_sync(0xffffffffu, mn1, 2));
        float corr0 = __expf(m0 - mn0);
        float corr1 = __expf(m1 - mn1);

        uint32_t phi[16][2], plo[16][2];
        float ls0 = 0.0f, ls1 = 0.0f;
        #pragma unroll
        for (int t = 0; t < 16; t++) {
            float p0 = __expf(sc[t][0] - mn0);
            float p1 = __expf(sc[t][1] - mn0);
            float p2 = __expf(sc[t][2] - mn1);
            float p3 = __expf(sc[t][3] - mn1);
            ls0 += p0 + p1;  ls1 += p2 + p3;
            split2(p0, p1, phi[t][0], plo[t][0]);
            split2(p2, p3, phi[t][1], plo[t][1]);
        }
        ls0 += __shfl_xor_sync(0xffffffffu, ls0, 1);
        ls0 += __shfl_xor_sync(0xffffffffu, ls0, 2);
        ls1 += __shfl_xor_sync(0xffffffffu, ls1, 1);
        ls1 += __shfl_xor_sync(0xffffffffu, ls1, 2);
        l0 = l0 * corr0 + ls0;  l1 = l1 * corr1 + ls1;
        m0 = mn0;  m1 = mn1;
        #pragma unroll
        for (int g = 0; g < 8; g++) {
            acc[g][0] *= corr0; acc[g][1] *= corr0;
            acc[g][2] *= corr1; acc[g][3] *= corr1;
        }

        #pragma unroll
        for (int k = 0; k < 8; k++) {
            uint32_t ph_[4] = {phi[k * 2][0], phi[k * 2][1], phi[k * 2 + 1][0], phi[k * 2 + 1][1]};
            uint32_t pl_[4] = {plo[k * 2][0], plo[k * 2][1], plo[k * 2 + 1][0], plo[k * 2 + 1][1]};
            #pragma unroll
            for (int g = 0; g < 4; g++) {
                uint32_t off = (uint32_t)((k * 16 + (lid & 15)) * FROW_B +
                                          (g * 16 + ((lid >> 4) & 1) * 8) * 2);
                uint32_t v0, v1, v2, v3, w0, w1, w2, w3;
                ldsm_x4_t(v0, v1, v2, v3, sV + off);
                ldsm_x4_t(w0, w1, w2, w3, sVl + off);
                mma16816(acc[g * 2],     ph_, v0, v1);
                mma16816(acc[g * 2 + 1], ph_, v2, v3);
                mma16816(acc[g * 2],     ph_, w0, w1);
                mma16816(acc[g * 2 + 1], ph_, w2, w3);
                mma16816(acc[g * 2],     pl_, v0, v1);
                mma16816(acc[g * 2 + 1], pl_, v2, v3);
            }
        }

        if (kt + 1 < nkv) CP_WAIT(0);
        __syncthreads();
    }
#undef LOAD_KV

    float inv0 = 1.0f / l0, inv1 = 1.0f / l1;
    #pragma unroll
    for (int g = 0; g < 8; g++) {
        int col = h * HD + g * 8 + (lid & 3) * 2;
        int r = q0 + wid * 16 + (lid >> 2);
        uint32_t h0, lo0, h1, lo1;
        split2(acc[g][0] * inv0, acc[g][1] * inv0, h0, lo0);
        split2(acc[g][2] * inv1, acc[g][3] * inv1, h1, lo1);
        *reinterpret_cast<uint32_t*>(&oh[(size_t)r * QDIM + col]) = h0;
        *reinterpret_cast<uint32_t*>(&ol[(size_t)r * QDIM + col]) = lo0;
        *reinterpret_cast<uint32_t*>(&oh[(size_t)(r + 8) * QDIM + col]) = h1;
        *reinterpret_cast<uint32_t*>(&ol[(size_t)(r + 8) * QDIM + col]) = lo1;
    }
}

// ---------------- launch ----------------------------------------------------
extern "C" void kernel_launch(void* const* d_in, const int* in_sizes, int n_in,
                              void* d_out, int out_size)
{
    const float* x       = (const float*)d_in[0];
    const float* qkv_w   = (const float*)d_in[1];
    const float* dense_w = (const float*)d_in[2];
    float* out = (float*)d_out;

    float* fused; cudaGetSymbolAddress((void**)&fused, g_fused);
    __nv_bfloat16 *xh, *xl, *wqh, *wql, *wdh, *wdl, *ah, *al;
    __nv_bfloat16 *qsh, *qsl, *ksh, *ksl, *vsh, *vsl;
    cudaGetSymbolAddress((void**)&xh,  g_xh);  cudaGetSymbolAddress((void**)&xl,  g_xl);
    cudaGetSymbolAddress((void**)&wqh, g_wqh); cudaGetSymbolAddress((void**)&wql, g_wql);
    cudaGetSymbolAddress((void**)&wdh, g_wdh); cudaGetSymbolAddress((void**)&wdl, g_wdl);
    cudaGetSymbolAddress((void**)&ah,  g_ah);  cudaGetSymbolAddress((void**)&al,  g_al);
    cudaGetSymbolAddress((void**)&qsh, g_qsh); cudaGetSymbolAddress((void**)&qsl, g_qsl);
    cudaGetSymbolAddress((void**)&ksh, g_ksh); cudaGetSymbolAddress((void**)&ksl, g_ksl);
    cudaGetSymbolAddress((void**)&vsh, g_vsh); cudaGetSymbolAddress((void**)&vsl, g_vsl);

    cudaFuncSetAttribute(gemm_mma,
                         cudaFuncAttributeMaxDynamicSharedMemorySize, GEMM_SMEM);
    cudaFuncSetAttribute(flash_mma,
                         cudaFuncAttributeMaxDynamicSharedMemorySize, FA_SMEM);

    // 1. RoPE table
    rope_table_kernel<<<(SEQ * 32 + 255) / 256, 256>>>();

    // 2. bf16 hi/lo splits (vectorized)
    {
        int t4 = SEQ * HIDDEN / 4;
        split4_kernel<<<(t4 + 255) / 256, 256>>>(
            (const float4*)x, (uint2*)xh, (uint2*)xl, t4, t4);
        int tw4 = QKV_PAD * HIDDEN / 4, sw4 = QKV_OUT * HIDDEN / 4;
        split4_kernel<<<(tw4 + 255) / 256, 256>>>(
            (const float4*)qkv_w, (uint2*)wqh, (uint2*)wql, tw4, sw4);
        int td4 = DEN_PAD * HIDDEN / 4, sd4 = HIDDEN * HIDDEN / 4;
        split4_kernel<<<(td4 + 255) / 256, 256>>>(
            (const float4*)dense_w, (uint2*)wdh, (uint2*)wdl, td4, sd4);
    }

    // 3. QKV GEMM: 2048x4736 tiles of 256x128
    {
        dim3 grid(QKV_PAD / BN2, SEQ / BM2);
        gemm_mma<<<grid, 256, GEMM_SMEM>>>(xh, xl, wqh, wql, fused,
                                           QKV_OUT, HIDDEN);
    }

    // 4. prep: rope + scale + hi/lo split of q, k, v
    {
        int total = SEQ * (NH + 2) * 32;
        prep_kernel<<<(total + 255) / 256, 256>>>();
    }

    // 5. flash attention (tensor cores) -> bf16 hi/lo activations
    {
        dim3 grid(SEQ / 128, NH);
        flash_mma<<<grid, 256, FA_SMEM>>>(qsh, qsl, ksh, ksl, vsh, vsl, ah, al);
    }

    // 6. dense GEMM -> out
    {
        dim3 grid(DEN_PAD / BN2, SEQ / BM2);
        gemm_mma<<<grid, 256, GEMM_SMEM>>>(ah, al, wdh, wdl, out,
                                           HIDDEN, HIDDEN);
    }
}

// round 8
// speedup vs baseline: 3.3329x; 1.0016x over previous
#include <cuda_runtime.h>
#include <cuda_bf16.h>
#include <math.h>
#include <stdint.h>

#define SEQ     2048
#define HIDDEN  4544
#define NH      71
#define HD      64
#define QKV_OUT 4672
#define QKV_PAD 4736            // 37*128
#define DEN_PAD 4608            // 36*128
#define QDIM    4544

// ---------------- scratch (device globals; no allocations allowed) ----------
__device__ float g_fused[SEQ * QKV_OUT];
__device__ float g_cos  [SEQ * 32];
__device__ float g_sin  [SEQ * 32];
__device__ __nv_bfloat16 g_xh [SEQ * HIDDEN],     g_xl [SEQ * HIDDEN];
__device__ __nv_bfloat16 g_wqh[QKV_PAD * HIDDEN], g_wql[QKV_PAD * HIDDEN];
__device__ __nv_bfloat16 g_wdh[DEN_PAD * HIDDEN], g_wdl[DEN_PAD * HIDDEN];
__device__ __nv_bfloat16 g_ah [SEQ * HIDDEN],     g_al [SEQ * HIDDEN];
// flash inputs (bf16 hi/lo, roped; q pre-scaled by 1/8)
__device__ __nv_bfloat16 g_qsh[NH * SEQ * HD], g_qsl[NH * SEQ * HD];
__device__ __nv_bfloat16 g_ksh[SEQ * HD], g_ksl[SEQ * HD];
__device__ __nv_bfloat16 g_vsh[SEQ * HD], g_vsl[SEQ * HD];

// ================= portable PTX helpers (sm_80+; no tcgen05) ================
__device__ __forceinline__ uint32_t smem_to_u32(const void* p) {
    uint32_t a;
    asm("{ .reg .u64 t; cvta.to.shared.u64 t, %1; cvt.u32.u64 %0, t; }"
        : "=r"(a) : "l"(p));
    return a;
}
__device__ __forceinline__ void ldsm_x4(uint32_t& r0, uint32_t& r1,
                                        uint32_t& r2, uint32_t& r3, uint32_t addr) {
    asm volatile("ldmatrix.sync.aligned.m8n8.x4.shared.b16 {%0,%1,%2,%3}, [%4];"
                 : "=r"(r0), "=r"(r1), "=r"(r2), "=r"(r3) : "r"(addr));
}
__device__ __forceinline__ void ldsm_x4_t(uint32_t& r0, uint32_t& r1,
                                          uint32_t& r2, uint32_t& r3, uint32_t addr) {
    asm volatile("ldmatrix.sync.aligned.m8n8.x4.trans.shared.b16 {%0,%1,%2,%3}, [%4];"
                 : "=r"(r0), "=r"(r1), "=r"(r2), "=r"(r3) : "r"(addr));
}
__device__ __forceinline__ void mma16816(float* c, const uint32_t* a,
                                         uint32_t b0, uint32_t b1) {
    asm volatile("mma.sync.aligned.m16n8k16.row.col.f32.bf16.bf16.f32 "
                 "{%0,%1,%2,%3}, {%4,%5,%6,%7}, {%8,%9}, {%0,%1,%2,%3};"
                 : "+f"(c[0]), "+f"(c[1]), "+f"(c[2]), "+f"(c[3])
                 : "r"(a[0]), "r"(a[1]), "r"(a[2]), "r"(a[3]), "r"(b0), "r"(b1));
}
__device__ __forceinline__ void cp_async16(uint32_t sdst, const void* gsrc) {
    asm volatile("cp.async.cg.shared.global [%0], [%1], 16;" :: "r"(sdst), "l"(gsrc));
}
#define CP_COMMIT() asm volatile("cp.async.commit_group;" ::: "memory")
#define CP_WAIT(n)  asm volatile("cp.async.wait_group %0;" :: "n"(n) : "memory")

__device__ __forceinline__ void split2(float a, float b, uint32_t& hi, uint32_t& lo) {
    __nv_bfloat162 h2 = __floats2bfloat162_rn(a, b);
    hi = *reinterpret_cast<uint32_t*>(&h2);
    float ra = a - __bfloat162float(h2.x);
    float rb = b - __bfloat162float(h2.y);
    __nv_bfloat162 l2 = __floats2bfloat162_rn(ra, rb);
    lo = *reinterpret_cast<uint32_t*>(&l2);
}

// ---------------- RoPE table (fp64 trig for accuracy) -----------------------
__global__ void rope_table_kernel() {
    int idx = blockIdx.x * blockDim.x + threadIdx.x;
    if (idx >= SEQ * 32) return;
    int s = idx >> 5, j = idx & 31;
    double inv = exp(-(double)j / 32.0 * log(10000.0));
    double ang = (double)s * inv;
    g_cos[idx] = (float)cos(ang);
    g_sin[idx] = (float)sin(ang);
}

// ---------------- fp32 -> bf16 hi/lo split, vectorized ----------------------
__global__ void split4_kernel(const float4* __restrict__ src,
                              uint2* __restrict__ hi,
                              uint2* __restrict__ lo,
                              int total4, int src_total4)
{
    int i = blockIdx.x * blockDim.x + threadIdx.x;
    if (i >= total4) return;
    float4 v = (i < src_total4) ? src[i] : make_float4(0.f, 0.f, 0.f, 0.f);
    uint2 h, l;
    split2(v.x, v.y, h.x, l.x);
    split2(v.z, v.w, h.y, l.y);
    hi[i] = h;
    lo[i] = l;
}

// ---------------- prep: rope + scale + bf16 hi/lo for q,k,v -----------------
__global__ void prep_kernel() {
    int idx = blockIdx.x * blockDim.x + threadIdx.x;
    const int total = SEQ * (NH + 2) * 32;
    if (idx >= total) return;
    int j  = idx & 31;
    int t  = idx >> 5;
    int hh = t % (NH + 2);
    int s  = t / (NH + 2);
    size_t base = (size_t)s * QKV_OUT + hh * HD;
    float a = g_fused[base + j];
    float b = g_fused[base + j + 32];
    float o1, o2;
    if (hh <= NH) {
        float c  = g_cos[s * 32 + j];
        float sn = g_sin[s * 32 + j];
        o1 = a * c - b * sn;
        o2 = b * c + a * sn;
    } else {
        o1 = a; o2 = b;
    }
    __nv_bfloat16 *dh, *dl;
    size_t doff;
    if (hh < NH) {
        o1 *= 0.125f; o2 *= 0.125f;
        dh = g_qsh; dl = g_qsl;
        doff = ((size_t)hh * SEQ + s) * HD;
    } else if (hh == NH) {
        dh = g_ksh; dl = g_ksl;
        doff = (size_t)s * HD;
    } else {
        dh = g_vsh; dl = g_vsl;
        doff = (size_t)s * HD;
    }
    __nv_bfloat16 h1 = __float2bfloat16(o1);
    __nv_bfloat16 h2 = __float2bfloat16(o2);
    dh[doff + j]      = h1;
    dh[doff + j + 32] = h2;
    dl[doff + j]      = __float2bfloat16(o1 - __bfloat162float(h1));
    dl[doff + j + 32] = __float2bfloat16(o2 - __bfloat162float(h2));
}

// ---------------- mma.sync bf16-split GEMM ----------------------------------
// 256x128 CTA tile, 512 threads (16 warps, 4Mx4N of 64x32 warptiles),
// 3-stage cp.async pipeline. 4 warps/SMSP hide LDSM phases under HMMA.
#define BM2 256
#define BN2 128
#define BKC 32
#define PIT 80                        // smem row pitch bytes (64B data)
#define A_ARR (BM2 * PIT)             // 20480
#define B_ARR (BN2 * PIT)             // 10240
#define STG2 (2 * A_ARR + 2 * B_ARR)  // 61440
#define NSTG 3
#define GEMM_SMEM (NSTG * STG2)       // 184320

__global__ __launch_bounds__(512, 1) void gemm_mma(
    const __nv_bfloat16* __restrict__ Ah, const __nv_bfloat16* __restrict__ Al,
    const __nv_bfloat16* __restrict__ Bh, const __nv_bfloat16* __restrict__ Bl,
    float* __restrict__ C, int N_real, int K)
{
    extern __shared__ __align__(128) char smem[];
    const int tid = threadIdx.x;
    const int wid = tid >> 5;
    const int lid = tid & 31;
    const int m0 = blockIdx.y * BM2;
    const int n0 = blockIdx.x * BN2;
    const int wm = (wid >> 2) * 64;       // 0,64,128,192
    const int wn = (wid & 3) * 32;        // 0,32,64,96
    const uint32_t sbase = smem_to_u32(smem);

#define LOAD_STAGE(s, k0) do {                                                  \
        uint32_t st_ = sbase + (s) * STG2;                                      \
        _Pragma("unroll")                                                       \
        for (int it_ = 0; it_ < 4; it_++) {          /* A: Ah then Al */        \
            int id_ = it_ * 512 + tid;                                          \
            int sel_ = id_ >> 10, w_ = id_ & 1023;                              \
            int r_ = w_ >> 2, ch_ = w_ & 3;                                     \
            const __nv_bfloat16* g_ = sel_ ? Al : Ah;                           \
            cp_async16(st_ + sel_ * A_ARR + r_ * PIT + ch_ * 16,                \
                       g_ + (size_t)(m0 + r_) * K + (k0) + ch_ * 8);            \
        }                                                                       \
        _Pragma("unroll")                                                       \
        for (int jt_ = 0; jt_ < 2; jt_++) {          /* B: Bh then Bl */        \
            int id_ = jt_ * 512 + tid;                                          \
            int sel_ = id_ >> 9, w_ = id_ & 511;                                \
            int r_ = w_ >> 2, ch_ = w_ & 3;                                     \
            const __nv_bfloat16* g_ = sel_ ? Bl : Bh;                           \
            cp_async16(st_ + 2 * A_ARR + sel_ * B_ARR + r_ * PIT + ch_ * 16,    \
                       g_ + (size_t)(n0 + r_) * K + (k0) + ch_ * 8);            \
        }                                                                       \
    } while (0)

    float acc[4][4][4];
    #pragma unroll
    for (int i = 0; i < 4; i++)
        #pragma unroll
        for (int j = 0; j < 4; j++)
            #pragma unroll
            for (int e = 0; e < 4; e++) acc[i][j][e] = 0.0f;

    const int nchunk = K / BKC;
    LOAD_STAGE(0, 0);
    CP_COMMIT();
    LOAD_STAGE(1, BKC);
    CP_COMMIT();

    const int arow  = (lid & 7) | (((lid >> 3) & 1) << 3);
    const int acolh = (lid >> 4) * 8;
    const int brow  = (lid & 7) + ((lid >> 4) & 1) * 8;
    const int bcolh = ((lid >> 3) & 1) * 8;

    int cur = 0;
    for (int c = 0; c < nchunk; c++) {
        if (c + 1 < nchunk) { CP_WAIT(1); } else { CP_WAIT(0); }
        __syncthreads();
        if (c + 2 < nchunk) {
            int nxt = cur + 2; if (nxt >= NSTG) nxt -= NSTG;
            LOAD_STAGE(nxt, (c + 2) * BKC);
            CP_COMMIT();
        }

        const uint32_t sAh = sbase + cur * STG2;
        const uint32_t sAl = sAh + A_ARR;
        const uint32_t sBh = sAh + 2 * A_ARR;
        const uint32_t sBl = sBh + B_ARR;

        #pragma unroll
        for (int kk = 0; kk < 2; kk++) {
            const int kc = kk * 16;
            uint32_t bh[2][4], bl[2][4], af[4][4];
            #pragma unroll
            for (int j = 0; j < 2; j++) {
                uint32_t off = (uint32_t)((wn + j * 16 + brow) * PIT + (kc + bcolh) * 2);
                ldsm_x4(bh[j][0], bh[j][1], bh[j][2], bh[j][3], sBh + off);
                ldsm_x4(bl[j][0], bl[j][1], bl[j][2], bl[j][3], sBl + off);
            }
            // phase A: af = Ah; acc += Ah*Bh + Ah*Bl
            #pragma unroll
            for (int i = 0; i < 4; i++) {
                uint32_t off = (uint32_t)((wm + i * 16 + arow) * PIT + (kc + acolh) * 2);
                ldsm_x4(af[i][0], af[i][1], af[i][2], af[i][3], sAh + off);
            }
            #pragma unroll
            for (int i = 0; i < 4; i++) {
                #pragma unroll
                for (int j = 0; j < 2; j++) {
                    mma16816(acc[i][j * 2 + 0], af[i], bh[j][0], bh[j][1]);
                    mma16816(acc[i][j * 2 + 1], af[i], bh[j][2], bh[j][3]);
                    mma16816(acc[i][j * 2 + 0], af[i], bl[j][0], bl[j][1]);
                    mma16816(acc[i][j * 2 + 1], af[i], bl[j][2], bl[j][3]);
                }
            }
            // phase B: af = Al; acc += Al*Bh
            #pragma unroll
            for (int i = 0; i < 4; i++) {
                uint32_t off = (uint32_t)((wm + i * 16 + arow) * PIT + (kc + acolh) * 2);
                ldsm_x4(af[i][0], af[i][1], af[i][2], af[i][3], sAl + off);
            }
            #pragma unroll
            for (int i = 0; i < 4; i++) {
                #pragma unroll
                for (int j = 0; j < 2; j++) {
                    mma16816(acc[i][j * 2 + 0], af[i], bh[j][0], bh[j][1]);
                    mma16816(acc[i][j * 2 + 1], af[i], bh[j][2], bh[j][3]);
                }
            }
        }
        cur++; if (cur >= NSTG) cur -= NSTG;
    }

    const int gr = lid >> 2, tg = lid & 3;
    #pragma unroll
    for (int i = 0; i < 4; i++) {
        #pragma unroll
        for (int j = 0; j < 4; j++) {
            int col = n0 + wn + j * 8 + tg * 2;
            if (col < N_real) {
                int row = m0 + wm + i * 16 + gr;
                float2 v0 = make_float2(acc[i][j][0], acc[i][j][1]);
                float2 v1 = make_float2(acc[i][j][2], acc[i][j][3]);
                *reinterpret_cast<float2*>(&C[(size_t)row * N_real + col]) = v0;
                *reinterpret_cast<float2*>(&C[(size_t)(row + 8) * N_real + col]) = v1;
            }
        }
    }
#undef LOAD_STAGE
}

// ---------------- flash attention via mma.sync (MQA, causal) -----------------
#define FROW_B 144
#define QARR_B (128 * FROW_B)
#define KV_STG (4 * QARR_B)
#define FA_SMEM (2 * QARR_B + 2 * KV_STG)

__global__ __launch_bounds__(256, 1) void flash_mma(
    const __nv_bfloat16* __restrict__ qh, const __nv_bfloat16* __restrict__ ql,
    const __nv_bfloat16* __restrict__ kh, const __nv_bfloat16* __restrict__ kl,
    const __nv_bfloat16* __restrict__ vh, const __nv_bfloat16* __restrict__ vl,
    __nv_bfloat16* __restrict__ oh, __nv_bfloat16* __restrict__ ol)
{
    extern __shared__ __align__(128) char smem[];
    const int tid = threadIdx.x, wid = tid >> 5, lid = tid & 31;
    const int qt = blockIdx.x, h = blockIdx.y;
    const int q0 = qt * 128;
    const uint32_t sb = smem_to_u32(smem);
    const uint32_t sQh = sb, sQl = sb + QARR_B;
    const uint32_t sKV = sb + 2 * QARR_B;

    {
        const __nv_bfloat16* srcs[2] = {qh, ql};
        #pragma unroll
        for (int i = 0; i < 8; i++) {
            int id = i * 256 + tid;
            int a = id >> 10, w = id & 1023, r = w >> 3, c = w & 7;
            cp_async16(sb + a * QARR_B + r * FROW_B + c * 16,
                       srcs[a] + ((size_t)h * SEQ + q0 + r) * HD + c * 8);
        }
    }
    const __nv_bfloat16* kvsrc[4] = {kh, kl, vh, vl};
#define LOAD_KV(s, kt_) do {                                                   \
        _Pragma("unroll")                                                      \
        for (int i_ = 0; i_ < 16; i_++) {                                      \
            int id_ = i_ * 256 + tid;                                          \
            int a_ = id_ >> 10, w_ = id_ & 1023, r_ = w_ >> 3, c_ = w_ & 7;    \
            cp_async16(sKV + (s) * KV_STG + a_ * QARR_B + r_ * FROW_B + c_ * 16, \
                       kvsrc[a_] + ((size_t)((kt_) * 128 + r_)) * HD + c_ * 8); \
        }                                                                      \
    } while (0)
    LOAD_KV(0, 0);
    CP_COMMIT();
    CP_WAIT(0);
    __syncthreads();

    const int arow  = (lid & 7) | (((lid >> 3) & 1) << 3);
    const int acolh = (lid >> 4) * 8;
    const int brow  = (lid & 7) + ((lid >> 4) & 1) * 8;
    const int bcolh = ((lid >> 3) & 1) * 8;

    uint32_t aqh[4][4], aql[4][4];
    #pragma unroll
    for (int k = 0; k < 4; k++) {
        uint32_t off = (uint32_t)((wid * 16 + arow) * FROW_B + (k * 16 + acolh) * 2);
        ldsm_x4(aqh[k][0], aqh[k][1], aqh[k][2], aqh[k][3], sQh + off);
        ldsm_x4(aql[k][0], aql[k][1], aql[k][2], aql[k][3], sQl + off);
    }

    float acc[8][4];
    #pragma unroll
    for (int g = 0; g < 8; g++)
        #pragma unroll
        for (int e = 0; e < 4; e++) acc[g][e] = 0.0f;
    float m0 = -1e30f, m1 = -1e30f, l0 = 0.0f, l1 = 0.0f;
    const int row0 = q0 + wid * 16 + (lid >> 2);

    const int nkv = qt + 1;
    for (int kt = 0; kt < nkv; kt++) {
        const int cur = kt & 1;
        if (kt + 1 < nkv) { LOAD_KV(cur ^ 1, kt + 1); CP_COMMIT(); }
        const uint32_t sK  = sKV + cur * KV_STG;
        const uint32_t sKl = sK + QARR_B;
        const uint32_t sV  = sK + 2 * QARR_B;
        const uint32_t sVl = sK + 3 * QARR_B;

        float sc[16][4];
        #pragma unroll
        for (int t = 0; t < 16; t++)
            #pragma unroll
            for (int e = 0; e < 4; e++) sc[t][e] = 0.0f;

        #pragma unroll
        for (int j2 = 0; j2 < 8; j2++) {
            #pragma unroll
            for (int k = 0; k < 4; k++) {
                uint32_t off = (uint32_t)((j2 * 16 + brow) * FROW_B + (k * 16 + bcolh) * 2);
                uint32_t b0, b1, b2, b3, c0, c1, c2, c3;
                ldsm_x4(b0, b1, b2, b3, sK + off);
                ldsm_x4(c0, c1, c2, c3, sKl + off);
                mma16816(sc[j2 * 2],     aqh[k], b0, b1);
                mma16816(sc[j2 * 2 + 1], aqh[k], b2, b3);
                mma16816(sc[j2 * 2],     aqh[k], c0, c1);
                mma16816(sc[j2 * 2 + 1], aqh[k], c2, c3);
                mma16816(sc[j2 * 2],     aql[k], b0, b1);
                mma16816(sc[j2 * 2 + 1], aql[k], b2, b3);
            }
        }

        if (kt == qt) {
            #pragma unroll
            for (int t = 0; t < 16; t++) {
                int colb = kt * 128 + t * 8 + (lid & 3) * 2;
                if (colb     > row0)     sc[t][0] = -1e30f;
                if (colb + 1 > row0)     sc[t][1] = -1e30f;
                if (colb     > row0 + 8) sc[t][2] = -1e30f;
                if (colb + 1 > row0 + 8) sc[t][3] = -1e30f;
            }
        }

        float mn0 = m0, mn1 = m1;
        #pragma unroll
        for (int t = 0; t < 16; t++) {
            mn0 = fmaxf(mn0, fmaxf(sc[t][0], sc[t][1]));
            mn1 = fmaxf(mn1, fmaxf(sc[t][2], sc[t][3]));
        }
        mn0 = fmaxf(mn0, __shfl_xor_sync(0xffffffffu, mn0, 1));
        mn0 = fmaxf(mn0, __shfl_xor_sync(0xffffffffu, mn0, 2));
        mn1 = fmaxf(mn1, __shfl_xor_sync(0xffffffffu, mn1, 1));
        mn1 = fmaxf(mn1, __shfl_xor_sync(0xffffffffu, mn1, 2));
        float corr0 = __expf(m0 - mn0);
        float corr1 = __expf(m1 - mn1);

        uint32_t phi[16][2], plo[16][2];
        float ls0 = 0.0f, ls1 = 0.0f;
        #pragma unroll
        for (int t = 0; t < 16; t++) {
            float p0 = __expf(sc[t][0] - mn0);
            float p1 = __expf(sc[t][1] - mn0);
            float p2 = __expf(sc[t][2] - mn1);
            float p3 = __expf(sc[t][3] - mn1);
            ls0 += p0 + p1;  ls1 += p2 + p3;
            split2(p0, p1, phi[t][0], plo[t][0]);
            split2(p2, p3, phi[t][1], plo[t][1]);
        }
        ls0 += __shfl_xor_sync(0xffffffffu, ls0, 1);
        ls0 += __shfl_xor_sync(0xffffffffu, ls0, 2);
        ls1 += __shfl_xor_sync(0xffffffffu, ls1, 1);
        ls1 += __shfl_xor_sync(0xffffffffu, ls1, 2);
        l0 = l0 * corr0 + ls0;  l1 = l1 * corr1 + ls1;
        m0 = mn0;  m1 = mn1;
        #pragma unroll
        for (int g = 0; g < 8; g++) {
            acc[g][0] *= corr0; acc[g][1] *= corr0;
            acc[g][2] *= corr1; acc[g][3] *= corr1;
        }

        #pragma unroll
        for (int k = 0; k < 8; k++) {
            uint32_t ph_[4] = {phi[k * 2][0], phi[k * 2][1], phi[k * 2 + 1][0], phi[k * 2 + 1][1]};
            uint32_t pl_[4] = {plo[k * 2][0], plo[k * 2][1], plo[k * 2 + 1][0], plo[k * 2 + 1][1]};
            #pragma unroll
            for (int g = 0; g < 4; g++) {
                uint32_t off = (uint32_t)((k * 16 + (lid & 15)) * FROW_B +
                                          (g * 16 + ((lid >> 4) & 1) * 8) * 2);
                uint32_t v0, v1, v2, v3, w0, w1, w2, w3;
                ldsm_x4_t(v0, v1, v2, v3, sV + off);
                ldsm_x4_t(w0, w1, w2, w3, sVl + off);
                mma16816(acc[g * 2],     ph_, v0, v1);
                mma16816(acc[g * 2 + 1], ph_, v2, v3);
                mma16816(acc[g * 2],     ph_, w0, w1);
                mma16816(acc[g * 2 + 1], ph_, w2, w3);
                mma16816(acc[g * 2],     pl_, v0, v1);
                mma16816(acc[g * 2 + 1], pl_, v2, v3);
            }
        }

        if (kt + 1 < nkv) CP_WAIT(0);
        __syncthreads();
    }
#undef LOAD_KV

    float inv0 = 1.0f / l0, inv1 = 1.0f / l1;
    #pragma unroll
    for (int g = 0; g < 8; g++) {
        int col = h * HD + g * 8 + (lid & 3) * 2;
        int r = q0 + wid * 16 + (lid >> 2);
        uint32_t h0, lo0, h1, lo1;
        split2(acc[g][0] * inv0, acc[g][1] * inv0, h0, lo0);
        split2(acc[g][2] * inv1, acc[g][3] * inv1, h1, lo1);
        *reinterpret_cast<uint32_t*>(&oh[(size_t)r * QDIM + col]) = h0;
        *reinterpret_cast<uint32_t*>(&ol[(size_t)r * QDIM + col]) = lo0;
        *reinterpret_cast<uint32_t*>(&oh[(size_t)(r + 8) * QDIM + col]) = h1;
        *reinterpret_cast<uint32_t*>(&ol[(size_t)(r + 8) * QDIM + col]) = lo1;
    }
}

// ---------------- launch ----------------------------------------------------
extern "C" void kernel_launch(void* const* d_in, const int* in_sizes, int n_in,
                              void* d_out, int out_size)
{
    const float* x       = (const float*)d_in[0];
    const float* qkv_w   = (const float*)d_in[1];
    const float* dense_w = (const float*)d_in[2];
    float* out = (float*)d_out;

    float* fused; cudaGetSymbolAddress((void**)&fused, g_fused);
    __nv_bfloat16 *xh, *xl, *wqh, *wql, *wdh, *wdl, *ah, *al;
    __nv_bfloat16 *qsh, *qsl, *ksh, *ksl, *vsh, *vsl;
    cudaGetSymbolAddress((void**)&xh,  g_xh);  cudaGetSymbolAddress((void**)&xl,  g_xl);
    cudaGetSymbolAddress((void**)&wqh, g_wqh); cudaGetSymbolAddress((void**)&wql, g_wql);
    cudaGetSymbolAddress((void**)&wdh, g_wdh); cudaGetSymbolAddress((void**)&wdl, g_wdl);
    cudaGetSymbolAddress((void**)&ah,  g_ah);  cudaGetSymbolAddress((void**)&al,  g_al);
    cudaGetSymbolAddress((void**)&qsh, g_qsh); cudaGetSymbolAddress((void**)&qsl, g_qsl);
    cudaGetSymbolAddress((void**)&ksh, g_ksh); cudaGetSymbolAddress((void**)&ksl, g_ksl);
    cudaGetSymbolAddress((void**)&vsh, g_vsh); cudaGetSymbolAddress((void**)&vsl, g_vsl);

    cudaFuncSetAttribute(gemm_mma,
                         cudaFuncAttributeMaxDynamicSharedMemorySize, GEMM_SMEM);
    cudaFuncSetAttribute(flash_mma,
                         cudaFuncAttributeMaxDynamicSharedMemorySize, FA_SMEM);

    // 1. RoPE table
    rope_table_kernel<<<(SEQ * 32 + 255) / 256, 256>>>();

    // 2. bf16 hi/lo splits (vectorized)
    {
        int t4 = SEQ * HIDDEN / 4;
        split4_kernel<<<(t4 + 255) / 256, 256>>>(
            (const float4*)x, (uint2*)xh, (uint2*)xl, t4, t4);
        int tw4 = QKV_PAD * HIDDEN / 4, sw4 = QKV_OUT * HIDDEN / 4;
        split4_kernel<<<(tw4 + 255) / 256, 256>>>(
            (const float4*)qkv_w, (uint2*)wqh, (uint2*)wql, tw4, sw4);
        int td4 = DEN_PAD * HIDDEN / 4, sd4 = HIDDEN * HIDDEN / 4;
        split4_kernel<<<(td4 + 255) / 256, 256>>>(
            (const float4*)dense_w, (uint2*)wdh, (uint2*)wdl, td4, sd4);
    }

    // 3. QKV GEMM: 256x128 tiles, 512 threads
    {
        dim3 grid(QKV_PAD / BN2, SEQ / BM2);
        gemm_mma<<<grid, 512, GEMM_SMEM>>>(xh, xl, wqh, wql, fused,
                                           QKV_OUT, HIDDEN);
    }

    // 4. prep: rope + scale + hi/lo split of q, k, v
    {
        int total = SEQ * (NH + 2) * 32;
        prep_kernel<<<(total + 255) / 256, 256>>>();
    }

    // 5. flash attention (tensor cores) -> bf16 hi/lo activations
    {
        dim3 grid(SEQ / 128, NH);
        flash_mma<<<grid, 256, FA_SMEM>>>(qsh, qsl, ksh, ksl, vsh, vsl, ah, al);
    }

    // 6. dense GEMM -> out
    {
        dim3 grid(DEN_PAD / BN2, SEQ / BM2);
        gemm_mma<<<grid, 512, GEMM_SMEM>>>(ah, al, wdh, wdl, out,
                                           HIDDEN, HIDDEN);
    }
}

// round 9
// speedup vs baseline: 4.6224x; 1.3869x over previous
#include <cuda_runtime.h>
#include <cuda_fp16.h>
#include <math.h>
#include <stdint.h>

#define SEQ     2048
#define HIDDEN  4544
#define NH      71
#define HD      64
#define QKV_OUT 4672
#define QKV_PAD 4736            // 37*128
#define DEN_PAD 4608            // 36*128
#define QDIM    4544

// Scaling scheme (keeps fp16 lo-parts in normal range):
//  activations/weights stored as 64*x (hi+lo for A-side, hi only for B-side)
//  GEMM acc = 4096 * true  -> epilogue * 2^-12
//  q stored as 32*q (folds softmax 1/8), k as 64*k -> scores = 2^14 * true
//  P stored as 64*P, v as 64*v -> attn acc = 4096 * (P.V); out' = 64*true

// ---------------- scratch (device globals; no allocations allowed) ----------
__device__ float g_fused[SEQ * QKV_OUT];
__device__ float g_cos  [SEQ * 32];
__device__ float g_sin  [SEQ * 32];
__device__ __half g_xh [SEQ * HIDDEN], g_xl [SEQ * HIDDEN];
__device__ __half g_wqh[QKV_PAD * HIDDEN];
__device__ __half g_wdh[DEN_PAD * HIDDEN];
__device__ __half g_ah [SEQ * HIDDEN], g_al [SEQ * HIDDEN];
__device__ __half g_qsh[NH * SEQ * HD], g_qsl[NH * SEQ * HD];
__device__ __half g_ksh[SEQ * HD];
__device__ __half g_vsh[SEQ * HD];

// ================= portable PTX helpers (sm_80+; no tcgen05) ================
__device__ __forceinline__ uint32_t smem_to_u32(const void* p) {
    uint32_t a;
    asm("{ .reg .u64 t; cvta.to.shared.u64 t, %1; cvt.u32.u64 %0, t; }"
        : "=r"(a) : "l"(p));
    return a;
}
__device__ __forceinline__ void ldsm_x4(uint32_t& r0, uint32_t& r1,
                                        uint32_t& r2, uint32_t& r3, uint32_t addr) {
    asm volatile("ldmatrix.sync.aligned.m8n8.x4.shared.b16 {%0,%1,%2,%3}, [%4];"
                 : "=r"(r0), "=r"(r1), "=r"(r2), "=r"(r3) : "r"(addr));
}
__device__ __forceinline__ void ldsm_x4_t(uint32_t& r0, uint32_t& r1,
                                          uint32_t& r2, uint32_t& r3, uint32_t addr) {
    asm volatile("ldmatrix.sync.aligned.m8n8.x4.trans.shared.b16 {%0,%1,%2,%3}, [%4];"
                 : "=r"(r0), "=r"(r1), "=r"(r2), "=r"(r3) : "r"(addr));
}
__device__ __forceinline__ void mma16816(float* c, const uint32_t* a,
                                         uint32_t b0, uint32_t b1) {
    asm volatile("mma.sync.aligned.m16n8k16.row.col.f32.f16.f16.f32 "
                 "{%0,%1,%2,%3}, {%4,%5,%6,%7}, {%8,%9}, {%0,%1,%2,%3};"
                 : "+f"(c[0]), "+f"(c[1]), "+f"(c[2]), "+f"(c[3])
                 : "r"(a[0]), "r"(a[1]), "r"(a[2]), "r"(a[3]), "r"(b0), "r"(b1));
}
__device__ __forceinline__ void cp_async16(uint32_t sdst, const void* gsrc) {
    asm volatile("cp.async.cg.shared.global [%0], [%1], 16;" :: "r"(sdst), "l"(gsrc));
}
#define CP_COMMIT() asm volatile("cp.async.commit_group;" ::: "memory")
#define CP_WAIT(n)  asm volatile("cp.async.wait_group %0;" :: "n"(n) : "memory")

// fp16 hi/lo split of a pair
__device__ __forceinline__ void split2h(float a, float b, uint32_t& hi, uint32_t& lo) {
    __half2 h2 = __floats2half2_rn(a, b);
    hi = *reinterpret_cast<uint32_t*>(&h2);
    float ra = a - __half2float(__low2half(h2));
    float rb = b - __half2float(__high2half(h2));
    __half2 l2 = __floats2half2_rn(ra, rb);
    lo = *reinterpret_cast<uint32_t*>(&l2);
}

// ---------------- RoPE table (fp64 trig for accuracy) -----------------------
__global__ void rope_table_kernel() {
    int idx = blockIdx.x * blockDim.x + threadIdx.x;
    if (idx >= SEQ * 32) return;
    int s = idx >> 5, j = idx & 31;
    double inv = exp(-(double)j / 32.0 * log(10000.0));
    double ang = (double)s * inv;
    g_cos[idx] = (float)cos(ang);
    g_sin[idx] = (float)sin(ang);
}

// ---------------- fp32 -> fp16 hi/lo split (x64), vectorized ----------------
__global__ void split4_hl(const float4* __restrict__ src,
                          uint2* __restrict__ hi, uint2* __restrict__ lo,
                          int total4)
{
    int i = blockIdx.x * blockDim.x + threadIdx.x;
    if (i >= total4) return;
    float4 v = src[i];
    uint2 h, l;
    split2h(v.x * 64.f, v.y * 64.f, h.x, l.x);
    split2h(v.z * 64.f, v.w * 64.f, h.y, l.y);
    hi[i] = h;
    lo[i] = l;
}

// hi-only variant (weights; zero-pads rows past src_total4)
__global__ void split4_h(const float4* __restrict__ src,
                         uint2* __restrict__ hi,
                         int total4, int src_total4)
{
    int i = blockIdx.x * blockDim.x + threadIdx.x;
    if (i >= total4) return;
    float4 v = (i < src_total4) ? src[i] : make_float4(0.f, 0.f, 0.f, 0.f);
    __half2 a = __floats2half2_rn(v.x * 64.f, v.y * 64.f);
    __half2 b = __floats2half2_rn(v.z * 64.f, v.w * 64.f);
    uint2 h;
    h.x = *reinterpret_cast<uint32_t*>(&a);
    h.y = *reinterpret_cast<uint32_t*>(&b);
    hi[i] = h;
}

// ---------------- prep: rope + scale + fp16 split for q,k,v -----------------
__global__ void prep_kernel() {
    int idx = blockIdx.x * blockDim.x + threadIdx.x;
    const int total = SEQ * (NH + 2) * 32;
    if (idx >= total) return;
    int j  = idx & 31;
    int t  = idx >> 5;
    int hh = t % (NH + 2);
    int s  = t / (NH + 2);
    size_t base = (size_t)s * QKV_OUT + hh * HD;
    float a = g_fused[base + j];
    float b = g_fused[base + j + 32];
    float o1, o2;
    if (hh <= NH) {
        float c  = g_cos[s * 32 + j];
        float sn = g_sin[s * 32 + j];
        o1 = a * c - b * sn;
        o2 = b * c + a * sn;
    } else {
        o1 = a; o2 = b;
    }
    if (hh < NH) {                        // q: hi/lo, scale 32 (folds 1/8 * 256)
        o1 *= 32.f; o2 *= 32.f;
        size_t doff = ((size_t)hh * SEQ + s) * HD;
        __half h1 = __float2half_rn(o1);
        __half h2 = __float2half_rn(o2);
        g_qsh[doff + j]      = h1;
        g_qsh[doff + j + 32] = h2;
        g_qsl[doff + j]      = __float2half_rn(o1 - __half2float(h1));
        g_qsl[doff + j + 32] = __float2half_rn(o2 - __half2float(h2));
    } else {                              // k or v: hi only, scale 64
        __half* dh = (hh == NH) ? g_ksh : g_vsh;
        size_t doff = (size_t)s * HD;
        dh[doff + j]      = __float2half_rn(o1 * 64.f);
        dh[doff + j + 32] = __float2half_rn(o2 * 64.f);
    }
}

// ---------------- mma.sync fp16 2-term GEMM ---------------------------------
// C = (Ah + Al) * Bh, A exact to 2^-24, B truncated (err ~2^-12).
// 256x128 CTA, 512 threads (16 warps, 4Mx4N of 64x32), 3-stage cp.async.
#define BM2 256
#define BN2 128
#define BKC 32
#define PIT 80                        // smem row pitch bytes (64B data)
#define A_ARR (BM2 * PIT)             // 20480
#define B_ARR (BN2 * PIT)             // 10240
#define STG2 (2 * A_ARR + B_ARR)      // 51200
#define NSTG 3
#define GEMM_SMEM (NSTG * STG2)       // 153600

__global__ __launch_bounds__(512, 1) void gemm_mma(
    const __half* __restrict__ Ah, const __half* __restrict__ Al,
    const __half* __restrict__ Bh,
    float* __restrict__ C, int N_real, int K)
{
    extern __shared__ __align__(128) char smem[];
    const int tid = threadIdx.x;
    const int wid = tid >> 5;
    const int lid = tid & 31;
    const int m0 = blockIdx.y * BM2;
    const int n0 = blockIdx.x * BN2;
    const int wm = (wid >> 2) * 64;
    const int wn = (wid & 3) * 32;
    const uint32_t sbase = smem_to_u32(smem);

#define LOAD_STAGE(s, k0) do {                                                  \
        uint32_t st_ = sbase + (s) * STG2;                                      \
        _Pragma("unroll")                                                       \
        for (int it_ = 0; it_ < 4; it_++) {          /* A: Ah then Al */        \
            int id_ = it_ * 512 + tid;                                          \
            int sel_ = id_ >> 10, w_ = id_ & 1023;                              \
            int r_ = w_ >> 2, ch_ = w_ & 3;                                     \
            const __half* g_ = sel_ ? Al : Ah;                                  \
            cp_async16(st_ + sel_ * A_ARR + r_ * PIT + ch_ * 16,                \
                       g_ + (size_t)(m0 + r_) * K + (k0) + ch_ * 8);            \
        }                                                                       \
        {                                            /* B: Bh only */           \
            int r_ = tid >> 2, ch_ = tid & 3;                                   \
            cp_async16(st_ + 2 * A_ARR + r_ * PIT + ch_ * 16,                   \
                       Bh + (size_t)(n0 + r_) * K + (k0) + ch_ * 8);            \
        }                                                                       \
    } while (0)

    float acc[4][4][4];
    #pragma unroll
    for (int i = 0; i < 4; i++)
        #pragma unroll
        for (int j = 0; j < 4; j++)
            #pragma unroll
            for (int e = 0; e < 4; e++) acc[i][j][e] = 0.0f;

    const int nchunk = K / BKC;
    LOAD_STAGE(0, 0);
    CP_COMMIT();
    LOAD_STAGE(1, BKC);
    CP_COMMIT();

    const int arow  = (lid & 7) | (((lid >> 3) & 1) << 3);
    const int acolh = (lid >> 4) * 8;
    const int brow  = (lid & 7) + ((lid >> 4) & 1) * 8;
    const int bcolh = ((lid >> 3) & 1) * 8;

    int cur = 0;
    for (int c = 0; c < nchunk; c++) {
        if (c + 1 < nchunk) { CP_WAIT(1); } else { CP_WAIT(0); }
        __syncthreads();
        if (c + 2 < nchunk) {
            int nxt = cur + 2; if (nxt >= NSTG) nxt -= NSTG;
            LOAD_STAGE(nxt, (c + 2) * BKC);
            CP_COMMIT();
        }

        const uint32_t sAh = sbase + cur * STG2;
        const uint32_t sAl = sAh + A_ARR;
        const uint32_t sBh = sAh + 2 * A_ARR;

        #pragma unroll
        for (int kk = 0; kk < 2; kk++) {
            const int kc = kk * 16;
            uint32_t bh[2][4], af[4][4];
            #pragma unroll
            for (int j = 0; j < 2; j++) {
                uint32_t off = (uint32_t)((wn + j * 16 + brow) * PIT + (kc + bcolh) * 2);
                ldsm_x4(bh[j][0], bh[j][1], bh[j][2], bh[j][3], sBh + off);
            }
            // phase A: Ah * Bh
            #pragma unroll
            for (int i = 0; i < 4; i++) {
                uint32_t off = (uint32_t)((wm + i * 16 + arow) * PIT + (kc + acolh) * 2);
                ldsm_x4(af[i][0], af[i][1], af[i][2], af[i][3], sAh + off);
            }
            #pragma unroll
            for (int i = 0; i < 4; i++) {
                #pragma unroll
                for (int j = 0; j < 2; j++) {
                    mma16816(acc[i][j * 2 + 0], af[i], bh[j][0], bh[j][1]);
                    mma16816(acc[i][j * 2 + 1], af[i], bh[j][2], bh[j][3]);
                }
            }
            // phase B: Al * Bh
            #pragma unroll
            for (int i = 0; i < 4; i++) {
                uint32_t off = (uint32_t)((wm + i * 16 + arow) * PIT + (kc + acolh) * 2);
                ldsm_x4(af[i][0], af[i][1], af[i][2], af[i][3], sAl + off);
            }
            #pragma unroll
            for (int i = 0; i < 4; i++) {
                #pragma unroll
                for (int j = 0; j < 2; j++) {
                    mma16816(acc[i][j * 2 + 0], af[i], bh[j][0], bh[j][1]);
                    mma16816(acc[i][j * 2 + 1], af[i], bh[j][2], bh[j][3]);
                }
            }
        }
        cur++; if (cur >= NSTG) cur -= NSTG;
    }

    const float DS = 1.0f / 4096.0f;     // undo 64*64 input scaling
    const int gr = lid >> 2, tg = lid & 3;
    #pragma unroll
    for (int i = 0; i < 4; i++) {
        #pragma unroll
        for (int j = 0; j < 4; j++) {
            int col = n0 + wn + j * 8 + tg * 2;
            if (col < N_real) {
                int row = m0 + wm + i * 16 + gr;
                float2 v0 = make_float2(acc[i][j][0] * DS, acc[i][j][1] * DS);
                float2 v1 = make_float2(acc[i][j][2] * DS, acc[i][j][3] * DS);
                *reinterpret_cast<float2*>(&C[(size_t)row * N_real + col]) = v0;
                *reinterpret_cast<float2*>(&C[(size_t)(row + 8) * N_real + col]) = v1;
            }
        }
    }
#undef LOAD_STAGE
}

// ---------------- flash attention via mma.sync fp16 (MQA, causal) ------------
#define FROW_B 144
#define QARR_B (128 * FROW_B)
#define KV_STG (2 * QARR_B)                 // Kh, Vh only
#define FA_SMEM (2 * QARR_B + 2 * KV_STG)   // 110592

__global__ __launch_bounds__(256, 1) void flash_mma(
    const __half* __restrict__ qh, const __half* __restrict__ ql,
    const __half* __restrict__ kh, const __half* __restrict__ vh,
    __half* __restrict__ oh, __half* __restrict__ ol)
{
    extern __shared__ __align__(128) char smem[];
    const int tid = threadIdx.x, wid = tid >> 5, lid = tid & 31;
    const int qt = blockIdx.x, h = blockIdx.y;
    const int q0 = qt * 128;
    const uint32_t sb = smem_to_u32(smem);
    const uint32_t sQh = sb, sQl = sb + QARR_B;
    const uint32_t sKV = sb + 2 * QARR_B;

    {
        const __half* srcs[2] = {qh, ql};
        #pragma unroll
        for (int i = 0; i < 8; i++) {
            int id = i * 256 + tid;
            int a = id >> 10, w = id & 1023, r = w >> 3, c = w & 7;
            cp_async16(sb + a * QARR_B + r * FROW_B + c * 16,
                       srcs[a] + ((size_t)h * SEQ + q0 + r) * HD + c * 8);
        }
    }
    const __half* kvsrc[2] = {kh, vh};
#define LOAD_KV(s, kt_) do {                                                   \
        _Pragma("unroll")                                                      \
        for (int i_ = 0; i_ < 8; i_++) {                                       \
            int id_ = i_ * 256 + tid;                                          \
            int a_ = id_ >> 10, w_ = id_ & 1023, r_ = w_ >> 3, c_ = w_ & 7;    \
            cp_async16(sKV + (s) * KV_STG + a_ * QARR_B + r_ * FROW_B + c_ * 16, \
                       kvsrc[a_] + ((size_t)((kt_) * 128 + r_)) * HD + c_ * 8); \
        }                                                                      \
    } while (0)
    LOAD_KV(0, 0);
    CP_COMMIT();
    CP_WAIT(0);
    __syncthreads();

    const int arow  = (lid & 7) | (((lid >> 3) & 1) << 3);
    const int acolh = (lid >> 4) * 8;
    const int brow  = (lid & 7) + ((lid >> 4) & 1) * 8;
    const int bcolh = ((lid >> 3) & 1) * 8;

    uint32_t aqh[4][4], aql[4][4];
    #pragma unroll
    for (int k = 0; k < 4; k++) {
        uint32_t off = (uint32_t)((wid * 16 + arow) * FROW_B + (k * 16 + acolh) * 2);
        ldsm_x4(aqh[k][0], aqh[k][1], aqh[k][2], aqh[k][3], sQh + off);
        ldsm_x4(aql[k][0], aql[k][1], aql[k][2], aql[k][3], sQl + off);
    }

    float acc[8][4];
    #pragma unroll
    for (int g = 0; g < 8; g++)
        #pragma unroll
        for (int e = 0; e < 4; e++) acc[g][e] = 0.0f;
    float m0 = -1e30f, m1 = -1e30f, l0 = 0.0f, l1 = 0.0f;
    const int row0 = q0 + wid * 16 + (lid >> 2);
    const float SC = 1.0f / 16384.0f;   // undo 32*64 q/k scaling + keep 1/8

    const int nkv = qt + 1;
    for (int kt = 0; kt < nkv; kt++) {
        const int cur = kt & 1;
        if (kt + 1 < nkv) { LOAD_KV(cur ^ 1, kt + 1); CP_COMMIT(); }
        const uint32_t sK = sKV + cur * KV_STG;
        const uint32_t sV = sK + QARR_B;

        float sc[16][4];
        #pragma unroll
        for (int t = 0; t < 16; t++)
            #pragma unroll
            for (int e = 0; e < 4; e++) sc[t][e] = 0.0f;

        #pragma unroll
        for (int j2 = 0; j2 < 8; j2++) {
            #pragma unroll
            for (int k = 0; k < 4; k++) {
                uint32_t off = (uint32_t)((j2 * 16 + brow) * FROW_B + (k * 16 + bcolh) * 2);
                uint32_t b0, b1, b2, b3;
                ldsm_x4(b0, b1, b2, b3, sK + off);
                mma16816(sc[j2 * 2],     aqh[k], b0, b1);
                mma16816(sc[j2 * 2 + 1], aqh[k], b2, b3);
                mma16816(sc[j2 * 2],     aql[k], b0, b1);
                mma16816(sc[j2 * 2 + 1], aql[k], b2, b3);
            }
        }

        #pragma unroll
        for (int t = 0; t < 16; t++)
            #pragma unroll
            for (int e = 0; e < 4; e++) sc[t][e] *= SC;

        if (kt == qt) {
            #pragma unroll
            for (int t = 0; t < 16; t++) {
                int colb = kt * 128 + t * 8 + (lid & 3) * 2;
                if (colb     > row0)     sc[t][0] = -1e30f;
                if (colb + 1 > row0)     sc[t][1] = -1e30f;
                if (colb     > row0 + 8) sc[t][2] = -1e30f;
                if (colb + 1 > row0 + 8) sc[t][3] = -1e30f;
            }
        }

        float mn0 = m0, mn1 = m1;
        #pragma unroll
        for (int t = 0; t < 16; t++) {
            mn0 = fmaxf(mn0, fmaxf(sc[t][0], sc[t][1]));
            mn1 = fmaxf(mn1, fmaxf(sc[t][2], sc[t][3]));
        }
        mn0 = fmaxf(mn0, __shfl_xor_sync(0xffffffffu, mn0, 1));
        mn0 = fmaxf(mn0, __shfl_xor_sync(0xffffffffu, mn0, 2));
        mn1 = fmaxf(mn1, __shfl_xor_sync(0xffffffffu, mn1, 1));
        mn1 = fmaxf(mn1, __shfl_xor_sync(0xffffffffu, mn1, 2));
        float corr0 = __expf(m0 - mn0);
        float corr1 = __expf(m1 - mn1);

        uint32_t phi[16][2], plo[16][2];
        float ls0 = 0.0f, ls1 = 0.0f;
        #pragma unroll
        for (int t = 0; t < 16; t++) {
            float p0 = __expf(sc[t][0] - mn0);
            float p1 = __expf(sc[t][1] - mn0);
            float p2 = __expf(sc[t][2] - mn1);
            float p3 = __expf(sc[t][3] - mn1);
            ls0 += p0 + p1;  ls1 += p2 + p3;
            split2h(p0 * 64.f, p1 * 64.f, phi[t][0], plo[t][0]);
            split2h(p2 * 64.f, p3 * 64.f, phi[t][1], plo[t][1]);
        }
        ls0 += __shfl_xor_sync(0xffffffffu, ls0, 1);
        ls0 += __shfl_xor_sync(0xffffffffu, ls0, 2);
        ls1 += __shfl_xor_sync(0xffffffffu, ls1, 1);
        ls1 += __shfl_xor_sync(0xffffffffu, ls1, 2);
        l0 = l0 * corr0 + ls0;  l1 = l1 * corr1 + ls1;
        m0 = mn0;  m1 = mn1;
        #pragma unroll
        for (int g = 0; g < 8; g++) {
            acc[g][0] *= corr0; acc[g][1] *= corr0;
            acc[g][2] *= corr1; acc[g][3] *= corr1;
        }

        #pragma unroll
        for (int k = 0; k < 8; k++) {
            uint32_t ph_[4] = {phi[k * 2][0], phi[k * 2][1], phi[k * 2 + 1][0], phi[k * 2 + 1][1]};
            uint32_t pl_[4] = {plo[k * 2][0], plo[k * 2][1], plo[k * 2 + 1][0], plo[k * 2 + 1][1]};
            #pragma unroll
            for (int g = 0; g < 4; g++) {
                uint32_t off = (uint32_t)((k * 16 + (lid & 15)) * FROW_B +
                                          (g * 16 + ((lid >> 4) & 1) * 8) * 2);
                uint32_t v0, v1, v2, v3;
                ldsm_x4_t(v0, v1, v2, v3, sV + off);
                mma16816(acc[g * 2],     ph_, v0, v1);
                mma16816(acc[g * 2 + 1], ph_, v2, v3);
                mma16816(acc[g * 2],     pl_, v0, v1);
                mma16816(acc[g * 2 + 1], pl_, v2, v3);
            }
        }

        if (kt + 1 < nkv) CP_WAIT(0);
        __syncthreads();
    }
#undef LOAD_KV

    // out' = 64 * true_out (feeds dense GEMM A-side): acc = 4096*P.V, /l, *64
    float inv0 = 1.0f / (64.0f * l0), inv1 = 1.0f / (64.0f * l1);
    #pragma unroll
    for (int g = 0; g < 8; g++) {
        int col = h * HD + g * 8 + (lid & 3) * 2;
        int r = q0 + wid * 16 + (lid >> 2);
        uint32_t h0, lo0, h1, lo1;
        split2h(acc[g][0] * inv0, acc[g][1] * inv0, h0, lo0);
        split2h(acc[g][2] * inv1, acc[g][3] * inv1, h1, lo1);
        *reinterpret_cast<uint32_t*>(&oh[(size_t)r * QDIM + col]) = h0;
        *reinterpret_cast<uint32_t*>(&ol[(size_t)r * QDIM + col]) = lo0;
        *reinterpret_cast<uint32_t*>(&oh[(size_t)(r + 8) * QDIM + col]) = h1;
        *reinterpret_cast<uint32_t*>(&ol[(size_t)(r + 8) * QDIM + col]) = lo1;
    }
}

// ---------------- launch ----------------------------------------------------
extern "C" void kernel_launch(void* const* d_in, const int* in_sizes, int n_in,
                              void* d_out, int out_size)
{
    const float* x       = (const float*)d_in[0];
    const float* qkv_w   = (const float*)d_in[1];
    const float* dense_w = (const float*)d_in[2];
    float* out = (float*)d_out;

    float* fused; cudaGetSymbolAddress((void**)&fused, g_fused);
    __half *xh, *xl, *wqh, *wdh, *ah, *al, *qsh, *qsl, *ksh, *vsh;
    cudaGetSymbolAddress((void**)&xh,  g_xh);  cudaGetSymbolAddress((void**)&xl,  g_xl);
    cudaGetSymbolAddress((void**)&wqh, g_wqh); cudaGetSymbolAddress((void**)&wdh, g_wdh);
    cudaGetSymbolAddress((void**)&ah,  g_ah);  cudaGetSymbolAddress((void**)&al,  g_al);
    cudaGetSymbolAddress((void**)&qsh, g_qsh); cudaGetSymbolAddress((void**)&qsl, g_qsl);
    cudaGetSymbolAddress((void**)&ksh, g_ksh); cudaGetSymbolAddress((void**)&vsh, g_vsh);

    cudaFuncSetAttribute(gemm_mma,
                         cudaFuncAttributeMaxDynamicSharedMemorySize, GEMM_SMEM);
    cudaFuncSetAttribute(flash_mma,
                         cudaFuncAttributeMaxDynamicSharedMemorySize, FA_SMEM);

    // 1. RoPE table
    rope_table_kernel<<<(SEQ * 32 + 255) / 256, 256>>>();

    // 2. fp16 splits: x hi/lo; weights hi only
    {
        int t4 = SEQ * HIDDEN / 4;
        split4_hl<<<(t4 + 255) / 256, 256>>>(
            (const float4*)x, (uint2*)xh, (uint2*)xl, t4);
        int tw4 = QKV_PAD * HIDDEN / 4, sw4 = QKV_OUT * HIDDEN / 4;
        split4_h<<<(tw4 + 255) / 256, 256>>>(
            (const float4*)qkv_w, (uint2*)wqh, tw4, sw4);
        int td4 = DEN_PAD * HIDDEN / 4, sd4 = HIDDEN * HIDDEN / 4;
        split4_h<<<(td4 + 255) / 256, 256>>>(
            (const float4*)dense_w, (uint2*)wdh, td4, sd4);
    }

    // 3. QKV GEMM (2-term fp16)
    {
        dim3 grid(QKV_PAD / BN2, SEQ / BM2);
        gemm_mma<<<grid, 512, GEMM_SMEM>>>(xh, xl, wqh, fused, QKV_OUT, HIDDEN);
    }

    // 4. prep: rope + scale + fp16 split of q (hi/lo), k/v (hi)
    {
        int total = SEQ * (NH + 2) * 32;
        prep_kernel<<<(total + 255) / 256, 256>>>();
    }

    // 5. flash attention -> fp16 hi/lo activations (pre-scaled x64)
    {
        dim3 grid(SEQ / 128, NH);
        flash_mma<<<grid, 256, FA_SMEM>>>(qsh, qsl, ksh, vsh, ah, al);
    }

    // 6. dense GEMM (2-term fp16) -> out
    {
        dim3 grid(DEN_PAD / BN2, SEQ / BM2);
        gemm_mma<<<grid, 512, GEMM_SMEM>>>(ah, al, wdh, out, HIDDEN, HIDDEN);
    }
}

// round 10
// speedup vs baseline: 7.0422x; 1.5235x over previous
#include <cuda_runtime.h>
#include <cuda_fp16.h>
#include <math.h>
#include <stdint.h>

#define SEQ     2048
#define HIDDEN  4544
#define NH      71
#define HD      64
#define QKV_OUT 4672
#define QKV_PAD 4736            // 37*128
#define DEN_PAD 4608            // 36*128
#define QDIM    4544

// Scaling: activations/weights stored as 64*x (fp16), GEMM acc = 4096*true.
// q stored 32*q (folds 1/8), k 64*k -> scores = 16384*true.
// P stored 64*P, v 64*v -> attn acc = 4096*(P.V); attn out stored 64*true.

// ---------------- scratch (device globals; no allocations allowed) ----------
__device__ float g_fused[SEQ * QKV_OUT];
__device__ float g_cos  [SEQ * 32];
__device__ float g_sin  [SEQ * 32];
__device__ __half g_xh [SEQ * HIDDEN];
__device__ __half g_wqh[QKV_PAD * HIDDEN];
__device__ __half g_wdh[DEN_PAD * HIDDEN];
__device__ __half g_ah [SEQ * HIDDEN];
__device__ __half g_qsh[NH * SEQ * HD];
__device__ __half g_ksh[SEQ * HD];
__device__ __half g_vsh[SEQ * HD];

// ================= portable PTX helpers (sm_80+; no tcgen05) ================
__device__ __forceinline__ uint32_t smem_to_u32(const void* p) {
    uint32_t a;
    asm("{ .reg .u64 t; cvta.to.shared.u64 t, %1; cvt.u32.u64 %0, t; }"
        : "=r"(a) : "l"(p));
    return a;
}
__device__ __forceinline__ void ldsm_x4(uint32_t& r0, uint32_t& r1,
                                        uint32_t& r2, uint32_t& r3, uint32_t addr) {
    asm volatile("ldmatrix.sync.aligned.m8n8.x4.shared.b16 {%0,%1,%2,%3}, [%4];"
                 : "=r"(r0), "=r"(r1), "=r"(r2), "=r"(r3) : "r"(addr));
}
__device__ __forceinline__ void ldsm_x4_t(uint32_t& r0, uint32_t& r1,
                                          uint32_t& r2, uint32_t& r3, uint32_t addr) {
    asm volatile("ldmatrix.sync.aligned.m8n8.x4.trans.shared.b16 {%0,%1,%2,%3}, [%4];"
                 : "=r"(r0), "=r"(r1), "=r"(r2), "=r"(r3) : "r"(addr));
}
__device__ __forceinline__ void mma16816(float* c, const uint32_t* a,
                                         uint32_t b0, uint32_t b1) {
    asm volatile("mma.sync.aligned.m16n8k16.row.col.f32.f16.f16.f32 "
                 "{%0,%1,%2,%3}, {%4,%5,%6,%7}, {%8,%9}, {%0,%1,%2,%3};"
                 : "+f"(c[0]), "+f"(c[1]), "+f"(c[2]), "+f"(c[3])
                 : "r"(a[0]), "r"(a[1]), "r"(a[2]), "r"(a[3]), "r"(b0), "r"(b1));
}
__device__ __forceinline__ void cp_async16(uint32_t sdst, const void* gsrc) {
    asm volatile("cp.async.cg.shared.global [%0], [%1], 16;" :: "r"(sdst), "l"(gsrc));
}
#define CP_COMMIT() asm volatile("cp.async.commit_group;" ::: "memory")
#define CP_WAIT(n)  asm volatile("cp.async.wait_group %0;" :: "n"(n) : "memory")

// ---------------- RoPE table (fp64 trig for accuracy) -----------------------
__global__ void rope_table_kernel() {
    int idx = blockIdx.x * blockDim.x + threadIdx.x;
    if (idx >= SEQ * 32) return;
    int s = idx >> 5, j = idx & 31;
    double inv = exp(-(double)j / 32.0 * log(10000.0));
    double ang = (double)s * inv;
    g_cos[idx] = (float)cos(ang);
    g_sin[idx] = (float)sin(ang);
}

// ---------------- fp32 -> fp16 (x64), vectorized (zero-pads tail rows) ------
__global__ void split4_h(const float4* __restrict__ src,
                         uint2* __restrict__ hi,
                         int total4, int src_total4)
{
    int i = blockIdx.x * blockDim.x + threadIdx.x;
    if (i >= total4) return;
    float4 v = (i < src_total4) ? src[i] : make_float4(0.f, 0.f, 0.f, 0.f);
    __half2 a = __floats2half2_rn(v.x * 64.f, v.y * 64.f);
    __half2 b = __floats2half2_rn(v.z * 64.f, v.w * 64.f);
    uint2 h;
    h.x = *reinterpret_cast<uint32_t*>(&a);
    h.y = *reinterpret_cast<uint32_t*>(&b);
    hi[i] = h;
}

// ---------------- prep: rope + scale + fp16 for q,k,v -----------------------
__global__ void prep_kernel() {
    int idx = blockIdx.x * blockDim.x + threadIdx.x;
    const int total = SEQ * (NH + 2) * 32;
    if (idx >= total) return;
    int j  = idx & 31;
    int t  = idx >> 5;
    int hh = t % (NH + 2);
    int s  = t / (NH + 2);
    size_t base = (size_t)s * QKV_OUT + hh * HD;
    float a = g_fused[base + j];
    float b = g_fused[base + j + 32];
    float o1, o2;
    if (hh <= NH) {
        float c  = g_cos[s * 32 + j];
        float sn = g_sin[s * 32 + j];
        o1 = a * c - b * sn;
        o2 = b * c + a * sn;
    } else {
        o1 = a; o2 = b;
    }
    if (hh < NH) {                        // q: scale 32 (folds 1/8 * 256)
        size_t doff = ((size_t)hh * SEQ + s) * HD;
        g_qsh[doff + j]      = __float2half_rn(o1 * 32.f);
        g_qsh[doff + j + 32] = __float2half_rn(o2 * 32.f);
    } else {                              // k or v: scale 64
        __half* dh = (hh == NH) ? g_ksh : g_vsh;
        size_t doff = (size_t)s * HD;
        dh[doff + j]      = __float2half_rn(o1 * 64.f);
        dh[doff + j + 32] = __float2half_rn(o2 * 64.f);
    }
}

// ---------------- mma.sync fp16 single-term GEMM ----------------------------
// C = A * B^T, both truncated fp16 (x64 scaled). 256x128 CTA, 512 threads
// (16 warps, 4Mx4N of 64x32 warptiles), 3-stage cp.async pipeline.
#define BM2 256
#define BN2 128
#define BKC 32
#define PIT 80                        // smem row pitch bytes (64B data)
#define A_ARR (BM2 * PIT)             // 20480
#define B_ARR (BN2 * PIT)             // 10240
#define STG2 (A_ARR + B_ARR)          // 30720
#define NSTG 3
#define GEMM_SMEM (NSTG * STG2)       // 92160

__global__ __launch_bounds__(512, 1) void gemm_mma(
    const __half* __restrict__ Ah, const __half* __restrict__ Bh,
    float* __restrict__ C, int N_real, int K)
{
    extern __shared__ __align__(128) char smem[];
    const int tid = threadIdx.x;
    const int wid = tid >> 5;
    const int lid = tid & 31;
    const int m0 = blockIdx.y * BM2;
    const int n0 = blockIdx.x * BN2;
    const int wm = (wid >> 2) * 64;
    const int wn = (wid & 3) * 32;
    const uint32_t sbase = smem_to_u32(smem);

#define LOAD_STAGE(s, k0) do {                                                  \
        uint32_t st_ = sbase + (s) * STG2;                                      \
        _Pragma("unroll")                                                       \
        for (int it_ = 0; it_ < 2; it_++) {          /* A: 256x32 */            \
            int id_ = it_ * 512 + tid;                                          \
            int r_ = id_ >> 2, ch_ = id_ & 3;                                   \
            cp_async16(st_ + r_ * PIT + ch_ * 16,                               \
                       Ah + (size_t)(m0 + r_) * K + (k0) + ch_ * 8);            \
        }                                                                       \
        {                                            /* B: 128x32 */            \
            int r_ = tid >> 2, ch_ = tid & 3;                                   \
            cp_async16(st_ + A_ARR + r_ * PIT + ch_ * 16,                       \
                       Bh + (size_t)(n0 + r_) * K + (k0) + ch_ * 8);            \
        }                                                                       \
    } while (0)

    float acc[4][4][4];
    #pragma unroll
    for (int i = 0; i < 4; i++)
        #pragma unroll
        for (int j = 0; j < 4; j++)
            #pragma unroll
            for (int e = 0; e < 4; e++) acc[i][j][e] = 0.0f;

    const int nchunk = K / BKC;
    LOAD_STAGE(0, 0);
    CP_COMMIT();
    LOAD_STAGE(1, BKC);
    CP_COMMIT();

    const int arow  = (lid & 7) | (((lid >> 3) & 1) << 3);
    const int acolh = (lid >> 4) * 8;
    const int brow  = (lid & 7) + ((lid >> 4) & 1) * 8;
    const int bcolh = ((lid >> 3) & 1) * 8;

    int cur = 0;
    for (int c = 0; c < nchunk; c++) {
        if (c + 1 < nchunk) { CP_WAIT(1); } else { CP_WAIT(0); }
        __syncthreads();
        if (c + 2 < nchunk) {
            int nxt = cur + 2; if (nxt >= NSTG) nxt -= NSTG;
            LOAD_STAGE(nxt, (c + 2) * BKC);
            CP_COMMIT();
        }

        const uint32_t sA = sbase + cur * STG2;
        const uint32_t sB = sA + A_ARR;

        #pragma unroll
        for (int kk = 0; kk < 2; kk++) {
            const int kc = kk * 16;
            uint32_t bh[2][4], af[4][4];
            #pragma unroll
            for (int j = 0; j < 2; j++) {
                uint32_t off = (uint32_t)((wn + j * 16 + brow) * PIT + (kc + bcolh) * 2);
                ldsm_x4(bh[j][0], bh[j][1], bh[j][2], bh[j][3], sB + off);
            }
            #pragma unroll
            for (int i = 0; i < 4; i++) {
                uint32_t off = (uint32_t)((wm + i * 16 + arow) * PIT + (kc + acolh) * 2);
                ldsm_x4(af[i][0], af[i][1], af[i][2], af[i][3], sA + off);
            }
            #pragma unroll
            for (int i = 0; i < 4; i++) {
                #pragma unroll
                for (int j = 0; j < 2; j++) {
                    mma16816(acc[i][j * 2 + 0], af[i], bh[j][0], bh[j][1]);
                    mma16816(acc[i][j * 2 + 1], af[i], bh[j][2], bh[j][3]);
                }
            }
        }
        cur++; if (cur >= NSTG) cur -= NSTG;
    }

    const float DS = 1.0f / 4096.0f;     // undo 64*64 input scaling
    const int gr = lid >> 2, tg = lid & 3;
    #pragma unroll
    for (int i = 0; i < 4; i++) {
        #pragma unroll
        for (int j = 0; j < 4; j++) {
            int col = n0 + wn + j * 8 + tg * 2;
            if (col < N_real) {
                int row = m0 + wm + i * 16 + gr;
                float2 v0 = make_float2(acc[i][j][0] * DS, acc[i][j][1] * DS);
                float2 v1 = make_float2(acc[i][j][2] * DS, acc[i][j][3] * DS);
                *reinterpret_cast<float2*>(&C[(size_t)row * N_real + col]) = v0;
                *reinterpret_cast<float2*>(&C[(size_t)(row + 8) * N_real + col]) = v1;
            }
        }
    }
#undef LOAD_STAGE
}

// ---------------- flash attention via mma.sync fp16 (MQA, causal) ------------
#define FROW_B 144
#define QARR_B (128 * FROW_B)
#define KV_STG (2 * QARR_B)                 // K, V
#define FA_SMEM (QARR_B + 2 * KV_STG)       // 92160

__global__ __launch_bounds__(256, 1) void flash_mma(
    const __half* __restrict__ qh,
    const __half* __restrict__ kh, const __half* __restrict__ vh,
    __half* __restrict__ oh)
{
    extern __shared__ __align__(128) char smem[];
    const int tid = threadIdx.x, wid = tid >> 5, lid = tid & 31;
    const int qt = blockIdx.x, h = blockIdx.y;
    const int q0 = qt * 128;
    const uint32_t sb = smem_to_u32(smem);
    const uint32_t sQ  = sb;
    const uint32_t sKV = sb + QARR_B;

    {
        #pragma unroll
        for (int i = 0; i < 4; i++) {
            int id = i * 256 + tid;
            int r = id >> 3, c = id & 7;
            cp_async16(sQ + r * FROW_B + c * 16,
                       qh + ((size_t)h * SEQ + q0 + r) * HD + c * 8);
        }
    }
    const __half* kvsrc[2] = {kh, vh};
#define LOAD_KV(s, kt_) do {                                                   \
        _Pragma("unroll")                                                      \
        for (int i_ = 0; i_ < 8; i_++) {                                       \
            int id_ = i_ * 256 + tid;                                          \
            int a_ = id_ >> 10, w_ = id_ & 1023, r_ = w_ >> 3, c_ = w_ & 7;    \
            cp_async16(sKV + (s) * KV_STG + a_ * QARR_B + r_ * FROW_B + c_ * 16, \
                       kvsrc[a_] + ((size_t)((kt_) * 128 + r_)) * HD + c_ * 8); \
        }                                                                      \
    } while (0)
    LOAD_KV(0, 0);
    CP_COMMIT();
    CP_WAIT(0);
    __syncthreads();

    const int arow  = (lid & 7) | (((lid >> 3) & 1) << 3);
    const int acolh = (lid >> 4) * 8;
    const int brow  = (lid & 7) + ((lid >> 4) & 1) * 8;
    const int bcolh = ((lid >> 3) & 1) * 8;

    uint32_t aq[4][4];
    #pragma unroll
    for (int k = 0; k < 4; k++) {
        uint32_t off = (uint32_t)((wid * 16 + arow) * FROW_B + (k * 16 + acolh) * 2);
        ldsm_x4(aq[k][0], aq[k][1], aq[k][2], aq[k][3], sQ + off);
    }

    float acc[8][4];
    #pragma unroll
    for (int g = 0; g < 8; g++)
        #pragma unroll
        for (int e = 0; e < 4; e++) acc[g][e] = 0.0f;
    float m0 = -1e30f, m1 = -1e30f, l0 = 0.0f, l1 = 0.0f;
    const int row0 = q0 + wid * 16 + (lid >> 2);
    const float SC = 1.0f / 16384.0f;   // undo 32*64 q/k scaling (incl 1/8)

    const int nkv = qt + 1;
    for (int kt = 0; kt < nkv; kt++) {
        const int cur = kt & 1;
        if (kt + 1 < nkv) { LOAD_KV(cur ^ 1, kt + 1); CP_COMMIT(); }
        const uint32_t sK = sKV + cur * KV_STG;
        const uint32_t sV = sK + QARR_B;

        float sc[16][4];
        #pragma unroll
        for (int t = 0; t < 16; t++)
            #pragma unroll
            for (int e = 0; e < 4; e++) sc[t][e] = 0.0f;

        #pragma unroll
        for (int j2 = 0; j2 < 8; j2++) {
            #pragma unroll
            for (int k = 0; k < 4; k++) {
                uint32_t off = (uint32_t)((j2 * 16 + brow) * FROW_B + (k * 16 + bcolh) * 2);
                uint32_t b0, b1, b2, b3;
                ldsm_x4(b0, b1, b2, b3, sK + off);
                mma16816(sc[j2 * 2],     aq[k], b0, b1);
                mma16816(sc[j2 * 2 + 1], aq[k], b2, b3);
            }
        }

        #pragma unroll
        for (int t = 0; t < 16; t++)
            #pragma unroll
            for (int e = 0; e < 4; e++) sc[t][e] *= SC;

        if (kt == qt) {
            #pragma unroll
            for (int t = 0; t < 16; t++) {
                int colb = kt * 128 + t * 8 + (lid & 3) * 2;
                if (colb     > row0)     sc[t][0] = -1e30f;
                if (colb + 1 > row0)     sc[t][1] = -1e30f;
                if (colb     > row0 + 8) sc[t][2] = -1e30f;
                if (colb + 1 > row0 + 8) sc[t][3] = -1e30f;
            }
        }

        float mn0 = m0, mn1 = m1;
        #pragma unroll
        for (int t = 0; t < 16; t++) {
            mn0 = fmaxf(mn0, fmaxf(sc[t][0], sc[t][1]));
            mn1 = fmaxf(mn1, fmaxf(sc[t][2], sc[t][3]));
        }
        mn0 = fmaxf(mn0, __shfl_xor_sync(0xffffffffu, mn0, 1));
        mn0 = fmaxf(mn0, __shfl_xor_sync(0xffffffffu, mn0, 2));
        mn1 = fmaxf(mn1, __shfl_xor_sync(0xffffffffu, mn1, 1));
        mn1 = fmaxf(mn1, __shfl_xor_sync(0xffffffffu, mn1, 2));
        float corr0 = __expf(m0 - mn0);
        float corr1 = __expf(m1 - mn1);

        uint32_t phi[16][2];
        float ls0 = 0.0f, ls1 = 0.0f;
        #pragma unroll
        for (int t = 0; t < 16; t++) {
            float p0 = __expf(sc[t][0] - mn0);
            float p1 = __expf(sc[t][1] - mn0);
            float p2 = __expf(sc[t][2] - mn1);
            float p3 = __expf(sc[t][3] - mn1);
            ls0 += p0 + p1;  ls1 += p2 + p3;
            __half2 ph0 = __floats2half2_rn(p0 * 64.f, p1 * 64.f);
            __half2 ph1 = __floats2half2_rn(p2 * 64.f, p3 * 64.f);
            phi[t][0] = *reinterpret_cast<uint32_t*>(&ph0);
            phi[t][1] = *reinterpret_cast<uint32_t*>(&ph1);
        }
        ls0 += __shfl_xor_sync(0xffffffffu, ls0, 1);
        ls0 += __shfl_xor_sync(0xffffffffu, ls0, 2);
        ls1 += __shfl_xor_sync(0xffffffffu, ls1, 1);
        ls1 += __shfl_xor_sync(0xffffffffu, ls1, 2);
        l0 = l0 * corr0 + ls0;  l1 = l1 * corr1 + ls1;
        m0 = mn0;  m1 = mn1;
        #pragma unroll
        for (int g = 0; g < 8; g++) {
            acc[g][0] *= corr0; acc[g][1] *= corr0;
            acc[g][2] *= corr1; acc[g][3] *= corr1;
        }

        #pragma unroll
        for (int k = 0; k < 8; k++) {
            uint32_t ph_[4] = {phi[k * 2][0], phi[k * 2][1], phi[k * 2 + 1][0], phi[k * 2 + 1][1]};
            #pragma unroll
            for (int g = 0; g < 4; g++) {
                uint32_t off = (uint32_t)((k * 16 + (lid & 15)) * FROW_B +
                                          (g * 16 + ((lid >> 4) & 1) * 8) * 2);
                uint32_t v0, v1, v2, v3;
                ldsm_x4_t(v0, v1, v2, v3, sV + off);
                mma16816(acc[g * 2],     ph_, v0, v1);
                mma16816(acc[g * 2 + 1], ph_, v2, v3);
            }
        }

        if (kt + 1 < nkv) CP_WAIT(0);
        __syncthreads();
    }
#undef LOAD_KV

    // out' = 64 * true_out (feeds dense GEMM A-side): acc = 4096*P.V, /l, *64
    float inv0 = 1.0f / (64.0f * l0), inv1 = 1.0f / (64.0f * l1);
    #pragma unroll
    for (int g = 0; g < 8; g++) {
        int col = h * HD + g * 8 + (lid & 3) * 2;
        int r = q0 + wid * 16 + (lid >> 2);
        __half2 h0 = __floats2half2_rn(acc[g][0] * inv0, acc[g][1] * inv0);
        __half2 h1 = __floats2half2_rn(acc[g][2] * inv1, acc[g][3] * inv1);
        *reinterpret_cast<uint32_t*>(&oh[(size_t)r * QDIM + col]) =
            *reinterpret_cast<uint32_t*>(&h0);
        *reinterpret_cast<uint32_t*>(&oh[(size_t)(r + 8) * QDIM + col]) =
            *reinterpret_cast<uint32_t*>(&h1);
    }
}

// ---------------- launch ----------------------------------------------------
extern "C" void kernel_launch(void* const* d_in, const int* in_sizes, int n_in,
                              void* d_out, int out_size)
{
    const float* x       = (const float*)d_in[0];
    const float* qkv_w   = (const float*)d_in[1];
    const float* dense_w = (const float*)d_in[2];
    float* out = (float*)d_out;

    float* fused; cudaGetSymbolAddress((void**)&fused, g_fused);
    __half *xh, *wqh, *wdh, *ah, *qsh, *ksh, *vsh;
    cudaGetSymbolAddress((void**)&xh,  g_xh);
    cudaGetSymbolAddress((void**)&wqh, g_wqh);
    cudaGetSymbolAddress((void**)&wdh, g_wdh);
    cudaGetSymbolAddress((void**)&ah,  g_ah);
    cudaGetSymbolAddress((void**)&qsh, g_qsh);
    cudaGetSymbolAddress((void**)&ksh, g_ksh);
    cudaGetSymbolAddress((void**)&vsh, g_vsh);

    cudaFuncSetAttribute(gemm_mma,
                         cudaFuncAttributeMaxDynamicSharedMemorySize, GEMM_SMEM);
    cudaFuncSetAttribute(flash_mma,
                         cudaFuncAttributeMaxDynamicSharedMemorySize, FA_SMEM);

    // 1. RoPE table
    rope_table_kernel<<<(SEQ * 32 + 255) / 256, 256>>>();

    // 2. fp16 conversions (x64 scale)
    {
        int t4 = SEQ * HIDDEN / 4;
        split4_h<<<(t4 + 255) / 256, 256>>>(
            (const float4*)x, (uint2*)xh, t4, t4);
        int tw4 = QKV_PAD * HIDDEN / 4, sw4 = QKV_OUT * HIDDEN / 4;
        split4_h<<<(tw4 + 255) / 256, 256>>>(
            (const float4*)qkv_w, (uint2*)wqh, tw4, sw4);
        int td4 = DEN_PAD * HIDDEN / 4, sd4 = HIDDEN * HIDDEN / 4;
        split4_h<<<(td4 + 255) / 256, 256>>>(
            (const float4*)dense_w, (uint2*)wdh, td4, sd4);
    }

    // 3. QKV GEMM (single-term fp16)
    {
        dim3 grid(QKV_PAD / BN2, SEQ / BM2);
        gemm_mma<<<grid, 512, GEMM_SMEM>>>(xh, wqh, fused, QKV_OUT, HIDDEN);
    }

    // 4. prep: rope + scale + fp16 of q, k, v
    {
        int total = SEQ * (NH + 2) * 32;
        prep_kernel<<<(total + 255) / 256, 256>>>();
    }

    // 5. flash attention -> fp16 activations (pre-scaled x64)
    {
        dim3 grid(SEQ / 128, NH);
        flash_mma<<<grid, 256, FA_SMEM>>>(qsh, ksh, vsh, ah);
    }

    // 6. dense GEMM (single-term fp16) -> out
    {
        dim3 grid(DEN_PAD / BN2, SEQ / BM2);
        gemm_mma<<<grid, 512, GEMM_SMEM>>>(ah, wdh, out, HIDDEN, HIDDEN);
    }
}